// round 12
// baseline (speedup 1.0000x reference)
#include <cuda_runtime.h>
#include <cuda_bf16.h>
#include <math.h>
#include <stdint.h>

// ---------------- constants ----------------
#define BSZ   512
#define F66   66
#define TIN   50
#define KS_   10
#define VL    35          // KS + output_n
#define VN    16          // input_n - VL + 1
#define DCTN  20
#define GCNIN 40
#define MROWS (BSZ * F66) // 33792

#define FP    80          // padded feature row for src bf16 (160B pitch)
#define K1P   480         // conv1 K: 6*80
#define K2    2560        // conv2 K: 5*512

__device__ __forceinline__ uint32_t smem_u32(const void* p) {
    uint32_t a;
    asm("{ .reg .u64 t; cvta.to.shared.u64 t, %1; cvt.u32.u64 %0, t; }" : "=r"(a) : "l"(p));
    return a;
}

__device__ __forceinline__ void mma16816(float* c, const uint32_t* a, uint32_t b0, uint32_t b1) {
    asm volatile(
        "mma.sync.aligned.m16n8k16.row.col.f32.bf16.bf16.f32 "
        "{%0,%1,%2,%3}, {%4,%5,%6,%7}, {%8,%9}, {%0,%1,%2,%3};"
        : "+f"(c[0]), "+f"(c[1]), "+f"(c[2]), "+f"(c[3])
        : "r"(a[0]), "r"(a[1]), "r"(a[2]), "r"(a[3]), "r"(b0), "r"(b1));
}

#define LDSM4(r, addr) \
    asm volatile("ldmatrix.sync.aligned.m8n8.x4.shared.b16 {%0,%1,%2,%3}, [%4];" \
        : "=r"((r)[0]), "=r"((r)[1]), "=r"((r)[2]), "=r"((r)[3]) : "r"(addr))

#define LDSM4T(r, addr) \
    asm volatile("ldmatrix.sync.aligned.m8n8.x4.trans.shared.b16 {%0,%1,%2,%3}, [%4];" \
        : "=r"((r)[0]), "=r"((r)[1]), "=r"((r)[2]), "=r"((r)[3]) : "r"(addr))

#define CPA16(saddr, gptr) \
    asm volatile("cp.async.ca.shared.global [%0], [%1], 16;" :: "r"(saddr), "l"(gptr))

// swizzled 64B-row address: row r (64B stride), 16B-chunk c (0..3)
#define SWZ(r, c) ((uint32_t)(((r) << 6) + ((((c) ^ (((r) >> 1) & 3))) << 4)))

// ---------------- scratch (device globals; no allocation) ----------------
__device__ float g_dct[DCTN * VL];

#define SRCP_N (BSZ * TIN * FP)
__device__ __align__(16) __nv_bfloat16 g_srch[SRCP_N + 512];
__device__ __align__(16) __nv_bfloat16 g_srcl[SRCP_N + 512];
__device__ __align__(16) __nv_bfloat16 g_k1h[(size_t)10240 * 512];
__device__ __align__(16) __nv_bfloat16 g_k1l[(size_t)10240 * 512];
__device__ __align__(16) __nv_bfloat16 g_q1h[(size_t)2560 * 512];
__device__ __align__(16) __nv_bfloat16 g_q1l[(size_t)2560 * 512];

__device__ __align__(16) __nv_bfloat16 g_Wk1h[(size_t)512 * K1P];
__device__ __align__(16) __nv_bfloat16 g_Wk1l[(size_t)512 * K1P];
__device__ __align__(16) __nv_bfloat16 g_Wk2h[(size_t)512 * K2];
__device__ __align__(16) __nv_bfloat16 g_Wk2l[(size_t)512 * K2];
__device__ __align__(16) __nv_bfloat16 g_Wq1h[(size_t)512 * K1P];
__device__ __align__(16) __nv_bfloat16 g_Wq1l[(size_t)512 * K1P];
__device__ __align__(16) __nv_bfloat16 g_Wq2h[(size_t)512 * K2];
__device__ __align__(16) __nv_bfloat16 g_Wq2l[(size_t)512 * K2];
__device__ __align__(16) __nv_bfloat16 g_Wg1h[(size_t)512 * 64];
__device__ __align__(16) __nv_bfloat16 g_Wg1l[(size_t)512 * 64];
__device__ __align__(16) __nv_bfloat16 g_Wgbh[(size_t)4 * 512 * 512];
__device__ __align__(16) __nv_bfloat16 g_Wgbl[(size_t)4 * 512 * 512];
__device__ __align__(16) __nv_bfloat16 g_Th[(size_t)MROWS * 512];
__device__ __align__(16) __nv_bfloat16 g_Tl[(size_t)MROWS * 512];
__device__ __align__(16) __nv_bfloat16 g_yh[(size_t)MROWS * 512];
__device__ __align__(16) __nv_bfloat16 g_yl[(size_t)MROWS * 512];
__device__ __align__(16) __nv_bfloat16 g_zh[(size_t)MROWS * 512];
__device__ __align__(16) __nv_bfloat16 g_zl[(size_t)MROWS * 512];
__device__ __align__(16) __nv_bfloat16 g_Aph[5 * 80 * 80];
__device__ __align__(16) __nv_bfloat16 g_Apl[5 * 80 * 80];

__device__ float g_key2[(size_t)8192 * 512];
__device__ float g_q[(size_t)512 * 512];
__device__ float g_att[BSZ * VN];
__device__ float g_x[(size_t)BSZ * F66 * GCNIN];
__device__ float g_t[(size_t)MROWS * 512];
__device__ float g_do20[(size_t)MROWS * DCTN];

// ---------------- epilogue descriptor ----------------
// modes: 0 plain fp32, 1 relu, 2 bias+bn+tanh, 3 bias+bn+tanh+resid
struct Epi {
    const float* bias;
    const float* gamma;
    const float* beta;
    int mode;
};

__device__ __forceinline__ void split_bf16(float v, __nv_bfloat16& h, __nv_bfloat16& l) {
    h = __float2bfloat16_rn(v);
    l = __float2bfloat16_rn(v - __bfloat162float(h));
}

__device__ __forceinline__ uint32_t pack2(float a, float b, bool lo) {
    __nv_bfloat16 ha, la, hb, lb;
    split_bf16(a, ha, la); split_bf16(b, hb, lb);
    uint16_t x = lo ? __bfloat16_as_ushort(la) : __bfloat16_as_ushort(ha);
    uint16_t y = lo ? __bfloat16_as_ushort(lb) : __bfloat16_as_ushort(hb);
    return (uint32_t)x | ((uint32_t)y << 16);
}

// ---------------- dct matrix ----------------
__global__ void dct_build() {
    for (int i = threadIdx.x; i < DCTN * VL; i += blockDim.x) {
        int k = i / VL, v = i % VL;
        double w = (k == 0) ? sqrt(1.0 / VL) : sqrt(2.0 / VL);
        g_dct[i] = (float)(w * cos(3.14159265358979323846 * (v + 0.5) * k / VL));
    }
}

// ---------------- src -> bf16 hi/lo (x 1e-3), padded layout [b*50+t][80] ----------------
__global__ void src_to_bf16(const float* __restrict__ src) {
    int total = SRCP_N + 512;
    for (int i = blockIdx.x * blockDim.x + threadIdx.x; i < total;
         i += gridDim.x * blockDim.x) {
        float v = 0.f;
        if (i < SRCP_N) {
            int f = i % FP;
            int row = i / FP;
            if (f < F66) v = src[row * F66 + f] * 1e-3f;
        }
        __nv_bfloat16 h, l; split_bf16(v, h, l);
        g_srch[i] = h; g_srcl[i] = l;
    }
}

// ---------------- weight preps ----------------
__global__ void prep_c1w(const float* __restrict__ W, __nv_bfloat16* __restrict__ Bh,
                         __nv_bfloat16* __restrict__ Bl) {
    int total = 512 * K1P;
    for (int i = blockIdx.x * blockDim.x + threadIdx.x; i < total;
         i += gridDim.x * blockDim.x) {
        int n = i / K1P, k = i % K1P;
        int tt = k / FP, f = k % FP;
        float v = (f < F66) ? W[n * 396 + f * 6 + tt] : 0.f;
        __nv_bfloat16 h, l; split_bf16(v, h, l);
        Bh[i] = h; Bl[i] = l;
    }
}

__global__ void prep_c2w(const float* __restrict__ W, __nv_bfloat16* __restrict__ Bh,
                         __nv_bfloat16* __restrict__ Bl) {
    int total = 512 * K2;
    for (int i = blockIdx.x * blockDim.x + threadIdx.x; i < total;
         i += gridDim.x * blockDim.x) {
        int n = i / K2, k = i % K2;
        int tt = k >> 9, c = k & 511;
        float v = W[n * K2 + c * 5 + tt];
        __nv_bfloat16 h, l; split_bf16(v, h, l);
        Bh[i] = h; Bl[i] = l;
    }
}

__global__ void prep_KN(const float* __restrict__ W, __nv_bfloat16* __restrict__ Bh,
                        __nv_bfloat16* __restrict__ Bl, int K, int N, int Kp) {
    size_t total = (size_t)N * Kp;
    for (size_t i = (size_t)blockIdx.x * blockDim.x + threadIdx.x; i < total;
         i += (size_t)gridDim.x * blockDim.x) {
        int k = (int)(i % Kp);
        int n = (int)(i / Kp);
        float v = (k < K) ? W[(size_t)k * N + n] : 0.f;
        __nv_bfloat16 h, l; split_bf16(v, h, l);
        Bh[i] = h; Bl[i] = l;
    }
}

__global__ void prep_att(const float* __restrict__ gcb_att, const float* __restrict__ gc7_att) {
    int total = 5 * 80 * 80;
    for (int i = blockIdx.x * blockDim.x + threadIdx.x; i < total; i += gridDim.x * blockDim.x) {
        int li = i / 6400, rem = i % 6400;
        int r = rem / 80, c = rem % 80;
        float v = 0.f;
        if (r < F66 && c < F66) {
            const float* src = (li < 4) ? (gcb_att + (size_t)li * F66 * F66) : gc7_att;
            v = src[r * F66 + c];
        }
        __nv_bfloat16 h, l; split_bf16(v, h, l);
        g_Aph[i] = h; g_Apl[i] = l;
    }
}

// ---------------- HMMA bf16x3 GEMM, 128x128 tile, 256 threads, 2 CTAs/SM ----------------
// 8 warps (2m x 4n), warp tile 64x32. Swizzled 64B smem rows.
// 3-stage cp.async ring: 3 bufs x 32768 = 98304 per CTA (2 CTAs = 192KB <= 228KB).
#define HG_SMEM 98304

__device__ __forceinline__ float epi_apply(float v, int col, int nmod, const Epi& e) {
    if (e.mode == 1) return fmaxf(v, 0.f);
    if (e.mode == 2 || e.mode == 3) {
        v += e.bias[col];
        int gi = nmod * 512 + col;
        v = tanhf(v * e.gamma[gi] * 0.9999950000374997f + e.beta[gi]);
    }
    return v;
}

__device__ __forceinline__ size_t amap(int amode, int r, int npos, int off, int K) {
    if (amode == 0)      return (size_t)r * K;
    else if (amode == 1) return ((size_t)(r / npos) * TIN + off + (r % npos)) * FP;
    else if (amode == 2) return ((size_t)(r >> 4) * 20 + (r & 15)) * 512;
    else                 return (size_t)r * 2560;
}

__global__ void __launch_bounds__(256, 2) hgemm(
    const __nv_bfloat16* __restrict__ Ah, const __nv_bfloat16* __restrict__ Al,
    int amode, int npos, int off,
    const __nv_bfloat16* __restrict__ Bh, const __nv_bfloat16* __restrict__ Bl,
    float* __restrict__ C, __nv_bfloat16* __restrict__ Ch, __nv_bfloat16* __restrict__ Cl,
    const __nv_bfloat16* __restrict__ Rh, const __nv_bfloat16* __restrict__ Rl,
    int M, int K, Epi e) {
    extern __shared__ __align__(16) char smem[];
    const uint32_t sb = smem_u32(smem);
    const int tid = threadIdx.x;
    const int bm0 = blockIdx.y * 128;
    const int bn0 = blockIdx.x * 128;
    const int warp = tid >> 5, lane = tid & 31;
    const int wm = warp & 1, wn = warp >> 1;   // wn 0..3 (32-col tiles)
    const int KT = K >> 5;
    const int nkt = KT / gridDim.z;
    const int kt0 = blockIdx.z * nkt;
    const int ktend = kt0 + nkt;

    const int lr = tid >> 2;          // 0..63
    const int lc = tid & 3;           // 16B chunk
    const size_t aRow0 = amap(amode, bm0 + lr, npos, off, K);
    const size_t aRow1 = amap(amode, bm0 + 64 + lr, npos, off, K);
    const size_t bRow0 = (size_t)(bn0 + lr) * K;
    const size_t bRow1 = (size_t)(bn0 + 64 + lr) * K;
    const uint32_t swA0 = SWZ(lr, lc);
    const uint32_t swA1 = SWZ(lr + 64, lc);

    float c[4][4][4];
#pragma unroll
    for (int i = 0; i < 4; i++)
#pragma unroll
        for (int j = 0; j < 4; j++)
#pragma unroll
            for (int q = 0; q < 4; q++) c[i][j][q] = 0.f;

#define HLOAD(bufo, kt) do {                                                       \
    const int k0 = (kt) << 5;                                                      \
    const uint32_t bo = sb + (uint32_t)(bufo);                                     \
    CPA16(bo + swA0, Ah + aRow0 + k0 + lc * 8);                                    \
    CPA16(bo + swA1, Ah + aRow1 + k0 + lc * 8);                                    \
    CPA16(bo + 8192u + swA0, Al + aRow0 + k0 + lc * 8);                            \
    CPA16(bo + 8192u + swA1, Al + aRow1 + k0 + lc * 8);                            \
    CPA16(bo + 16384u + swA0, Bh + bRow0 + k0 + lc * 8);                           \
    CPA16(bo + 16384u + swA1, Bh + bRow1 + k0 + lc * 8);                           \
    CPA16(bo + 24576u + swA0, Bl + bRow0 + k0 + lc * 8);                           \
    CPA16(bo + 24576u + swA1, Bl + bRow1 + k0 + lc * 8);                           \
    asm volatile("cp.async.commit_group;");                                        \
} while (0)

    // 3-stage prologue
    HLOAD(0u, kt0);
    if (kt0 + 1 < ktend) HLOAD(32768u, kt0 + 1);

    uint32_t bufc = 0u;        // buffer offset of current chunk
    uint32_t bufn = 65536u;    // buffer offset for the chunk 2 ahead
    for (int kt = kt0; kt < ktend; kt++) {
        if (kt + 2 < ktend) {
            HLOAD(bufn, kt + 2);
            asm volatile("cp.async.wait_group 2;");
        } else if (kt + 1 < ktend) {
            asm volatile("cp.async.wait_group 1;");
        } else {
            asm volatile("cp.async.wait_group 0;");
        }
        __syncthreads();
        const uint32_t base = sb + bufc;
        bufc = (bufc == 65536u) ? 0u : bufc + 32768u;
        bufn = (bufn == 65536u) ? 0u : bufn + 32768u;
#pragma unroll
        for (int kh = 0; kh < 2; kh++) {
            uint32_t ah[4][4], al[4][4], bh2[2][4], bl2[2][4];
#pragma unroll
            for (int mi = 0; mi < 4; mi++) {
                int row = wm * 64 + mi * 16 + (lane & 7) + ((lane >> 3) & 1) * 8;
                int cc = kh * 2 + (lane >> 4);
                uint32_t ad = base + SWZ(row, cc);
                LDSM4(ah[mi], ad);
                LDSM4(al[mi], ad + 8192u);
            }
#pragma unroll
            for (int bi = 0; bi < 2; bi++) {
                int row = wn * 32 + bi * 16 + (lane & 7) + (lane >> 4) * 8;
                int cc = kh * 2 + ((lane >> 3) & 1);
                uint32_t bd = base + 16384u + SWZ(row, cc);
                LDSM4(bh2[bi], bd);
                LDSM4(bl2[bi], bd + 8192u);
            }
#pragma unroll
            for (int mi = 0; mi < 4; mi++)
#pragma unroll
                for (int ni = 0; ni < 4; ni++) {
                    uint32_t b0h = bh2[ni >> 1][(ni & 1) * 2];
                    uint32_t b1h = bh2[ni >> 1][(ni & 1) * 2 + 1];
                    uint32_t b0l = bl2[ni >> 1][(ni & 1) * 2];
                    uint32_t b1l = bl2[ni >> 1][(ni & 1) * 2 + 1];
                    mma16816(c[mi][ni], ah[mi], b0h, b1h);
                    mma16816(c[mi][ni], al[mi], b0h, b1h);
                    mma16816(c[mi][ni], ah[mi], b0l, b1l);
                }
        }
        __syncthreads();
    }
#undef HLOAD

    // ---- epilogue ----
    float* Cz = C ? (C + (size_t)blockIdx.z * M * 512) : C;
#pragma unroll
    for (int mi = 0; mi < 4; mi++) {
        int r0 = bm0 + wm * 64 + mi * 16 + (lane >> 2);
        int r1 = r0 + 8;
        int nm0 = r0 % F66, nm1 = r1 % F66;
#pragma unroll
        for (int ni = 0; ni < 4; ni++) {
            int cb = bn0 + wn * 32 + ni * 8 + (lane & 3) * 2;
            size_t i0 = (size_t)r0 * 512 + cb;
            size_t i1 = (size_t)r1 * 512 + cb;
            float v0 = epi_apply(c[mi][ni][0], cb, nm0, e);
            float v1 = epi_apply(c[mi][ni][1], cb + 1, nm0, e);
            float v2 = epi_apply(c[mi][ni][2], cb, nm1, e);
            float v3 = epi_apply(c[mi][ni][3], cb + 1, nm1, e);
            if (e.mode == 3) {
                __nv_bfloat162 rh0 = *reinterpret_cast<const __nv_bfloat162*>(Rh + i0);
                __nv_bfloat162 rl0 = *reinterpret_cast<const __nv_bfloat162*>(Rl + i0);
                __nv_bfloat162 rh1 = *reinterpret_cast<const __nv_bfloat162*>(Rh + i1);
                __nv_bfloat162 rl1 = *reinterpret_cast<const __nv_bfloat162*>(Rl + i1);
                v0 += __bfloat162float(rh0.x) + __bfloat162float(rl0.x);
                v1 += __bfloat162float(rh0.y) + __bfloat162float(rl0.y);
                v2 += __bfloat162float(rh1.x) + __bfloat162float(rl1.x);
                v3 += __bfloat162float(rh1.y) + __bfloat162float(rl1.y);
            }
            if (Cz) {
                *reinterpret_cast<float2*>(Cz + i0) = make_float2(v0, v1);
                *reinterpret_cast<float2*>(Cz + i1) = make_float2(v2, v3);
            }
            if (Ch) {
                *reinterpret_cast<uint32_t*>(Ch + i0) = pack2(v0, v1, false);
                *reinterpret_cast<uint32_t*>(Cl + i0) = pack2(v0, v1, true);
                *reinterpret_cast<uint32_t*>(Ch + i1) = pack2(v2, v3, false);
                *reinterpret_cast<uint32_t*>(Cl + i1) = pack2(v2, v3, true);
            }
        }
    }
}

// ---------------- split-K reduce + relu ----------------
__global__ void reduce_relu(const float* __restrict__ part, float* __restrict__ outp,
                            int n, int zn) {
    for (int i = blockIdx.x * blockDim.x + threadIdx.x; i < n;
         i += gridDim.x * blockDim.x) {
        float s = 0.f;
        for (int z = 0; z < zn; z++) s += part[(size_t)z * n + i];
        outp[i] = fmaxf(s, 0.f);
    }
}

// ---------------- batched node-mix via HMMA ----------------
#define AM_SMEM 71680

__global__ void __launch_bounds__(256) amix_mma(
    const __nv_bfloat16* __restrict__ Aph, const __nv_bfloat16* __restrict__ Apl,
    const __nv_bfloat16* __restrict__ Yh, const __nv_bfloat16* __restrict__ Yl,
    __nv_bfloat16* __restrict__ Th, __nv_bfloat16* __restrict__ Tl,
    float* __restrict__ Tf) {
    extern __shared__ __align__(16) char smem[];
    const uint32_t sb = smem_u32(smem);
    const int b = blockIdx.y;
    const int f0 = blockIdx.x * 128;
    const int tid = threadIdx.x;
    const int warp = tid >> 5, lane = tid & 31;

    for (int i = tid; i < 800; i += 256) {
        int r = i / 10, cc = i % 10;
        uint32_t dst = sb + (uint32_t)(r * 176 + cc * 16);
        CPA16(dst, Aph + r * 80 + cc * 8);
        CPA16(dst + 14080u, Apl + r * 80 + cc * 8);
    }
    for (int i = tid; i < 1056; i += 256) {
        int r = i >> 4, cc = i & 15;
        uint32_t dst = sb + 28160u + (uint32_t)(r * 272 + cc * 16);
        const size_t gsrc = ((size_t)b * F66 + r) * 512 + f0 + cc * 8;
        CPA16(dst, Yh + gsrc);
        CPA16(dst + 21760u, Yl + gsrc);
    }
    asm volatile("cp.async.commit_group;");
    for (int i = tid; i < 224; i += 256) {
        int r = 66 + (i >> 4), cc = i & 15;
        uint32_t dst = sb + 28160u + (uint32_t)(r * 272 + cc * 16);
        asm volatile("st.shared.v4.b32 [%0], {%1,%1,%1,%1};" :: "r"(dst), "r"(0u));
        asm volatile("st.shared.v4.b32 [%0], {%1,%1,%1,%1};" :: "r"(dst + 21760u), "r"(0u));
    }
    asm volatile("cp.async.wait_group 0;");
    __syncthreads();

    const int n0c = warp * 16;
    uint32_t bh[5][4], bl[5][4];
#pragma unroll
    for (int kt = 0; kt < 5; kt++) {
        int row = kt * 16 + ((lane >> 3) & 1) * 8 + (lane & 7);
        int col = n0c + (lane >> 4) * 8;
        uint32_t ad = sb + 28160u + (uint32_t)(row * 272 + col * 2);
        LDSM4T(bh[kt], ad);
        LDSM4T(bl[kt], ad + 21760u);
    }

    float c[5][2][4];
#pragma unroll
    for (int mi = 0; mi < 5; mi++)
#pragma unroll
        for (int g = 0; g < 2; g++)
#pragma unroll
            for (int q = 0; q < 4; q++) c[mi][g][q] = 0.f;

#pragma unroll
    for (int mi = 0; mi < 5; mi++) {
#pragma unroll
        for (int kt = 0; kt < 5; kt++) {
            int row = mi * 16 + (lane & 7) + ((lane >> 3) & 1) * 8;
            int col = kt * 16 + (lane >> 4) * 8;
            uint32_t ad = sb + (uint32_t)(row * 176 + col * 2);
            uint32_t ah[4], al[4];
            LDSM4(ah, ad);
            LDSM4(al, ad + 14080u);
#pragma unroll
            for (int g = 0; g < 2; g++) {
                mma16816(c[mi][g], ah, bh[kt][g * 2], bh[kt][g * 2 + 1]);
                mma16816(c[mi][g], al, bh[kt][g * 2], bh[kt][g * 2 + 1]);
                mma16816(c[mi][g], ah, bl[kt][g * 2], bl[kt][g * 2 + 1]);
            }
        }
    }

#pragma unroll
    for (int mi = 0; mi < 5; mi++) {
        int n_0 = mi * 16 + (lane >> 2);
        int n_1 = n_0 + 8;
#pragma unroll
        for (int g = 0; g < 2; g++) {
            int f = f0 + n0c + g * 8 + (lane & 3) * 2;
            if (n_0 < F66) {
                size_t o = ((size_t)b * F66 + n_0) * 512 + f;
                if (Tf) {
                    *reinterpret_cast<float2*>(Tf + o) = make_float2(c[mi][g][0], c[mi][g][1]);
                } else {
                    *reinterpret_cast<uint32_t*>(Th + o) = pack2(c[mi][g][0], c[mi][g][1], false);
                    *reinterpret_cast<uint32_t*>(Tl + o) = pack2(c[mi][g][0], c[mi][g][1], true);
                }
            }
            if (n_1 < F66) {
                size_t o = ((size_t)b * F66 + n_1) * 512 + f;
                if (Tf) {
                    *reinterpret_cast<float2*>(Tf + o) = make_float2(c[mi][g][2], c[mi][g][3]);
                } else {
                    *reinterpret_cast<uint32_t*>(Th + o) = pack2(c[mi][g][2], c[mi][g][3], false);
                    *reinterpret_cast<uint32_t*>(Tl + o) = pack2(c[mi][g][2], c[mi][g][3], true);
                }
            }
        }
    }
}

// ---------------- gc7: C[M,20] = A[M,512] @ W[:, :20] + bias + x-resid ----------------
__global__ void __launch_bounds__(256) gc7_ffma(
    const float* __restrict__ A, const float* __restrict__ W,
    const float* __restrict__ bias, const float* __restrict__ xres,
    float* __restrict__ out20) {
    __shared__ float As[128][17];
    __shared__ float Bs[16][21];
    const int bm0 = blockIdx.x * 128;
    const int t = threadIdx.x;
    const int rp = t >> 2, cg = t & 3;
    float acc[2][5] = {};
    for (int k0 = 0; k0 < 512; k0 += 16) {
#pragma unroll
        for (int i = 0; i < 8; i++) {
            int idx = t + 256 * i;
            int r = idx >> 4, kk = idx & 15;
            As[r][kk] = A[(size_t)(bm0 + r) * 512 + k0 + kk];
        }
        for (int i = t; i < 320; i += 256) {
            int kk = i / 20, n = i % 20;
            Bs[kk][n] = W[(k0 + kk) * GCNIN + n];
        }
        __syncthreads();
#pragma unroll
        for (int kk = 0; kk < 16; kk++) {
            float a0 = As[rp * 2][kk], a1 = As[rp * 2 + 1][kk];
#pragma unroll
            for (int j = 0; j < 5; j++) {
                float bb = Bs[kk][cg * 5 + j];
                acc[0][j] += a0 * bb;
                acc[1][j] += a1 * bb;
            }
        }
        __syncthreads();
    }
#pragma unroll
    for (int rr = 0; rr < 2; rr++) {
        int row = bm0 + rp * 2 + rr;
#pragma unroll
        for (int j = 0; j < 5; j++) {
            int n = cg * 5 + j;
            out20[(size_t)row * DCTN + n] = acc[rr][j] + bias[n] + xres[(size_t)row * GCNIN + n];
        }
    }
}

// ---------------- attention: score + normalize ----------------
__global__ void score_att_kernel(const float* __restrict__ q,
                                 const float* __restrict__ key2,
                                 float* __restrict__ att) {
    int b = blockIdx.x;
    __shared__ float sc[VN];
    int t = threadIdx.x;
    int w = t / 32, lane = t % 32;
    for (int n = w; n < VN; n += 8) {
        float s = 0.f;
        const float* qp = q + (size_t)b * 512;
        const float* kp = key2 + (size_t)(b * VN + n) * 512;
        for (int d = lane; d < 512; d += 32) s += qp[d] * kp[d];
        for (int o = 16; o; o >>= 1) s += __shfl_xor_sync(0xffffffffu, s, o);
        if (lane == 0) sc[n] = s + 1e-15f;
    }
    __syncthreads();
    float tot = 0.f;
#pragma unroll
    for (int n = 0; n < VN; n++) tot += sc[n];
    if (t < VN) att[b * VN + t] = sc[t] / tot;
}

// ---------------- build x = [dct_in | dct_att]  (b, 66, 40) ----------------
__global__ void x_build(const float* __restrict__ src) {
    int b = blockIdx.x;
    int t = threadIdx.x;
    __shared__ float ss[TIN * F66];
    __shared__ float sh_s[VL * F66];
    __shared__ float sh_dct[DCTN * VL];
    __shared__ float sh_att[VN];
    for (int i = t; i < TIN * F66; i += 256) ss[i] = src[(size_t)b * TIN * F66 + i];
    for (int i = t; i < DCTN * VL; i += 256) sh_dct[i] = g_dct[i];
    if (t < VN) sh_att[t] = g_att[b * VN + t];
    __syncthreads();
    for (int i = t; i < VL * F66; i += 256) {
        int v = i / F66, f = i % F66;
        float a = 0.f;
#pragma unroll
        for (int n = 0; n < VN; n++) a += sh_att[n] * ss[(n + v) * F66 + f];
        sh_s[i] = a;
    }
    __syncthreads();
    for (int i = t; i < F66 * GCNIN; i += 256) {
        int f = i / GCNIN, k = i % GCNIN;
        float a = 0.f;
        if (k < DCTN) {
#pragma unroll
            for (int v = 0; v < VL; v++) {
                int r = (v < KS_) ? (TIN - KS_ + v) : (TIN - 1);
                a += sh_dct[k * VL + v] * ss[r * F66 + f];
            }
        } else {
            int kk = k - DCTN;
#pragma unroll
            for (int v = 0; v < VL; v++) a += sh_dct[kk * VL + v] * sh_s[v * F66 + f];
        }
        g_x[(size_t)b * F66 * GCNIN + i] = a;
    }
}

// ---------------- scalar node mix for gc1 (F=40 -> Th/Tl Kp=64) ----------------
__global__ void __launch_bounds__(256) amix2(
    const float* __restrict__ A, const float* __restrict__ in,
    __nv_bfloat16* __restrict__ oh, __nv_bfloat16* __restrict__ ol, int F, int Kp) {
    int b = blockIdx.x;
    __shared__ float Ash[F66 * F66];
    __shared__ float insh[F66][64];
    int t = threadIdx.x;
    for (int i = t; i < F66 * F66; i += 256) Ash[i] = A[i];
    int fw = F;
    for (int i = t; i < F66 * 64; i += 256) {
        int m = i >> 6, f = i & 63;
        insh[m][f] = (f < fw) ? in[((size_t)b * F66 + m) * F + f] : 0.f;
    }
    __syncthreads();
    int w = t >> 5, lane = t & 31;
    int h = lane >> 4, sub = lane & 15;
    int fl = sub * 4;
#pragma unroll
    for (int pass = 0; pass < 5; pass++) {
        int n = pass * 16 + w * 2 + h;
        int nn = (n < F66) ? n : 0;
        const float* arow = Ash + nn * F66;
        float ax = 0.f, ay = 0.f, az = 0.f, aw = 0.f;
#pragma unroll 6
        for (int m = 0; m < F66; m++) {
            float a = arow[m];
            float4 yv = *reinterpret_cast<const float4*>(&insh[m][fl]);
            ax += a * yv.x; ay += a * yv.y; az += a * yv.z; aw += a * yv.w;
        }
        if (n < F66) {
            float vals[4] = {ax, ay, az, aw};
            size_t o = ((size_t)b * F66 + n) * Kp + fl;
#pragma unroll
            for (int j = 0; j < 4; j++) {
                float v = (fl + j < fw) ? vals[j] : 0.f;
                __nv_bfloat16 hh, ll; split_bf16(v, hh, ll);
                oh[o + j] = hh; ol[o + j] = ll;
            }
        }
    }
}

// ---------------- final iDCT (reads compact [M][20] dct_out) ----------------
__global__ void final_idct(float* __restrict__ out) {
    size_t total = (size_t)BSZ * VL * F66;
    for (size_t i = (size_t)blockIdx.x * blockDim.x + threadIdx.x; i < total;
         i += (size_t)gridDim.x * blockDim.x) {
        int f = (int)(i % F66);
        int v = (int)((i / F66) % VL);
        int b = (int)(i / ((size_t)F66 * VL));
        float a = 0.f;
#pragma unroll
        for (int k = 0; k < DCTN; k++)
            a += g_dct[k * VL + v] * g_do20[((size_t)b * F66 + f) * DCTN + k];
        out[i] = a;
    }
}

// ---------------- host launcher ----------------
template <typename T>
static T* sym(const void* s) {
    void* p = nullptr;
    cudaGetSymbolAddress(&p, s);
    return (T*)p;
}

extern "C" void kernel_launch(void* const* d_in, const int* in_sizes, int n_in,
                              void* d_out, int out_size) {
    const float* src     = (const float*)d_in[0];
    const float* Wq1     = (const float*)d_in[1];
    const float* Wq2     = (const float*)d_in[2];
    const float* Wk1     = (const float*)d_in[3];
    const float* Wk2     = (const float*)d_in[4];
    const float* gc1_W   = (const float*)d_in[5];
    const float* gc1_att = (const float*)d_in[6];
    const float* gc1_b   = (const float*)d_in[7];
    const float* bn1_g   = (const float*)d_in[8];
    const float* bn1_b   = (const float*)d_in[9];
    const float* gcb_W   = (const float*)d_in[10];
    const float* gcb_att = (const float*)d_in[11];
    const float* gcb_b   = (const float*)d_in[12];
    const float* gcb_bn_g= (const float*)d_in[13];
    const float* gcb_bn_b= (const float*)d_in[14];
    const float* gc7_W   = (const float*)d_in[15];
    const float* gc7_att = (const float*)d_in[16];
    const float* gc7_b   = (const float*)d_in[17];
    float* out = (float*)d_out;

    cudaFuncSetAttribute(hgemm, cudaFuncAttributeMaxDynamicSharedMemorySize, HG_SMEM);
    cudaFuncSetAttribute(amix_mma, cudaFuncAttributeMaxDynamicSharedMemorySize, AM_SMEM);

    __nv_bfloat16* srch = sym<__nv_bfloat16>(g_srch); __nv_bfloat16* srcl = sym<__nv_bfloat16>(g_srcl);
    __nv_bfloat16* k1h  = sym<__nv_bfloat16>(g_k1h);  __nv_bfloat16* k1l  = sym<__nv_bfloat16>(g_k1l);
    __nv_bfloat16* q1h  = sym<__nv_bfloat16>(g_q1h);  __nv_bfloat16* q1l  = sym<__nv_bfloat16>(g_q1l);
    __nv_bfloat16* Wk1h = sym<__nv_bfloat16>(g_Wk1h); __nv_bfloat16* Wk1l = sym<__nv_bfloat16>(g_Wk1l);
    __nv_bfloat16* Wk2h = sym<__nv_bfloat16>(g_Wk2h); __nv_bfloat16* Wk2l = sym<__nv_bfloat16>(g_Wk2l);
    __nv_bfloat16* Wq1h = sym<__nv_bfloat16>(g_Wq1h); __nv_bfloat16* Wq1l = sym<__nv_bfloat16>(g_Wq1l);
    __nv_bfloat16* Wq2h = sym<__nv_bfloat16>(g_Wq2h); __nv_bfloat16* Wq2l = sym<__nv_bfloat16>(g_Wq2l);
    __nv_bfloat16* Wg1h = sym<__nv_bfloat16>(g_Wg1h); __nv_bfloat16* Wg1l = sym<__nv_bfloat16>(g_Wg1l);
    __nv_bfloat16* Wgbh = sym<__nv_bfloat16>(g_Wgbh); __nv_bfloat16* Wgbl = sym<__nv_bfloat16>(g_Wgbl);
    __nv_bfloat16* Th   = sym<__nv_bfloat16>(g_Th);   __nv_bfloat16* Tl   = sym<__nv_bfloat16>(g_Tl);
    __nv_bfloat16* yh   = sym<__nv_bfloat16>(g_yh);   __nv_bfloat16* yl   = sym<__nv_bfloat16>(g_yl);
    __nv_bfloat16* zh   = sym<__nv_bfloat16>(g_zh);   __nv_bfloat16* zl   = sym<__nv_bfloat16>(g_zl);
    __nv_bfloat16* Aph  = sym<__nv_bfloat16>(g_Aph);  __nv_bfloat16* Apl  = sym<__nv_bfloat16>(g_Apl);

    float* key2 = sym<float>(g_key2);
    float* qv   = sym<float>(g_q);
    float* patt = sym<float>(g_att);
    float* px   = sym<float>(g_x);
    float* pt   = sym<float>(g_t);
    float* pdo  = sym<float>(g_do20);

    Epi ep_relu  = {nullptr, nullptr, nullptr, 1};
    Epi ep_plain = {nullptr, nullptr, nullptr, 0};

    // launch #3 (0-indexed) = conv1 hgemm for ncu capture
    dct_build<<<1, 256>>>();                                    // #0
    src_to_bf16<<<1024, 256>>>(src);                             // #1
    prep_c1w<<<240, 256>>>(Wk1, Wk1h, Wk1l);                     // #2
    hgemm<<<dim3(4, 80), 256, HG_SMEM>>>(srch, srcl, 1, 20, 0,   // #3  <- ncu target
        Wk1h, Wk1l, nullptr, k1h, k1l, nullptr, nullptr, 10240, K1P, ep_relu);
    prep_c2w<<<512, 256>>>(Wk2, Wk2h, Wk2l);                     // #4
    hgemm<<<dim3(4, 64), 256, HG_SMEM>>>(k1h, k1l, 2, 0, 0,      // #5
        Wk2h, Wk2l, key2, nullptr, nullptr, nullptr, nullptr, 8192, K2, ep_relu);

    // ---- query conv stack ----
    prep_c1w<<<240, 256>>>(Wq1, Wq1h, Wq1l);
    prep_c2w<<<512, 256>>>(Wq2, Wq2h, Wq2l);
    hgemm<<<dim3(4, 20), 256, HG_SMEM>>>(srch, srcl, 1, 5, TIN - KS_, Wq1h, Wq1l,
        nullptr, q1h, q1l, nullptr, nullptr, 2560, K1P, ep_relu);
    hgemm<<<dim3(4, 4, 16), 256, HG_SMEM>>>(q1h, q1l, 3, 0, 0, Wq2h, Wq2l,
        pt, nullptr, nullptr, nullptr, nullptr, 512, K2, ep_plain);
    reduce_relu<<<512, 256>>>(pt, qv, 512 * 512, 16);

    // ---- attention + x ----
    score_att_kernel<<<BSZ, 256>>>(qv, key2, patt);
    x_build<<<BSZ, 256>>>(src);

    // ---- remaining weight preps ----
    prep_KN<<<64, 256>>>(gc1_W, Wg1h, Wg1l, GCNIN, 512, 64);
    for (int li = 0; li < 4; li++)
        prep_KN<<<256, 256>>>(gcb_W + (size_t)li * 512 * 512,
                              Wgbh + (size_t)li * 512 * 512,
                              Wgbl + (size_t)li * 512 * 512, 512, 512, 512);
    prep_att<<<64, 256>>>(gcb_att, gc7_att);

    const int M = MROWS;

    // ---- gc1 ----
    {
        amix2<<<BSZ, 256>>>(gc1_att, px, Th, Tl, GCNIN, 64);
        Epi e = {gc1_b, bn1_g, bn1_b, 2};
        hgemm<<<dim3(4, M / 128), 256, HG_SMEM>>>(Th, Tl, 0, 0, 0, Wg1h, Wg1l,
            nullptr, yh, yl, nullptr, nullptr, M, 64, e);
    }

    // ---- 2 stages x 2 layers ----
    for (int st = 0; st < 2; st++) {
        for (int l = 0; l < 2; l++) {
            int li = st * 2 + l;
            const __nv_bfloat16* ih = (l == 0) ? yh : zh;
            const __nv_bfloat16* il = (l == 0) ? yl : zl;
            __nv_bfloat16* oh = (l == 0) ? zh : yh;
            __nv_bfloat16* ol = (l == 0) ? zl : yl;
            amix_mma<<<dim3(4, BSZ), 256, AM_SMEM>>>(Aph + li * 6400, Apl + li * 6400,
                                                     ih, il, Th, Tl, nullptr);
            Epi e = {gcb_b + (size_t)li * 512,
                     gcb_bn_g + (size_t)li * F66 * 512,
                     gcb_bn_b + (size_t)li * F66 * 512,
                     (l == 1) ? 3 : 2};
            hgemm<<<dim3(4, M / 128), 256, HG_SMEM>>>(Th, Tl, 0, 0, 0,
                Wgbh + (size_t)li * 512 * 512, Wgbl + (size_t)li * 512 * 512,
                nullptr, oh, ol,
                (l == 1) ? yh : nullptr, (l == 1) ? yl : nullptr, M, 512, e);
        }
    }

    // ---- gc7 (+x residual), N=20 only ----
    {
        amix_mma<<<dim3(4, BSZ), 256, AM_SMEM>>>(Aph + 4 * 6400, Apl + 4 * 6400,
                                                 yh, yl, nullptr, nullptr, pt);
        gc7_ffma<<<M / 128, 256>>>(pt, gc7_W, gc7_b, px, pdo);
    }

    // ---- final iDCT ----
    final_idct<<<4620, 256>>>(out);
    (void)in_sizes; (void)n_in; (void)out_size;
}

// round 13
// speedup vs baseline: 1.0108x; 1.0108x over previous
#include <cuda_runtime.h>
#include <cuda_bf16.h>
#include <math.h>
#include <stdint.h>

// ---------------- constants ----------------
#define BSZ   512
#define F66   66
#define TIN   50
#define KS_   10
#define VL    35          // KS + output_n
#define VN    16          // input_n - VL + 1
#define DCTN  20
#define GCNIN 40
#define MROWS (BSZ * F66) // 33792

#define FP    80          // padded feature row for src bf16 (160B pitch)
#define K1P   480         // conv1 K: 6*80
#define K2    2560        // conv2 K: 5*512

__device__ __forceinline__ uint32_t smem_u32(const void* p) {
    uint32_t a;
    asm("{ .reg .u64 t; cvta.to.shared.u64 t, %1; cvt.u32.u64 %0, t; }" : "=r"(a) : "l"(p));
    return a;
}

__device__ __forceinline__ void mma16816(float* c, const uint32_t* a, uint32_t b0, uint32_t b1) {
    asm volatile(
        "mma.sync.aligned.m16n8k16.row.col.f32.bf16.bf16.f32 "
        "{%0,%1,%2,%3}, {%4,%5,%6,%7}, {%8,%9}, {%0,%1,%2,%3};"
        : "+f"(c[0]), "+f"(c[1]), "+f"(c[2]), "+f"(c[3])
        : "r"(a[0]), "r"(a[1]), "r"(a[2]), "r"(a[3]), "r"(b0), "r"(b1));
}

#define LDSM4(r, addr) \
    asm volatile("ldmatrix.sync.aligned.m8n8.x4.shared.b16 {%0,%1,%2,%3}, [%4];" \
        : "=r"((r)[0]), "=r"((r)[1]), "=r"((r)[2]), "=r"((r)[3]) : "r"(addr))

#define LDSM4T(r, addr) \
    asm volatile("ldmatrix.sync.aligned.m8n8.x4.trans.shared.b16 {%0,%1,%2,%3}, [%4];" \
        : "=r"((r)[0]), "=r"((r)[1]), "=r"((r)[2]), "=r"((r)[3]) : "r"(addr))

#define CPA16(saddr, gptr) \
    asm volatile("cp.async.ca.shared.global [%0], [%1], 16;" :: "r"(saddr), "l"(gptr))

// swizzled 64B-row address: row r (64B stride), 16B-chunk c (0..3)
#define SWZ(r, c) ((uint32_t)(((r) << 6) + ((((c) ^ (((r) >> 1) & 3))) << 4)))

// ---------------- scratch (device globals; no allocation) ----------------
__device__ float g_dct[DCTN * VL];

#define SRCP_N (BSZ * TIN * FP)
__device__ __align__(16) __nv_bfloat16 g_srch[SRCP_N + 512];
__device__ __align__(16) __nv_bfloat16 g_srcl[SRCP_N + 512];
__device__ __align__(16) __nv_bfloat16 g_k1h[(size_t)10240 * 512];
__device__ __align__(16) __nv_bfloat16 g_k1l[(size_t)10240 * 512];
__device__ __align__(16) __nv_bfloat16 g_q1h[(size_t)2560 * 512];
__device__ __align__(16) __nv_bfloat16 g_q1l[(size_t)2560 * 512];

__device__ __align__(16) __nv_bfloat16 g_Wk1h[(size_t)512 * K1P];
__device__ __align__(16) __nv_bfloat16 g_Wk1l[(size_t)512 * K1P];
__device__ __align__(16) __nv_bfloat16 g_Wk2h[(size_t)512 * K2];
__device__ __align__(16) __nv_bfloat16 g_Wk2l[(size_t)512 * K2];
__device__ __align__(16) __nv_bfloat16 g_Wq1h[(size_t)512 * K1P];
__device__ __align__(16) __nv_bfloat16 g_Wq1l[(size_t)512 * K1P];
__device__ __align__(16) __nv_bfloat16 g_Wq2h[(size_t)512 * K2];
__device__ __align__(16) __nv_bfloat16 g_Wq2l[(size_t)512 * K2];
__device__ __align__(16) __nv_bfloat16 g_Wg1h[(size_t)512 * 64];
__device__ __align__(16) __nv_bfloat16 g_Wg1l[(size_t)512 * 64];
__device__ __align__(16) __nv_bfloat16 g_Wgbh[(size_t)4 * 512 * 512];
__device__ __align__(16) __nv_bfloat16 g_Wgbl[(size_t)4 * 512 * 512];
__device__ __align__(16) __nv_bfloat16 g_Th[(size_t)MROWS * 512];
__device__ __align__(16) __nv_bfloat16 g_Tl[(size_t)MROWS * 512];
__device__ __align__(16) __nv_bfloat16 g_yh[(size_t)MROWS * 512];
__device__ __align__(16) __nv_bfloat16 g_yl[(size_t)MROWS * 512];
__device__ __align__(16) __nv_bfloat16 g_zh[(size_t)MROWS * 512];
__device__ __align__(16) __nv_bfloat16 g_zl[(size_t)MROWS * 512];
__device__ __align__(16) __nv_bfloat16 g_Aph[5 * 80 * 80];
__device__ __align__(16) __nv_bfloat16 g_Apl[5 * 80 * 80];

__device__ float g_key2[(size_t)8192 * 512];
__device__ float g_q[(size_t)512 * 512];
__device__ float g_att[BSZ * VN];
__device__ float g_x[(size_t)BSZ * F66 * GCNIN];
__device__ float g_t[(size_t)MROWS * 512];
__device__ float g_do20[(size_t)MROWS * DCTN];

// ---------------- epilogue descriptor ----------------
// modes: 0 plain fp32, 1 relu, 2 bias+bn+tanh, 3 bias+bn+tanh+resid
struct Epi {
    const float* bias;
    const float* gamma;
    const float* beta;
    int mode;
};

__device__ __forceinline__ void split_bf16(float v, __nv_bfloat16& h, __nv_bfloat16& l) {
    h = __float2bfloat16_rn(v);
    l = __float2bfloat16_rn(v - __bfloat162float(h));
}

__device__ __forceinline__ uint32_t pack2(float a, float b, bool lo) {
    __nv_bfloat16 ha, la, hb, lb;
    split_bf16(a, ha, la); split_bf16(b, hb, lb);
    uint16_t x = lo ? __bfloat16_as_ushort(la) : __bfloat16_as_ushort(ha);
    uint16_t y = lo ? __bfloat16_as_ushort(lb) : __bfloat16_as_ushort(hb);
    return (uint32_t)x | ((uint32_t)y << 16);
}

// ---------------- dct matrix ----------------
__global__ void dct_build() {
    for (int i = threadIdx.x; i < DCTN * VL; i += blockDim.x) {
        int k = i / VL, v = i % VL;
        double w = (k == 0) ? sqrt(1.0 / VL) : sqrt(2.0 / VL);
        g_dct[i] = (float)(w * cos(3.14159265358979323846 * (v + 0.5) * k / VL));
    }
}

// ---------------- src -> bf16 hi/lo (x 1e-3), padded layout [b*50+t][80] ----------------
__global__ void src_to_bf16(const float* __restrict__ src) {
    int total = SRCP_N + 512;
    for (int i = blockIdx.x * blockDim.x + threadIdx.x; i < total;
         i += gridDim.x * blockDim.x) {
        float v = 0.f;
        if (i < SRCP_N) {
            int f = i % FP;
            int row = i / FP;
            if (f < F66) v = src[row * F66 + f] * 1e-3f;
        }
        __nv_bfloat16 h, l; split_bf16(v, h, l);
        g_srch[i] = h; g_srcl[i] = l;
    }
}

// ---------------- weight preps ----------------
__global__ void prep_c1w(const float* __restrict__ W, __nv_bfloat16* __restrict__ Bh,
                         __nv_bfloat16* __restrict__ Bl) {
    int total = 512 * K1P;
    for (int i = blockIdx.x * blockDim.x + threadIdx.x; i < total;
         i += gridDim.x * blockDim.x) {
        int n = i / K1P, k = i % K1P;
        int tt = k / FP, f = k % FP;
        float v = (f < F66) ? W[n * 396 + f * 6 + tt] : 0.f;
        __nv_bfloat16 h, l; split_bf16(v, h, l);
        Bh[i] = h; Bl[i] = l;
    }
}

__global__ void prep_c2w(const float* __restrict__ W, __nv_bfloat16* __restrict__ Bh,
                         __nv_bfloat16* __restrict__ Bl) {
    int total = 512 * K2;
    for (int i = blockIdx.x * blockDim.x + threadIdx.x; i < total;
         i += gridDim.x * blockDim.x) {
        int n = i / K2, k = i % K2;
        int tt = k >> 9, c = k & 511;
        float v = W[n * K2 + c * 5 + tt];
        __nv_bfloat16 h, l; split_bf16(v, h, l);
        Bh[i] = h; Bl[i] = l;
    }
}

__global__ void prep_KN(const float* __restrict__ W, __nv_bfloat16* __restrict__ Bh,
                        __nv_bfloat16* __restrict__ Bl, int K, int N, int Kp) {
    size_t total = (size_t)N * Kp;
    for (size_t i = (size_t)blockIdx.x * blockDim.x + threadIdx.x; i < total;
         i += (size_t)gridDim.x * blockDim.x) {
        int k = (int)(i % Kp);
        int n = (int)(i / Kp);
        float v = (k < K) ? W[(size_t)k * N + n] : 0.f;
        __nv_bfloat16 h, l; split_bf16(v, h, l);
        Bh[i] = h; Bl[i] = l;
    }
}

__global__ void prep_att(const float* __restrict__ gcb_att, const float* __restrict__ gc7_att) {
    int total = 5 * 80 * 80;
    for (int i = blockIdx.x * blockDim.x + threadIdx.x; i < total; i += gridDim.x * blockDim.x) {
        int li = i / 6400, rem = i % 6400;
        int r = rem / 80, c = rem % 80;
        float v = 0.f;
        if (r < F66 && c < F66) {
            const float* src = (li < 4) ? (gcb_att + (size_t)li * F66 * F66) : gc7_att;
            v = src[r * F66 + c];
        }
        __nv_bfloat16 h, l; split_bf16(v, h, l);
        g_Aph[i] = h; g_Apl[i] = l;
    }
}

// ---------------- HMMA bf16x3 GEMM, 128x128 tile, 256 threads, 2 CTAs/SM ----------------
// 8 warps (2m x 4n), warp tile 64x32. Swizzled 64B smem rows.
// 3-stage cp.async ring, ONE __syncthreads per chunk:
//   wait_group(1) -> barrier -> prefetch(kt+2) -> compute(kt)
// Buffer(kt+2 mod 3) == buffer(kt-1), free after the barrier (all warps completed
// compute(kt-1) in program order before reaching this barrier).
#define HG_SMEM 98304

__device__ __forceinline__ float epi_apply(float v, int col, int nmod, const Epi& e) {
    if (e.mode == 1) return fmaxf(v, 0.f);
    if (e.mode == 2 || e.mode == 3) {
        v += e.bias[col];
        int gi = nmod * 512 + col;
        v = tanhf(v * e.gamma[gi] * 0.9999950000374997f + e.beta[gi]);
    }
    return v;
}

__device__ __forceinline__ size_t amap(int amode, int r, int npos, int off, int K) {
    if (amode == 0)      return (size_t)r * K;
    else if (amode == 1) return ((size_t)(r / npos) * TIN + off + (r % npos)) * FP;
    else if (amode == 2) return ((size_t)(r >> 4) * 20 + (r & 15)) * 512;
    else                 return (size_t)r * 2560;
}

__global__ void __launch_bounds__(256, 2) hgemm(
    const __nv_bfloat16* __restrict__ Ah, const __nv_bfloat16* __restrict__ Al,
    int amode, int npos, int off,
    const __nv_bfloat16* __restrict__ Bh, const __nv_bfloat16* __restrict__ Bl,
    float* __restrict__ C, __nv_bfloat16* __restrict__ Ch, __nv_bfloat16* __restrict__ Cl,
    const __nv_bfloat16* __restrict__ Rh, const __nv_bfloat16* __restrict__ Rl,
    int M, int K, Epi e) {
    extern __shared__ __align__(16) char smem[];
    const uint32_t sb = smem_u32(smem);
    const int tid = threadIdx.x;
    const int bm0 = blockIdx.y * 128;
    const int bn0 = blockIdx.x * 128;
    const int warp = tid >> 5, lane = tid & 31;
    const int wm = warp & 1, wn = warp >> 1;   // wn 0..3 (32-col tiles)
    const int KT = K >> 5;
    const int nkt = KT / gridDim.z;
    const int kt0 = blockIdx.z * nkt;
    const int ktend = kt0 + nkt;

    const int lr = tid >> 2;          // 0..63
    const int lc = tid & 3;           // 16B chunk
    const size_t aRow0 = amap(amode, bm0 + lr, npos, off, K);
    const size_t aRow1 = amap(amode, bm0 + 64 + lr, npos, off, K);
    const size_t bRow0 = (size_t)(bn0 + lr) * K;
    const size_t bRow1 = (size_t)(bn0 + 64 + lr) * K;
    const uint32_t swA0 = SWZ(lr, lc);
    const uint32_t swA1 = SWZ(lr + 64, lc);

    float c[4][4][4];
#pragma unroll
    for (int i = 0; i < 4; i++)
#pragma unroll
        for (int j = 0; j < 4; j++)
#pragma unroll
            for (int q = 0; q < 4; q++) c[i][j][q] = 0.f;

#define HLOAD(bufo, kt) do {                                                       \
    const int k0 = (kt) << 5;                                                      \
    const uint32_t bo = sb + (uint32_t)(bufo);                                     \
    CPA16(bo + swA0, Ah + aRow0 + k0 + lc * 8);                                    \
    CPA16(bo + swA1, Ah + aRow1 + k0 + lc * 8);                                    \
    CPA16(bo + 8192u + swA0, Al + aRow0 + k0 + lc * 8);                            \
    CPA16(bo + 8192u + swA1, Al + aRow1 + k0 + lc * 8);                            \
    CPA16(bo + 16384u + swA0, Bh + bRow0 + k0 + lc * 8);                           \
    CPA16(bo + 16384u + swA1, Bh + bRow1 + k0 + lc * 8);                           \
    CPA16(bo + 24576u + swA0, Bl + bRow0 + k0 + lc * 8);                           \
    CPA16(bo + 24576u + swA1, Bl + bRow1 + k0 + lc * 8);                           \
    asm volatile("cp.async.commit_group;");                                        \
} while (0)

    // 3-stage prologue
    HLOAD(0u, kt0);
    if (kt0 + 1 < ktend) HLOAD(32768u, kt0 + 1);

    uint32_t bufc = 0u;        // buffer of current chunk
    uint32_t bufn = 65536u;    // buffer for the chunk 2 ahead (== buffer of kt-1)
    for (int kt = kt0; kt < ktend; kt++) {
        if (kt + 1 < ktend) {
            asm volatile("cp.async.wait_group 1;");
        } else {
            asm volatile("cp.async.wait_group 0;");
        }
        __syncthreads();
        if (kt + 2 < ktend) HLOAD(bufn, kt + 2);
        const uint32_t base = sb + bufc;
        bufc = (bufc == 65536u) ? 0u : bufc + 32768u;
        bufn = (bufn == 65536u) ? 0u : bufn + 32768u;
#pragma unroll
        for (int kh = 0; kh < 2; kh++) {
            uint32_t ah[4][4], al[4][4], bh2[2][4], bl2[2][4];
#pragma unroll
            for (int mi = 0; mi < 4; mi++) {
                int row = wm * 64 + mi * 16 + (lane & 7) + ((lane >> 3) & 1) * 8;
                int cc = kh * 2 + (lane >> 4);
                uint32_t ad = base + SWZ(row, cc);
                LDSM4(ah[mi], ad);
                LDSM4(al[mi], ad + 8192u);
            }
#pragma unroll
            for (int bi = 0; bi < 2; bi++) {
                int row = wn * 32 + bi * 16 + (lane & 7) + (lane >> 4) * 8;
                int cc = kh * 2 + ((lane >> 3) & 1);
                uint32_t bd = base + 16384u + SWZ(row, cc);
                LDSM4(bh2[bi], bd);
                LDSM4(bl2[bi], bd + 8192u);
            }
#pragma unroll
            for (int mi = 0; mi < 4; mi++)
#pragma unroll
                for (int ni = 0; ni < 4; ni++) {
                    uint32_t b0h = bh2[ni >> 1][(ni & 1) * 2];
                    uint32_t b1h = bh2[ni >> 1][(ni & 1) * 2 + 1];
                    uint32_t b0l = bl2[ni >> 1][(ni & 1) * 2];
                    uint32_t b1l = bl2[ni >> 1][(ni & 1) * 2 + 1];
                    mma16816(c[mi][ni], ah[mi], b0h, b1h);
                    mma16816(c[mi][ni], al[mi], b0h, b1h);
                    mma16816(c[mi][ni], ah[mi], b0l, b1l);
                }
        }
    }
#undef HLOAD

    // ---- epilogue ----
    float* Cz = C ? (C + (size_t)blockIdx.z * M * 512) : C;
#pragma unroll
    for (int mi = 0; mi < 4; mi++) {
        int r0 = bm0 + wm * 64 + mi * 16 + (lane >> 2);
        int r1 = r0 + 8;
        int nm0 = r0 % F66, nm1 = r1 % F66;
#pragma unroll
        for (int ni = 0; ni < 4; ni++) {
            int cb = bn0 + wn * 32 + ni * 8 + (lane & 3) * 2;
            size_t i0 = (size_t)r0 * 512 + cb;
            size_t i1 = (size_t)r1 * 512 + cb;
            float v0 = epi_apply(c[mi][ni][0], cb, nm0, e);
            float v1 = epi_apply(c[mi][ni][1], cb + 1, nm0, e);
            float v2 = epi_apply(c[mi][ni][2], cb, nm1, e);
            float v3 = epi_apply(c[mi][ni][3], cb + 1, nm1, e);
            if (e.mode == 3) {
                __nv_bfloat162 rh0 = *reinterpret_cast<const __nv_bfloat162*>(Rh + i0);
                __nv_bfloat162 rl0 = *reinterpret_cast<const __nv_bfloat162*>(Rl + i0);
                __nv_bfloat162 rh1 = *reinterpret_cast<const __nv_bfloat162*>(Rh + i1);
                __nv_bfloat162 rl1 = *reinterpret_cast<const __nv_bfloat162*>(Rl + i1);
                v0 += __bfloat162float(rh0.x) + __bfloat162float(rl0.x);
                v1 += __bfloat162float(rh0.y) + __bfloat162float(rl0.y);
                v2 += __bfloat162float(rh1.x) + __bfloat162float(rl1.x);
                v3 += __bfloat162float(rh1.y) + __bfloat162float(rl1.y);
            }
            if (Cz) {
                *reinterpret_cast<float2*>(Cz + i0) = make_float2(v0, v1);
                *reinterpret_cast<float2*>(Cz + i1) = make_float2(v2, v3);
            }
            if (Ch) {
                *reinterpret_cast<uint32_t*>(Ch + i0) = pack2(v0, v1, false);
                *reinterpret_cast<uint32_t*>(Cl + i0) = pack2(v0, v1, true);
                *reinterpret_cast<uint32_t*>(Ch + i1) = pack2(v2, v3, false);
                *reinterpret_cast<uint32_t*>(Cl + i1) = pack2(v2, v3, true);
            }
        }
    }
}

// ---------------- split-K reduce + relu ----------------
__global__ void reduce_relu(const float* __restrict__ part, float* __restrict__ outp,
                            int n, int zn) {
    for (int i = blockIdx.x * blockDim.x + threadIdx.x; i < n;
         i += gridDim.x * blockDim.x) {
        float s = 0.f;
        for (int z = 0; z < zn; z++) s += part[(size_t)z * n + i];
        outp[i] = fmaxf(s, 0.f);
    }
}

// ---------------- batched node-mix via HMMA ----------------
#define AM_SMEM 71680

__global__ void __launch_bounds__(256) amix_mma(
    const __nv_bfloat16* __restrict__ Aph, const __nv_bfloat16* __restrict__ Apl,
    const __nv_bfloat16* __restrict__ Yh, const __nv_bfloat16* __restrict__ Yl,
    __nv_bfloat16* __restrict__ Th, __nv_bfloat16* __restrict__ Tl,
    float* __restrict__ Tf) {
    extern __shared__ __align__(16) char smem[];
    const uint32_t sb = smem_u32(smem);
    const int b = blockIdx.y;
    const int f0 = blockIdx.x * 128;
    const int tid = threadIdx.x;
    const int warp = tid >> 5, lane = tid & 31;

    for (int i = tid; i < 800; i += 256) {
        int r = i / 10, cc = i % 10;
        uint32_t dst = sb + (uint32_t)(r * 176 + cc * 16);
        CPA16(dst, Aph + r * 80 + cc * 8);
        CPA16(dst + 14080u, Apl + r * 80 + cc * 8);
    }
    for (int i = tid; i < 1056; i += 256) {
        int r = i >> 4, cc = i & 15;
        uint32_t dst = sb + 28160u + (uint32_t)(r * 272 + cc * 16);
        const size_t gsrc = ((size_t)b * F66 + r) * 512 + f0 + cc * 8;
        CPA16(dst, Yh + gsrc);
        CPA16(dst + 21760u, Yl + gsrc);
    }
    asm volatile("cp.async.commit_group;");
    for (int i = tid; i < 224; i += 256) {
        int r = 66 + (i >> 4), cc = i & 15;
        uint32_t dst = sb + 28160u + (uint32_t)(r * 272 + cc * 16);
        asm volatile("st.shared.v4.b32 [%0], {%1,%1,%1,%1};" :: "r"(dst), "r"(0u));
        asm volatile("st.shared.v4.b32 [%0], {%1,%1,%1,%1};" :: "r"(dst + 21760u), "r"(0u));
    }
    asm volatile("cp.async.wait_group 0;");
    __syncthreads();

    const int n0c = warp * 16;
    uint32_t bh[5][4], bl[5][4];
#pragma unroll
    for (int kt = 0; kt < 5; kt++) {
        int row = kt * 16 + ((lane >> 3) & 1) * 8 + (lane & 7);
        int col = n0c + (lane >> 4) * 8;
        uint32_t ad = sb + 28160u + (uint32_t)(row * 272 + col * 2);
        LDSM4T(bh[kt], ad);
        LDSM4T(bl[kt], ad + 21760u);
    }

    float c[5][2][4];
#pragma unroll
    for (int mi = 0; mi < 5; mi++)
#pragma unroll
        for (int g = 0; g < 2; g++)
#pragma unroll
            for (int q = 0; q < 4; q++) c[mi][g][q] = 0.f;

#pragma unroll
    for (int mi = 0; mi < 5; mi++) {
#pragma unroll
        for (int kt = 0; kt < 5; kt++) {
            int row = mi * 16 + (lane & 7) + ((lane >> 3) & 1) * 8;
            int col = kt * 16 + (lane >> 4) * 8;
            uint32_t ad = sb + (uint32_t)(row * 176 + col * 2);
            uint32_t ah[4], al[4];
            LDSM4(ah, ad);
            LDSM4(al, ad + 14080u);
#pragma unroll
            for (int g = 0; g < 2; g++) {
                mma16816(c[mi][g], ah, bh[kt][g * 2], bh[kt][g * 2 + 1]);
                mma16816(c[mi][g], al, bh[kt][g * 2], bh[kt][g * 2 + 1]);
                mma16816(c[mi][g], ah, bl[kt][g * 2], bl[kt][g * 2 + 1]);
            }
        }
    }

#pragma unroll
    for (int mi = 0; mi < 5; mi++) {
        int n_0 = mi * 16 + (lane >> 2);
        int n_1 = n_0 + 8;
#pragma unroll
        for (int g = 0; g < 2; g++) {
            int f = f0 + n0c + g * 8 + (lane & 3) * 2;
            if (n_0 < F66) {
                size_t o = ((size_t)b * F66 + n_0) * 512 + f;
                if (Tf) {
                    *reinterpret_cast<float2*>(Tf + o) = make_float2(c[mi][g][0], c[mi][g][1]);
                } else {
                    *reinterpret_cast<uint32_t*>(Th + o) = pack2(c[mi][g][0], c[mi][g][1], false);
                    *reinterpret_cast<uint32_t*>(Tl + o) = pack2(c[mi][g][0], c[mi][g][1], true);
                }
            }
            if (n_1 < F66) {
                size_t o = ((size_t)b * F66 + n_1) * 512 + f;
                if (Tf) {
                    *reinterpret_cast<float2*>(Tf + o) = make_float2(c[mi][g][2], c[mi][g][3]);
                } else {
                    *reinterpret_cast<uint32_t*>(Th + o) = pack2(c[mi][g][2], c[mi][g][3], false);
                    *reinterpret_cast<uint32_t*>(Tl + o) = pack2(c[mi][g][2], c[mi][g][3], true);
                }
            }
        }
    }
}

// ---------------- gc7: C[M,20] = A[M,512] @ W[:, :20] + bias + x-resid ----------------
__global__ void __launch_bounds__(256) gc7_ffma(
    const float* __restrict__ A, const float* __restrict__ W,
    const float* __restrict__ bias, const float* __restrict__ xres,
    float* __restrict__ out20) {
    __shared__ float As[128][17];
    __shared__ float Bs[16][21];
    const int bm0 = blockIdx.x * 128;
    const int t = threadIdx.x;
    const int rp = t >> 2, cg = t & 3;
    float acc[2][5] = {};
    for (int k0 = 0; k0 < 512; k0 += 16) {
#pragma unroll
        for (int i = 0; i < 8; i++) {
            int idx = t + 256 * i;
            int r = idx >> 4, kk = idx & 15;
            As[r][kk] = A[(size_t)(bm0 + r) * 512 + k0 + kk];
        }
        for (int i = t; i < 320; i += 256) {
            int kk = i / 20, n = i % 20;
            Bs[kk][n] = W[(k0 + kk) * GCNIN + n];
        }
        __syncthreads();
#pragma unroll
        for (int kk = 0; kk < 16; kk++) {
            float a0 = As[rp * 2][kk], a1 = As[rp * 2 + 1][kk];
#pragma unroll
            for (int j = 0; j < 5; j++) {
                float bb = Bs[kk][cg * 5 + j];
                acc[0][j] += a0 * bb;
                acc[1][j] += a1 * bb;
            }
        }
        __syncthreads();
    }
#pragma unroll
    for (int rr = 0; rr < 2; rr++) {
        int row = bm0 + rp * 2 + rr;
#pragma unroll
        for (int j = 0; j < 5; j++) {
            int n = cg * 5 + j;
            out20[(size_t)row * DCTN + n] = acc[rr][j] + bias[n] + xres[(size_t)row * GCNIN + n];
        }
    }
}

// ---------------- attention: score + normalize ----------------
__global__ void score_att_kernel(const float* __restrict__ q,
                                 const float* __restrict__ key2,
                                 float* __restrict__ att) {
    int b = blockIdx.x;
    __shared__ float sc[VN];
    int t = threadIdx.x;
    int w = t / 32, lane = t % 32;
    for (int n = w; n < VN; n += 8) {
        float s = 0.f;
        const float* qp = q + (size_t)b * 512;
        const float* kp = key2 + (size_t)(b * VN + n) * 512;
        for (int d = lane; d < 512; d += 32) s += qp[d] * kp[d];
        for (int o = 16; o; o >>= 1) s += __shfl_xor_sync(0xffffffffu, s, o);
        if (lane == 0) sc[n] = s + 1e-15f;
    }
    __syncthreads();
    float tot = 0.f;
#pragma unroll
    for (int n = 0; n < VN; n++) tot += sc[n];
    if (t < VN) att[b * VN + t] = sc[t] / tot;
}

// ---------------- build x = [dct_in | dct_att]  (b, 66, 40) ----------------
__global__ void x_build(const float* __restrict__ src) {
    int b = blockIdx.x;
    int t = threadIdx.x;
    __shared__ float ss[TIN * F66];
    __shared__ float sh_s[VL * F66];
    __shared__ float sh_dct[DCTN * VL];
    __shared__ float sh_att[VN];
    for (int i = t; i < TIN * F66; i += 256) ss[i] = src[(size_t)b * TIN * F66 + i];
    for (int i = t; i < DCTN * VL; i += 256) sh_dct[i] = g_dct[i];
    if (t < VN) sh_att[t] = g_att[b * VN + t];
    __syncthreads();
    for (int i = t; i < VL * F66; i += 256) {
        int v = i / F66, f = i % F66;
        float a = 0.f;
#pragma unroll
        for (int n = 0; n < VN; n++) a += sh_att[n] * ss[(n + v) * F66 + f];
        sh_s[i] = a;
    }
    __syncthreads();
    for (int i = t; i < F66 * GCNIN; i += 256) {
        int f = i / GCNIN, k = i % GCNIN;
        float a = 0.f;
        if (k < DCTN) {
#pragma unroll
            for (int v = 0; v < VL; v++) {
                int r = (v < KS_) ? (TIN - KS_ + v) : (TIN - 1);
                a += sh_dct[k * VL + v] * ss[r * F66 + f];
            }
        } else {
            int kk = k - DCTN;
#pragma unroll
            for (int v = 0; v < VL; v++) a += sh_dct[kk * VL + v] * sh_s[v * F66 + f];
        }
        g_x[(size_t)b * F66 * GCNIN + i] = a;
    }
}

// ---------------- scalar node mix for gc1 (F=40 -> Th/Tl Kp=64) ----------------
__global__ void __launch_bounds__(256) amix2(
    const float* __restrict__ A, const float* __restrict__ in,
    __nv_bfloat16* __restrict__ oh, __nv_bfloat16* __restrict__ ol, int F, int Kp) {
    int b = blockIdx.x;
    __shared__ float Ash[F66 * F66];
    __shared__ float insh[F66][64];
    int t = threadIdx.x;
    for (int i = t; i < F66 * F66; i += 256) Ash[i] = A[i];
    int fw = F;
    for (int i = t; i < F66 * 64; i += 256) {
        int m = i >> 6, f = i & 63;
        insh[m][f] = (f < fw) ? in[((size_t)b * F66 + m) * F + f] : 0.f;
    }
    __syncthreads();
    int w = t >> 5, lane = t & 31;
    int h = lane >> 4, sub = lane & 15;
    int fl = sub * 4;
#pragma unroll
    for (int pass = 0; pass < 5; pass++) {
        int n = pass * 16 + w * 2 + h;
        int nn = (n < F66) ? n : 0;
        const float* arow = Ash + nn * F66;
        float ax = 0.f, ay = 0.f, az = 0.f, aw = 0.f;
#pragma unroll 6
        for (int m = 0; m < F66; m++) {
            float a = arow[m];
            float4 yv = *reinterpret_cast<const float4*>(&insh[m][fl]);
            ax += a * yv.x; ay += a * yv.y; az += a * yv.z; aw += a * yv.w;
        }
        if (n < F66) {
            float vals[4] = {ax, ay, az, aw};
            size_t o = ((size_t)b * F66 + n) * Kp + fl;
#pragma unroll
            for (int j = 0; j < 4; j++) {
                float v = (fl + j < fw) ? vals[j] : 0.f;
                __nv_bfloat16 hh, ll; split_bf16(v, hh, ll);
                oh[o + j] = hh; ol[o + j] = ll;
            }
        }
    }
}

// ---------------- final iDCT (reads compact [M][20] dct_out) ----------------
__global__ void final_idct(float* __restrict__ out) {
    size_t total = (size_t)BSZ * VL * F66;
    for (size_t i = (size_t)blockIdx.x * blockDim.x + threadIdx.x; i < total;
         i += (size_t)gridDim.x * blockDim.x) {
        int f = (int)(i % F66);
        int v = (int)((i / F66) % VL);
        int b = (int)(i / ((size_t)F66 * VL));
        float a = 0.f;
#pragma unroll
        for (int k = 0; k < DCTN; k++)
            a += g_dct[k * VL + v] * g_do20[((size_t)b * F66 + f) * DCTN + k];
        out[i] = a;
    }
}

// ---------------- host launcher ----------------
template <typename T>
static T* sym(const void* s) {
    void* p = nullptr;
    cudaGetSymbolAddress(&p, s);
    return (T*)p;
}

extern "C" void kernel_launch(void* const* d_in, const int* in_sizes, int n_in,
                              void* d_out, int out_size) {
    const float* src     = (const float*)d_in[0];
    const float* Wq1     = (const float*)d_in[1];
    const float* Wq2     = (const float*)d_in[2];
    const float* Wk1     = (const float*)d_in[3];
    const float* Wk2     = (const float*)d_in[4];
    const float* gc1_W   = (const float*)d_in[5];
    const float* gc1_att = (const float*)d_in[6];
    const float* gc1_b   = (const float*)d_in[7];
    const float* bn1_g   = (const float*)d_in[8];
    const float* bn1_b   = (const float*)d_in[9];
    const float* gcb_W   = (const float*)d_in[10];
    const float* gcb_att = (const float*)d_in[11];
    const float* gcb_b   = (const float*)d_in[12];
    const float* gcb_bn_g= (const float*)d_in[13];
    const float* gcb_bn_b= (const float*)d_in[14];
    const float* gc7_W   = (const float*)d_in[15];
    const float* gc7_att = (const float*)d_in[16];
    const float* gc7_b   = (const float*)d_in[17];
    float* out = (float*)d_out;

    cudaFuncSetAttribute(hgemm, cudaFuncAttributeMaxDynamicSharedMemorySize, HG_SMEM);
    cudaFuncSetAttribute(amix_mma, cudaFuncAttributeMaxDynamicSharedMemorySize, AM_SMEM);

    __nv_bfloat16* srch = sym<__nv_bfloat16>(g_srch); __nv_bfloat16* srcl = sym<__nv_bfloat16>(g_srcl);
    __nv_bfloat16* k1h  = sym<__nv_bfloat16>(g_k1h);  __nv_bfloat16* k1l  = sym<__nv_bfloat16>(g_k1l);
    __nv_bfloat16* q1h  = sym<__nv_bfloat16>(g_q1h);  __nv_bfloat16* q1l  = sym<__nv_bfloat16>(g_q1l);
    __nv_bfloat16* Wk1h = sym<__nv_bfloat16>(g_Wk1h); __nv_bfloat16* Wk1l = sym<__nv_bfloat16>(g_Wk1l);
    __nv_bfloat16* Wk2h = sym<__nv_bfloat16>(g_Wk2h); __nv_bfloat16* Wk2l = sym<__nv_bfloat16>(g_Wk2l);
    __nv_bfloat16* Wq1h = sym<__nv_bfloat16>(g_Wq1h); __nv_bfloat16* Wq1l = sym<__nv_bfloat16>(g_Wq1l);
    __nv_bfloat16* Wq2h = sym<__nv_bfloat16>(g_Wq2h); __nv_bfloat16* Wq2l = sym<__nv_bfloat16>(g_Wq2l);
    __nv_bfloat16* Wg1h = sym<__nv_bfloat16>(g_Wg1h); __nv_bfloat16* Wg1l = sym<__nv_bfloat16>(g_Wg1l);
    __nv_bfloat16* Wgbh = sym<__nv_bfloat16>(g_Wgbh); __nv_bfloat16* Wgbl = sym<__nv_bfloat16>(g_Wgbl);
    __nv_bfloat16* Th   = sym<__nv_bfloat16>(g_Th);   __nv_bfloat16* Tl   = sym<__nv_bfloat16>(g_Tl);
    __nv_bfloat16* yh   = sym<__nv_bfloat16>(g_yh);   __nv_bfloat16* yl   = sym<__nv_bfloat16>(g_yl);
    __nv_bfloat16* zh   = sym<__nv_bfloat16>(g_zh);   __nv_bfloat16* zl   = sym<__nv_bfloat16>(g_zl);
    __nv_bfloat16* Aph  = sym<__nv_bfloat16>(g_Aph);  __nv_bfloat16* Apl  = sym<__nv_bfloat16>(g_Apl);

    float* key2 = sym<float>(g_key2);
    float* qv   = sym<float>(g_q);
    float* patt = sym<float>(g_att);
    float* px   = sym<float>(g_x);
    float* pt   = sym<float>(g_t);
    float* pdo  = sym<float>(g_do20);

    Epi ep_relu  = {nullptr, nullptr, nullptr, 1};
    Epi ep_plain = {nullptr, nullptr, nullptr, 0};

    // launch #3 (0-indexed) = conv1 hgemm for ncu capture
    dct_build<<<1, 256>>>();                                    // #0
    src_to_bf16<<<1024, 256>>>(src);                             // #1
    prep_c1w<<<240, 256>>>(Wk1, Wk1h, Wk1l);                     // #2
    hgemm<<<dim3(4, 80), 256, HG_SMEM>>>(srch, srcl, 1, 20, 0,   // #3  <- ncu target
        Wk1h, Wk1l, nullptr, k1h, k1l, nullptr, nullptr, 10240, K1P, ep_relu);
    prep_c2w<<<512, 256>>>(Wk2, Wk2h, Wk2l);                     // #4
    hgemm<<<dim3(4, 64), 256, HG_SMEM>>>(k1h, k1l, 2, 0, 0,      // #5
        Wk2h, Wk2l, key2, nullptr, nullptr, nullptr, nullptr, 8192, K2, ep_relu);

    // ---- query conv stack ----
    prep_c1w<<<240, 256>>>(Wq1, Wq1h, Wq1l);
    prep_c2w<<<512, 256>>>(Wq2, Wq2h, Wq2l);
    hgemm<<<dim3(4, 20), 256, HG_SMEM>>>(srch, srcl, 1, 5, TIN - KS_, Wq1h, Wq1l,
        nullptr, q1h, q1l, nullptr, nullptr, 2560, K1P, ep_relu);
    hgemm<<<dim3(4, 4, 16), 256, HG_SMEM>>>(q1h, q1l, 3, 0, 0, Wq2h, Wq2l,
        pt, nullptr, nullptr, nullptr, nullptr, 512, K2, ep_plain);
    reduce_relu<<<512, 256>>>(pt, qv, 512 * 512, 16);

    // ---- attention + x ----
    score_att_kernel<<<BSZ, 256>>>(qv, key2, patt);
    x_build<<<BSZ, 256>>>(src);

    // ---- remaining weight preps ----
    prep_KN<<<64, 256>>>(gc1_W, Wg1h, Wg1l, GCNIN, 512, 64);
    for (int li = 0; li < 4; li++)
        prep_KN<<<256, 256>>>(gcb_W + (size_t)li * 512 * 512,
                              Wgbh + (size_t)li * 512 * 512,
                              Wgbl + (size_t)li * 512 * 512, 512, 512, 512);
    prep_att<<<64, 256>>>(gcb_att, gc7_att);

    const int M = MROWS;

    // ---- gc1 ----
    {
        amix2<<<BSZ, 256>>>(gc1_att, px, Th, Tl, GCNIN, 64);
        Epi e = {gc1_b, bn1_g, bn1_b, 2};
        hgemm<<<dim3(4, M / 128), 256, HG_SMEM>>>(Th, Tl, 0, 0, 0, Wg1h, Wg1l,
            nullptr, yh, yl, nullptr, nullptr, M, 64, e);
    }

    // ---- 2 stages x 2 layers ----
    for (int st = 0; st < 2; st++) {
        for (int l = 0; l < 2; l++) {
            int li = st * 2 + l;
            const __nv_bfloat16* ih = (l == 0) ? yh : zh;
            const __nv_bfloat16* il = (l == 0) ? yl : zl;
            __nv_bfloat16* oh = (l == 0) ? zh : yh;
            __nv_bfloat16* ol = (l == 0) ? zl : yl;
            amix_mma<<<dim3(4, BSZ), 256, AM_SMEM>>>(Aph + li * 6400, Apl + li * 6400,
                                                     ih, il, Th, Tl, nullptr);
            Epi e = {gcb_b + (size_t)li * 512,
                     gcb_bn_g + (size_t)li * F66 * 512,
                     gcb_bn_b + (size_t)li * F66 * 512,
                     (l == 1) ? 3 : 2};
            hgemm<<<dim3(4, M / 128), 256, HG_SMEM>>>(Th, Tl, 0, 0, 0,
                Wgbh + (size_t)li * 512 * 512, Wgbl + (size_t)li * 512 * 512,
                nullptr, oh, ol,
                (l == 1) ? yh : nullptr, (l == 1) ? yl : nullptr, M, 512, e);
        }
    }

    // ---- gc7 (+x residual), N=20 only ----
    {
        amix_mma<<<dim3(4, BSZ), 256, AM_SMEM>>>(Aph + 4 * 6400, Apl + 4 * 6400,
                                                 yh, yl, nullptr, nullptr, pt);
        gc7_ffma<<<M / 128, 256>>>(pt, gc7_W, gc7_b, px, pdo);
    }

    // ---- final iDCT ----
    final_idct<<<4620, 256>>>(out);
    (void)in_sizes; (void)n_in; (void)out_size;
}

// round 14
// speedup vs baseline: 1.0323x; 1.0213x over previous
#include <cuda_runtime.h>
#include <cuda_bf16.h>
#include <math.h>
#include <stdint.h>

// ---------------- constants ----------------
#define BSZ   512
#define F66   66
#define TIN   50
#define KS_   10
#define VL    35          // KS + output_n
#define VN    16          // input_n - VL + 1
#define DCTN  20
#define GCNIN 40
#define MROWS (BSZ * F66) // 33792

#define FP    80          // padded feature row for src bf16 (160B pitch)
#define K1P   480         // conv1 K: 6*80
#define K2    2560        // conv2 K: 5*512

__device__ __forceinline__ uint32_t smem_u32(const void* p) {
    uint32_t a;
    asm("{ .reg .u64 t; cvta.to.shared.u64 t, %1; cvt.u32.u64 %0, t; }" : "=r"(a) : "l"(p));
    return a;
}

__device__ __forceinline__ void mma16816(float* c, const uint32_t* a, uint32_t b0, uint32_t b1) {
    asm volatile(
        "mma.sync.aligned.m16n8k16.row.col.f32.bf16.bf16.f32 "
        "{%0,%1,%2,%3}, {%4,%5,%6,%7}, {%8,%9}, {%0,%1,%2,%3};"
        : "+f"(c[0]), "+f"(c[1]), "+f"(c[2]), "+f"(c[3])
        : "r"(a[0]), "r"(a[1]), "r"(a[2]), "r"(a[3]), "r"(b0), "r"(b1));
}

#define LDSM4(r, addr) \
    asm volatile("ldmatrix.sync.aligned.m8n8.x4.shared.b16 {%0,%1,%2,%3}, [%4];" \
        : "=r"((r)[0]), "=r"((r)[1]), "=r"((r)[2]), "=r"((r)[3]) : "r"(addr))

#define LDSM4T(r, addr) \
    asm volatile("ldmatrix.sync.aligned.m8n8.x4.trans.shared.b16 {%0,%1,%2,%3}, [%4];" \
        : "=r"((r)[0]), "=r"((r)[1]), "=r"((r)[2]), "=r"((r)[3]) : "r"(addr))

#define CPA16(saddr, gptr) \
    asm volatile("cp.async.ca.shared.global [%0], [%1], 16;" :: "r"(saddr), "l"(gptr))

// swizzled 64B-row address: row r (64B stride), 16B-chunk c (0..3)
#define SWZ(r, c) ((uint32_t)(((r) << 6) + ((((c) ^ (((r) >> 1) & 3))) << 4)))

// ---------------- scratch (device globals; no allocation) ----------------
__device__ float g_dct[DCTN * VL];

#define SRCP_N (BSZ * TIN * FP)
__device__ __align__(16) __nv_bfloat16 g_srch[SRCP_N + 512];
__device__ __align__(16) __nv_bfloat16 g_srcl[SRCP_N + 512];
__device__ __align__(16) __nv_bfloat16 g_k1h[(size_t)10240 * 512];
__device__ __align__(16) __nv_bfloat16 g_k1l[(size_t)10240 * 512];
__device__ __align__(16) __nv_bfloat16 g_q1h[(size_t)2560 * 512];
__device__ __align__(16) __nv_bfloat16 g_q1l[(size_t)2560 * 512];

__device__ __align__(16) __nv_bfloat16 g_Wk1h[(size_t)512 * K1P];
__device__ __align__(16) __nv_bfloat16 g_Wk1l[(size_t)512 * K1P];
__device__ __align__(16) __nv_bfloat16 g_Wk2h[(size_t)512 * K2];
__device__ __align__(16) __nv_bfloat16 g_Wk2l[(size_t)512 * K2];
__device__ __align__(16) __nv_bfloat16 g_Wq1h[(size_t)512 * K1P];
__device__ __align__(16) __nv_bfloat16 g_Wq1l[(size_t)512 * K1P];
__device__ __align__(16) __nv_bfloat16 g_Wq2h[(size_t)512 * K2];
__device__ __align__(16) __nv_bfloat16 g_Wq2l[(size_t)512 * K2];
__device__ __align__(16) __nv_bfloat16 g_Wg1h[(size_t)512 * 64];
__device__ __align__(16) __nv_bfloat16 g_Wg1l[(size_t)512 * 64];
__device__ __align__(16) __nv_bfloat16 g_Wgbh[(size_t)4 * 512 * 512];
__device__ __align__(16) __nv_bfloat16 g_Wgbl[(size_t)4 * 512 * 512];
__device__ __align__(16) __nv_bfloat16 g_Th[(size_t)MROWS * 512];
__device__ __align__(16) __nv_bfloat16 g_Tl[(size_t)MROWS * 512];
__device__ __align__(16) __nv_bfloat16 g_yh[(size_t)MROWS * 512];
__device__ __align__(16) __nv_bfloat16 g_yl[(size_t)MROWS * 512];
__device__ __align__(16) __nv_bfloat16 g_zh[(size_t)MROWS * 512];
__device__ __align__(16) __nv_bfloat16 g_zl[(size_t)MROWS * 512];
__device__ __align__(16) __nv_bfloat16 g_Aph[5 * 80 * 80];
__device__ __align__(16) __nv_bfloat16 g_Apl[5 * 80 * 80];

__device__ float g_key2[(size_t)8192 * 512];
__device__ float g_q[(size_t)512 * 512];
__device__ float g_att[BSZ * VN];
__device__ float g_x[(size_t)BSZ * F66 * GCNIN];
__device__ float g_t[(size_t)MROWS * 512];
__device__ float g_do20[(size_t)MROWS * DCTN];

// ---------------- epilogue descriptor ----------------
// modes: 0 plain fp32, 1 relu, 2 bias+bn+tanh, 3 bias+bn+tanh+resid
struct Epi {
    const float* bias;
    const float* gamma;
    const float* beta;
    int mode;
};

__device__ __forceinline__ void split_bf16(float v, __nv_bfloat16& h, __nv_bfloat16& l) {
    h = __float2bfloat16_rn(v);
    l = __float2bfloat16_rn(v - __bfloat162float(h));
}

__device__ __forceinline__ uint32_t pack2(float a, float b, bool lo) {
    __nv_bfloat16 ha, la, hb, lb;
    split_bf16(a, ha, la); split_bf16(b, hb, lb);
    uint16_t x = lo ? __bfloat16_as_ushort(la) : __bfloat16_as_ushort(ha);
    uint16_t y = lo ? __bfloat16_as_ushort(lb) : __bfloat16_as_ushort(hb);
    return (uint32_t)x | ((uint32_t)y << 16);
}

// ---------------- dct matrix ----------------
__global__ void dct_build() {
    for (int i = threadIdx.x; i < DCTN * VL; i += blockDim.x) {
        int k = i / VL, v = i % VL;
        double w = (k == 0) ? sqrt(1.0 / VL) : sqrt(2.0 / VL);
        g_dct[i] = (float)(w * cos(3.14159265358979323846 * (v + 0.5) * k / VL));
    }
}

// ---------------- src -> bf16 hi/lo (x 1e-3), padded layout [b*50+t][80] ----------------
__global__ void src_to_bf16(const float* __restrict__ src) {
    int total = SRCP_N + 512;
    for (int i = blockIdx.x * blockDim.x + threadIdx.x; i < total;
         i += gridDim.x * blockDim.x) {
        float v = 0.f;
        if (i < SRCP_N) {
            int f = i % FP;
            int row = i / FP;
            if (f < F66) v = src[row * F66 + f] * 1e-3f;
        }
        __nv_bfloat16 h, l; split_bf16(v, h, l);
        g_srch[i] = h; g_srcl[i] = l;
    }
}

// ---------------- weight preps ----------------
__global__ void prep_c1w(const float* __restrict__ W, __nv_bfloat16* __restrict__ Bh,
                         __nv_bfloat16* __restrict__ Bl) {
    int total = 512 * K1P;
    for (int i = blockIdx.x * blockDim.x + threadIdx.x; i < total;
         i += gridDim.x * blockDim.x) {
        int n = i / K1P, k = i % K1P;
        int tt = k / FP, f = k % FP;
        float v = (f < F66) ? W[n * 396 + f * 6 + tt] : 0.f;
        __nv_bfloat16 h, l; split_bf16(v, h, l);
        Bh[i] = h; Bl[i] = l;
    }
}

__global__ void prep_c2w(const float* __restrict__ W, __nv_bfloat16* __restrict__ Bh,
                         __nv_bfloat16* __restrict__ Bl) {
    int total = 512 * K2;
    for (int i = blockIdx.x * blockDim.x + threadIdx.x; i < total;
         i += gridDim.x * blockDim.x) {
        int n = i / K2, k = i % K2;
        int tt = k >> 9, c = k & 511;
        float v = W[n * K2 + c * 5 + tt];
        __nv_bfloat16 h, l; split_bf16(v, h, l);
        Bh[i] = h; Bl[i] = l;
    }
}

__global__ void prep_KN(const float* __restrict__ W, __nv_bfloat16* __restrict__ Bh,
                        __nv_bfloat16* __restrict__ Bl, int K, int N, int Kp) {
    size_t total = (size_t)N * Kp;
    for (size_t i = (size_t)blockIdx.x * blockDim.x + threadIdx.x; i < total;
         i += (size_t)gridDim.x * blockDim.x) {
        int k = (int)(i % Kp);
        int n = (int)(i / Kp);
        float v = (k < K) ? W[(size_t)k * N + n] : 0.f;
        __nv_bfloat16 h, l; split_bf16(v, h, l);
        Bh[i] = h; Bl[i] = l;
    }
}

__global__ void prep_att(const float* __restrict__ gcb_att, const float* __restrict__ gc7_att) {
    int total = 5 * 80 * 80;
    for (int i = blockIdx.x * blockDim.x + threadIdx.x; i < total; i += gridDim.x * blockDim.x) {
        int li = i / 6400, rem = i % 6400;
        int r = rem / 80, c = rem % 80;
        float v = 0.f;
        if (r < F66 && c < F66) {
            const float* src = (li < 4) ? (gcb_att + (size_t)li * F66 * F66) : gc7_att;
            v = src[r * F66 + c];
        }
        __nv_bfloat16 h, l; split_bf16(v, h, l);
        g_Aph[i] = h; g_Apl[i] = l;
    }
}

// ---------------- HMMA bf16x3 GEMM, 128x128 tile, 256 threads, 2 CTAs/SM ----------------
// (round-11 best config: 2-stage double buffer, two barriers per chunk)
#define HG_SMEM 65536

__device__ __forceinline__ float epi_apply(float v, int col, int nmod, const Epi& e) {
    if (e.mode == 1) return fmaxf(v, 0.f);
    if (e.mode == 2 || e.mode == 3) {
        v += e.bias[col];
        int gi = nmod * 512 + col;
        v = tanhf(v * e.gamma[gi] * 0.9999950000374997f + e.beta[gi]);
    }
    return v;
}

__device__ __forceinline__ size_t amap(int amode, int r, int npos, int off, int K) {
    if (amode == 0)      return (size_t)r * K;
    else if (amode == 1) return ((size_t)(r / npos) * TIN + off + (r % npos)) * FP;
    else if (amode == 2) return ((size_t)(r >> 4) * 20 + (r & 15)) * 512;
    else                 return (size_t)r * 2560;
}

__global__ void __launch_bounds__(256, 2) hgemm(
    const __nv_bfloat16* __restrict__ Ah, const __nv_bfloat16* __restrict__ Al,
    int amode, int npos, int off,
    const __nv_bfloat16* __restrict__ Bh, const __nv_bfloat16* __restrict__ Bl,
    float* __restrict__ C, __nv_bfloat16* __restrict__ Ch, __nv_bfloat16* __restrict__ Cl,
    const __nv_bfloat16* __restrict__ Rh, const __nv_bfloat16* __restrict__ Rl,
    int M, int K, Epi e) {
    extern __shared__ __align__(16) char smem[];
    const uint32_t sb = smem_u32(smem);
    const int tid = threadIdx.x;
    const int bm0 = blockIdx.y * 128;
    const int bn0 = blockIdx.x * 128;
    const int warp = tid >> 5, lane = tid & 31;
    const int wm = warp & 1, wn = warp >> 1;
    const int KT = K >> 5;
    const int nkt = KT / gridDim.z;
    const int kt0 = blockIdx.z * nkt;
    const int ktend = kt0 + nkt;

    const int lr = tid >> 2;
    const int lc = tid & 3;
    const size_t aRow0 = amap(amode, bm0 + lr, npos, off, K);
    const size_t aRow1 = amap(amode, bm0 + 64 + lr, npos, off, K);
    const size_t bRow0 = (size_t)(bn0 + lr) * K;
    const size_t bRow1 = (size_t)(bn0 + 64 + lr) * K;
    const uint32_t swA0 = SWZ(lr, lc);
    const uint32_t swA1 = SWZ(lr + 64, lc);

    float c[4][4][4];
#pragma unroll
    for (int i = 0; i < 4; i++)
#pragma unroll
        for (int j = 0; j < 4; j++)
#pragma unroll
            for (int q = 0; q < 4; q++) c[i][j][q] = 0.f;

#define HLOAD(buf, kt) do {                                                        \
    const int k0 = (kt) << 5;                                                      \
    const uint32_t bo = sb + (uint32_t)(buf) * 32768u;                             \
    CPA16(bo + swA0, Ah + aRow0 + k0 + lc * 8);                                    \
    CPA16(bo + swA1, Ah + aRow1 + k0 + lc * 8);                                    \
    CPA16(bo + 8192u + swA0, Al + aRow0 + k0 + lc * 8);                            \
    CPA16(bo + 8192u + swA1, Al + aRow1 + k0 + lc * 8);                            \
    CPA16(bo + 16384u + swA0, Bh + bRow0 + k0 + lc * 8);                           \
    CPA16(bo + 16384u + swA1, Bh + bRow1 + k0 + lc * 8);                           \
    CPA16(bo + 24576u + swA0, Bl + bRow0 + k0 + lc * 8);                           \
    CPA16(bo + 24576u + swA1, Bl + bRow1 + k0 + lc * 8);                           \
    asm volatile("cp.async.commit_group;");                                        \
} while (0)

    HLOAD(0, kt0);
    for (int kt = kt0; kt < ktend; kt++) {
        const int buf = (kt - kt0) & 1;
        if (kt + 1 < ktend) {
            HLOAD(buf ^ 1, kt + 1);
            asm volatile("cp.async.wait_group 1;");
        } else {
            asm volatile("cp.async.wait_group 0;");
        }
        __syncthreads();
        const uint32_t base = sb + (uint32_t)buf * 32768u;
#pragma unroll
        for (int kh = 0; kh < 2; kh++) {
            uint32_t ah[4][4], al[4][4], bh2[2][4], bl2[2][4];
#pragma unroll
            for (int mi = 0; mi < 4; mi++) {
                int row = wm * 64 + mi * 16 + (lane & 7) + ((lane >> 3) & 1) * 8;
                int cc = kh * 2 + (lane >> 4);
                uint32_t ad = base + SWZ(row, cc);
                LDSM4(ah[mi], ad);
                LDSM4(al[mi], ad + 8192u);
            }
#pragma unroll
            for (int bi = 0; bi < 2; bi++) {
                int row = wn * 32 + bi * 16 + (lane & 7) + (lane >> 4) * 8;
                int cc = kh * 2 + ((lane >> 3) & 1);
                uint32_t bd = base + 16384u + SWZ(row, cc);
                LDSM4(bh2[bi], bd);
                LDSM4(bl2[bi], bd + 8192u);
            }
#pragma unroll
            for (int mi = 0; mi < 4; mi++)
#pragma unroll
                for (int ni = 0; ni < 4; ni++) {
                    uint32_t b0h = bh2[ni >> 1][(ni & 1) * 2];
                    uint32_t b1h = bh2[ni >> 1][(ni & 1) * 2 + 1];
                    uint32_t b0l = bl2[ni >> 1][(ni & 1) * 2];
                    uint32_t b1l = bl2[ni >> 1][(ni & 1) * 2 + 1];
                    mma16816(c[mi][ni], ah[mi], b0h, b1h);
                    mma16816(c[mi][ni], al[mi], b0h, b1h);
                    mma16816(c[mi][ni], ah[mi], b0l, b1l);
                }
        }
        __syncthreads();
    }
#undef HLOAD

    // ---- epilogue ----
    float* Cz = C ? (C + (size_t)blockIdx.z * M * 512) : C;
#pragma unroll
    for (int mi = 0; mi < 4; mi++) {
        int r0 = bm0 + wm * 64 + mi * 16 + (lane >> 2);
        int r1 = r0 + 8;
        int nm0 = r0 % F66, nm1 = r1 % F66;
#pragma unroll
        for (int ni = 0; ni < 4; ni++) {
            int cb = bn0 + wn * 32 + ni * 8 + (lane & 3) * 2;
            size_t i0 = (size_t)r0 * 512 + cb;
            size_t i1 = (size_t)r1 * 512 + cb;
            float v0 = epi_apply(c[mi][ni][0], cb, nm0, e);
            float v1 = epi_apply(c[mi][ni][1], cb + 1, nm0, e);
            float v2 = epi_apply(c[mi][ni][2], cb, nm1, e);
            float v3 = epi_apply(c[mi][ni][3], cb + 1, nm1, e);
            if (e.mode == 3) {
                __nv_bfloat162 rh0 = *reinterpret_cast<const __nv_bfloat162*>(Rh + i0);
                __nv_bfloat162 rl0 = *reinterpret_cast<const __nv_bfloat162*>(Rl + i0);
                __nv_bfloat162 rh1 = *reinterpret_cast<const __nv_bfloat162*>(Rh + i1);
                __nv_bfloat162 rl1 = *reinterpret_cast<const __nv_bfloat162*>(Rl + i1);
                v0 += __bfloat162float(rh0.x) + __bfloat162float(rl0.x);
                v1 += __bfloat162float(rh0.y) + __bfloat162float(rl0.y);
                v2 += __bfloat162float(rh1.x) + __bfloat162float(rl1.x);
                v3 += __bfloat162float(rh1.y) + __bfloat162float(rl1.y);
            }
            if (Cz) {
                *reinterpret_cast<float2*>(Cz + i0) = make_float2(v0, v1);
                *reinterpret_cast<float2*>(Cz + i1) = make_float2(v2, v3);
            }
            if (Ch) {
                *reinterpret_cast<uint32_t*>(Ch + i0) = pack2(v0, v1, false);
                *reinterpret_cast<uint32_t*>(Cl + i0) = pack2(v0, v1, true);
                *reinterpret_cast<uint32_t*>(Ch + i1) = pack2(v2, v3, false);
                *reinterpret_cast<uint32_t*>(Cl + i1) = pack2(v2, v3, true);
            }
        }
    }
}

// ---------------- split-K reduce + relu ----------------
__global__ void reduce_relu(const float* __restrict__ part, float* __restrict__ outp,
                            int n, int zn) {
    for (int i = blockIdx.x * blockDim.x + threadIdx.x; i < n;
         i += gridDim.x * blockDim.x) {
        float s = 0.f;
        for (int z = 0; z < zn; z++) s += part[(size_t)z * n + i];
        outp[i] = fmaxf(s, 0.f);
    }
}

// ---------------- batched node-mix via HMMA ----------------
// One block per batch; loops over 4 f-tiles of 128 reusing the A smem load.
// Next Y tile's cp.async overlaps current compute (Y fully consumed into regs).
#define AM_SMEM 71680

__global__ void __launch_bounds__(256, 2) amix_mma(
    const __nv_bfloat16* __restrict__ Aph, const __nv_bfloat16* __restrict__ Apl,
    const __nv_bfloat16* __restrict__ Yh, const __nv_bfloat16* __restrict__ Yl,
    __nv_bfloat16* __restrict__ Th, __nv_bfloat16* __restrict__ Tl,
    float* __restrict__ Tf) {
    extern __shared__ __align__(16) char smem[];
    const uint32_t sb = smem_u32(smem);
    const int b = blockIdx.x;
    const int tid = threadIdx.x;
    const int warp = tid >> 5, lane = tid & 31;

    // prologue: A (hi/lo) + Y tile 0 + one-time zero pad of Y rows 66..79
    for (int i = tid; i < 800; i += 256) {
        int r = i / 10, cc = i % 10;
        uint32_t dst = sb + (uint32_t)(r * 176 + cc * 16);
        CPA16(dst, Aph + r * 80 + cc * 8);
        CPA16(dst + 14080u, Apl + r * 80 + cc * 8);
    }
    for (int i = tid; i < 1056; i += 256) {
        int r = i >> 4, cc = i & 15;
        uint32_t dst = sb + 28160u + (uint32_t)(r * 272 + cc * 16);
        const size_t gsrc = ((size_t)b * F66 + r) * 512 + cc * 8;
        CPA16(dst, Yh + gsrc);
        CPA16(dst + 21760u, Yl + gsrc);
    }
    asm volatile("cp.async.commit_group;");
    for (int i = tid; i < 224; i += 256) {
        int r = 66 + (i >> 4), cc = i & 15;
        uint32_t dst = sb + 28160u + (uint32_t)(r * 272 + cc * 16);
        asm volatile("st.shared.v4.b32 [%0], {%1,%1,%1,%1};" :: "r"(dst), "r"(0u));
        asm volatile("st.shared.v4.b32 [%0], {%1,%1,%1,%1};" :: "r"(dst + 21760u), "r"(0u));
    }
    asm volatile("cp.async.wait_group 0;");
    __syncthreads();

    const int n0c = warp * 16;

    for (int fi = 0; fi < 4; fi++) {
        const int f0 = fi * 128;
        // consume Y into B fragments
        uint32_t bh[5][4], bl[5][4];
#pragma unroll
        for (int kt = 0; kt < 5; kt++) {
            int row = kt * 16 + ((lane >> 3) & 1) * 8 + (lane & 7);
            int col = n0c + (lane >> 4) * 8;
            uint32_t ad = sb + 28160u + (uint32_t)(row * 272 + col * 2);
            LDSM4T(bh[kt], ad);
            LDSM4T(bl[kt], ad + 21760u);
        }
        __syncthreads();  // all warps done reading Y smem
        if (fi + 1 < 4) {
            // prefetch next Y tile (rows 0..65 only; pads stay zero)
            for (int i = tid; i < 1056; i += 256) {
                int r = i >> 4, cc = i & 15;
                uint32_t dst = sb + 28160u + (uint32_t)(r * 272 + cc * 16);
                const size_t gsrc = ((size_t)b * F66 + r) * 512 + (fi + 1) * 128 + cc * 8;
                CPA16(dst, Yh + gsrc);
                CPA16(dst + 21760u, Yl + gsrc);
            }
            asm volatile("cp.async.commit_group;");
        }

        float c[5][2][4];
#pragma unroll
        for (int mi = 0; mi < 5; mi++)
#pragma unroll
            for (int g = 0; g < 2; g++)
#pragma unroll
                for (int q = 0; q < 4; q++) c[mi][g][q] = 0.f;

#pragma unroll
        for (int mi = 0; mi < 5; mi++) {
#pragma unroll
            for (int kt = 0; kt < 5; kt++) {
                int row = mi * 16 + (lane & 7) + ((lane >> 3) & 1) * 8;
                int col = kt * 16 + (lane >> 4) * 8;
                uint32_t ad = sb + (uint32_t)(row * 176 + col * 2);
                uint32_t ah[4], al[4];
                LDSM4(ah, ad);
                LDSM4(al, ad + 14080u);
#pragma unroll
                for (int g = 0; g < 2; g++) {
                    mma16816(c[mi][g], ah, bh[kt][g * 2], bh[kt][g * 2 + 1]);
                    mma16816(c[mi][g], al, bh[kt][g * 2], bh[kt][g * 2 + 1]);
                    mma16816(c[mi][g], ah, bl[kt][g * 2], bl[kt][g * 2 + 1]);
                }
            }
        }

        // epilogue for this f-tile
#pragma unroll
        for (int mi = 0; mi < 5; mi++) {
            int n_0 = mi * 16 + (lane >> 2);
            int n_1 = n_0 + 8;
#pragma unroll
            for (int g = 0; g < 2; g++) {
                int f = f0 + n0c + g * 8 + (lane & 3) * 2;
                if (n_0 < F66) {
                    size_t o = ((size_t)b * F66 + n_0) * 512 + f;
                    if (Tf) {
                        *reinterpret_cast<float2*>(Tf + o) = make_float2(c[mi][g][0], c[mi][g][1]);
                    } else {
                        *reinterpret_cast<uint32_t*>(Th + o) = pack2(c[mi][g][0], c[mi][g][1], false);
                        *reinterpret_cast<uint32_t*>(Tl + o) = pack2(c[mi][g][0], c[mi][g][1], true);
                    }
                }
                if (n_1 < F66) {
                    size_t o = ((size_t)b * F66 + n_1) * 512 + f;
                    if (Tf) {
                        *reinterpret_cast<float2*>(Tf + o) = make_float2(c[mi][g][2], c[mi][g][3]);
                    } else {
                        *reinterpret_cast<uint32_t*>(Th + o) = pack2(c[mi][g][2], c[mi][g][3], false);
                        *reinterpret_cast<uint32_t*>(Tl + o) = pack2(c[mi][g][2], c[mi][g][3], true);
                    }
                }
            }
        }

        if (fi + 1 < 4) {
            asm volatile("cp.async.wait_group 0;");
            __syncthreads();
        }
    }
}

// ---------------- gc7: C[M,20] = A[M,512] @ W[:, :20] + bias + x-resid ----------------
__global__ void __launch_bounds__(256) gc7_ffma(
    const float* __restrict__ A, const float* __restrict__ W,
    const float* __restrict__ bias, const float* __restrict__ xres,
    float* __restrict__ out20) {
    __shared__ float As[128][17];
    __shared__ float Bs[16][21];
    const int bm0 = blockIdx.x * 128;
    const int t = threadIdx.x;
    const int rp = t >> 2, cg = t & 3;
    float acc[2][5] = {};
    for (int k0 = 0; k0 < 512; k0 += 16) {
#pragma unroll
        for (int i = 0; i < 8; i++) {
            int idx = t + 256 * i;
            int r = idx >> 4, kk = idx & 15;
            As[r][kk] = A[(size_t)(bm0 + r) * 512 + k0 + kk];
        }
        for (int i = t; i < 320; i += 256) {
            int kk = i / 20, n = i % 20;
            Bs[kk][n] = W[(k0 + kk) * GCNIN + n];
        }
        __syncthreads();
#pragma unroll
        for (int kk = 0; kk < 16; kk++) {
            float a0 = As[rp * 2][kk], a1 = As[rp * 2 + 1][kk];
#pragma unroll
            for (int j = 0; j < 5; j++) {
                float bb = Bs[kk][cg * 5 + j];
                acc[0][j] += a0 * bb;
                acc[1][j] += a1 * bb;
            }
        }
        __syncthreads();
    }
#pragma unroll
    for (int rr = 0; rr < 2; rr++) {
        int row = bm0 + rp * 2 + rr;
#pragma unroll
        for (int j = 0; j < 5; j++) {
            int n = cg * 5 + j;
            out20[(size_t)row * DCTN + n] = acc[rr][j] + bias[n] + xres[(size_t)row * GCNIN + n];
        }
    }
}

// ---------------- attention: score + normalize ----------------
__global__ void score_att_kernel(const float* __restrict__ q,
                                 const float* __restrict__ key2,
                                 float* __restrict__ att) {
    int b = blockIdx.x;
    __shared__ float sc[VN];
    int t = threadIdx.x;
    int w = t / 32, lane = t % 32;
    for (int n = w; n < VN; n += 8) {
        float s = 0.f;
        const float* qp = q + (size_t)b * 512;
        const float* kp = key2 + (size_t)(b * VN + n) * 512;
        for (int d = lane; d < 512; d += 32) s += qp[d] * kp[d];
        for (int o = 16; o; o >>= 1) s += __shfl_xor_sync(0xffffffffu, s, o);
        if (lane == 0) sc[n] = s + 1e-15f;
    }
    __syncthreads();
    float tot = 0.f;
#pragma unroll
    for (int n = 0; n < VN; n++) tot += sc[n];
    if (t < VN) att[b * VN + t] = sc[t] / tot;
}

// ---------------- build x = [dct_in | dct_att]  (b, 66, 40) ----------------
__global__ void x_build(const float* __restrict__ src) {
    int b = blockIdx.x;
    int t = threadIdx.x;
    __shared__ float ss[TIN * F66];
    __shared__ float sh_s[VL * F66];
    __shared__ float sh_dct[DCTN * VL];
    __shared__ float sh_att[VN];
    for (int i = t; i < TIN * F66; i += 256) ss[i] = src[(size_t)b * TIN * F66 + i];
    for (int i = t; i < DCTN * VL; i += 256) sh_dct[i] = g_dct[i];
    if (t < VN) sh_att[t] = g_att[b * VN + t];
    __syncthreads();
    for (int i = t; i < VL * F66; i += 256) {
        int v = i / F66, f = i % F66;
        float a = 0.f;
#pragma unroll
        for (int n = 0; n < VN; n++) a += sh_att[n] * ss[(n + v) * F66 + f];
        sh_s[i] = a;
    }
    __syncthreads();
    for (int i = t; i < F66 * GCNIN; i += 256) {
        int f = i / GCNIN, k = i % GCNIN;
        float a = 0.f;
        if (k < DCTN) {
#pragma unroll
            for (int v = 0; v < VL; v++) {
                int r = (v < KS_) ? (TIN - KS_ + v) : (TIN - 1);
                a += sh_dct[k * VL + v] * ss[r * F66 + f];
            }
        } else {
            int kk = k - DCTN;
#pragma unroll
            for (int v = 0; v < VL; v++) a += sh_dct[kk * VL + v] * sh_s[v * F66 + f];
        }
        g_x[(size_t)b * F66 * GCNIN + i] = a;
    }
}

// ---------------- scalar node mix for gc1 (F=40 -> Th/Tl Kp=64) ----------------
__global__ void __launch_bounds__(256) amix2(
    const float* __restrict__ A, const float* __restrict__ in,
    __nv_bfloat16* __restrict__ oh, __nv_bfloat16* __restrict__ ol, int F, int Kp) {
    int b = blockIdx.x;
    __shared__ float Ash[F66 * F66];
    __shared__ float insh[F66][64];
    int t = threadIdx.x;
    for (int i = t; i < F66 * F66; i += 256) Ash[i] = A[i];
    int fw = F;
    for (int i = t; i < F66 * 64; i += 256) {
        int m = i >> 6, f = i & 63;
        insh[m][f] = (f < fw) ? in[((size_t)b * F66 + m) * F + f] : 0.f;
    }
    __syncthreads();
    int w = t >> 5, lane = t & 31;
    int h = lane >> 4, sub = lane & 15;
    int fl = sub * 4;
#pragma unroll
    for (int pass = 0; pass < 5; pass++) {
        int n = pass * 16 + w * 2 + h;
        int nn = (n < F66) ? n : 0;
        const float* arow = Ash + nn * F66;
        float ax = 0.f, ay = 0.f, az = 0.f, aw = 0.f;
#pragma unroll 6
        for (int m = 0; m < F66; m++) {
            float a = arow[m];
            float4 yv = *reinterpret_cast<const float4*>(&insh[m][fl]);
            ax += a * yv.x; ay += a * yv.y; az += a * yv.z; aw += a * yv.w;
        }
        if (n < F66) {
            float vals[4] = {ax, ay, az, aw};
            size_t o = ((size_t)b * F66 + n) * Kp + fl;
#pragma unroll
            for (int j = 0; j < 4; j++) {
                float v = (fl + j < fw) ? vals[j] : 0.f;
                __nv_bfloat16 hh, ll; split_bf16(v, hh, ll);
                oh[o + j] = hh; ol[o + j] = ll;
            }
        }
    }
}

// ---------------- final iDCT (reads compact [M][20] dct_out) ----------------
__global__ void final_idct(float* __restrict__ out) {
    size_t total = (size_t)BSZ * VL * F66;
    for (size_t i = (size_t)blockIdx.x * blockDim.x + threadIdx.x; i < total;
         i += (size_t)gridDim.x * blockDim.x) {
        int f = (int)(i % F66);
        int v = (int)((i / F66) % VL);
        int b = (int)(i / ((size_t)F66 * VL));
        float a = 0.f;
#pragma unroll
        for (int k = 0; k < DCTN; k++)
            a += g_dct[k * VL + v] * g_do20[((size_t)b * F66 + f) * DCTN + k];
        out[i] = a;
    }
}

// ---------------- host launcher ----------------
template <typename T>
static T* sym(const void* s) {
    void* p = nullptr;
    cudaGetSymbolAddress(&p, s);
    return (T*)p;
}

extern "C" void kernel_launch(void* const* d_in, const int* in_sizes, int n_in,
                              void* d_out, int out_size) {
    const float* src     = (const float*)d_in[0];
    const float* Wq1     = (const float*)d_in[1];
    const float* Wq2     = (const float*)d_in[2];
    const float* Wk1     = (const float*)d_in[3];
    const float* Wk2     = (const float*)d_in[4];
    const float* gc1_W   = (const float*)d_in[5];
    const float* gc1_att = (const float*)d_in[6];
    const float* gc1_b   = (const float*)d_in[7];
    const float* bn1_g   = (const float*)d_in[8];
    const float* bn1_b   = (const float*)d_in[9];
    const float* gcb_W   = (const float*)d_in[10];
    const float* gcb_att = (const float*)d_in[11];
    const float* gcb_b   = (const float*)d_in[12];
    const float* gcb_bn_g= (const float*)d_in[13];
    const float* gcb_bn_b= (const float*)d_in[14];
    const float* gc7_W   = (const float*)d_in[15];
    const float* gc7_att = (const float*)d_in[16];
    const float* gc7_b   = (const float*)d_in[17];
    float* out = (float*)d_out;

    cudaFuncSetAttribute(hgemm, cudaFuncAttributeMaxDynamicSharedMemorySize, HG_SMEM);
    cudaFuncSetAttribute(amix_mma, cudaFuncAttributeMaxDynamicSharedMemorySize, AM_SMEM);

    __nv_bfloat16* srch = sym<__nv_bfloat16>(g_srch); __nv_bfloat16* srcl = sym<__nv_bfloat16>(g_srcl);
    __nv_bfloat16* k1h  = sym<__nv_bfloat16>(g_k1h);  __nv_bfloat16* k1l  = sym<__nv_bfloat16>(g_k1l);
    __nv_bfloat16* q1h  = sym<__nv_bfloat16>(g_q1h);  __nv_bfloat16* q1l  = sym<__nv_bfloat16>(g_q1l);
    __nv_bfloat16* Wk1h = sym<__nv_bfloat16>(g_Wk1h); __nv_bfloat16* Wk1l = sym<__nv_bfloat16>(g_Wk1l);
    __nv_bfloat16* Wk2h = sym<__nv_bfloat16>(g_Wk2h); __nv_bfloat16* Wk2l = sym<__nv_bfloat16>(g_Wk2l);
    __nv_bfloat16* Wq1h = sym<__nv_bfloat16>(g_Wq1h); __nv_bfloat16* Wq1l = sym<__nv_bfloat16>(g_Wq1l);
    __nv_bfloat16* Wq2h = sym<__nv_bfloat16>(g_Wq2h); __nv_bfloat16* Wq2l = sym<__nv_bfloat16>(g_Wq2l);
    __nv_bfloat16* Wg1h = sym<__nv_bfloat16>(g_Wg1h); __nv_bfloat16* Wg1l = sym<__nv_bfloat16>(g_Wg1l);
    __nv_bfloat16* Wgbh = sym<__nv_bfloat16>(g_Wgbh); __nv_bfloat16* Wgbl = sym<__nv_bfloat16>(g_Wgbl);
    __nv_bfloat16* Th   = sym<__nv_bfloat16>(g_Th);   __nv_bfloat16* Tl   = sym<__nv_bfloat16>(g_Tl);
    __nv_bfloat16* yh   = sym<__nv_bfloat16>(g_yh);   __nv_bfloat16* yl   = sym<__nv_bfloat16>(g_yl);
    __nv_bfloat16* zh   = sym<__nv_bfloat16>(g_zh);   __nv_bfloat16* zl   = sym<__nv_bfloat16>(g_zl);
    __nv_bfloat16* Aph  = sym<__nv_bfloat16>(g_Aph);  __nv_bfloat16* Apl  = sym<__nv_bfloat16>(g_Apl);

    float* key2 = sym<float>(g_key2);
    float* qv   = sym<float>(g_q);
    float* patt = sym<float>(g_att);
    float* px   = sym<float>(g_x);
    float* pt   = sym<float>(g_t);
    float* pdo  = sym<float>(g_do20);

    Epi ep_relu  = {nullptr, nullptr, nullptr, 1};
    Epi ep_plain = {nullptr, nullptr, nullptr, 0};

    // launch #3 (0-indexed) = conv1 hgemm for ncu capture
    dct_build<<<1, 256>>>();                                    // #0
    src_to_bf16<<<1024, 256>>>(src);                             // #1
    prep_c1w<<<240, 256>>>(Wk1, Wk1h, Wk1l);                     // #2
    hgemm<<<dim3(4, 80), 256, HG_SMEM>>>(srch, srcl, 1, 20, 0,   // #3  <- ncu target
        Wk1h, Wk1l, nullptr, k1h, k1l, nullptr, nullptr, 10240, K1P, ep_relu);
    prep_c2w<<<512, 256>>>(Wk2, Wk2h, Wk2l);                     // #4
    hgemm<<<dim3(4, 64), 256, HG_SMEM>>>(k1h, k1l, 2, 0, 0,      // #5
        Wk2h, Wk2l, key2, nullptr, nullptr, nullptr, nullptr, 8192, K2, ep_relu);

    // ---- query conv stack ----
    prep_c1w<<<240, 256>>>(Wq1, Wq1h, Wq1l);
    prep_c2w<<<512, 256>>>(Wq2, Wq2h, Wq2l);
    hgemm<<<dim3(4, 20), 256, HG_SMEM>>>(srch, srcl, 1, 5, TIN - KS_, Wq1h, Wq1l,
        nullptr, q1h, q1l, nullptr, nullptr, 2560, K1P, ep_relu);
    hgemm<<<dim3(4, 4, 16), 256, HG_SMEM>>>(q1h, q1l, 3, 0, 0, Wq2h, Wq2l,
        pt, nullptr, nullptr, nullptr, nullptr, 512, K2, ep_plain);
    reduce_relu<<<512, 256>>>(pt, qv, 512 * 512, 16);

    // ---- attention + x ----
    score_att_kernel<<<BSZ, 256>>>(qv, key2, patt);
    x_build<<<BSZ, 256>>>(src);

    // ---- remaining weight preps ----
    prep_KN<<<64, 256>>>(gc1_W, Wg1h, Wg1l, GCNIN, 512, 64);
    for (int li = 0; li < 4; li++)
        prep_KN<<<256, 256>>>(gcb_W + (size_t)li * 512 * 512,
                              Wgbh + (size_t)li * 512 * 512,
                              Wgbl + (size_t)li * 512 * 512, 512, 512, 512);
    prep_att<<<64, 256>>>(gcb_att, gc7_att);

    const int M = MROWS;

    // ---- gc1 ----
    {
        amix2<<<BSZ, 256>>>(gc1_att, px, Th, Tl, GCNIN, 64);
        Epi e = {gc1_b, bn1_g, bn1_b, 2};
        hgemm<<<dim3(4, M / 128), 256, HG_SMEM>>>(Th, Tl, 0, 0, 0, Wg1h, Wg1l,
            nullptr, yh, yl, nullptr, nullptr, M, 64, e);
    }

    // ---- 2 stages x 2 layers ----
    for (int st = 0; st < 2; st++) {
        for (int l = 0; l < 2; l++) {
            int li = st * 2 + l;
            const __nv_bfloat16* ih = (l == 0) ? yh : zh;
            const __nv_bfloat16* il = (l == 0) ? yl : zl;
            __nv_bfloat16* oh = (l == 0) ? zh : yh;
            __nv_bfloat16* ol = (l == 0) ? zl : yl;
            amix_mma<<<BSZ, 256, AM_SMEM>>>(Aph + li * 6400, Apl + li * 6400,
                                            ih, il, Th, Tl, nullptr);
            Epi e = {gcb_b + (size_t)li * 512,
                     gcb_bn_g + (size_t)li * F66 * 512,
                     gcb_bn_b + (size_t)li * F66 * 512,
                     (l == 1) ? 3 : 2};
            hgemm<<<dim3(4, M / 128), 256, HG_SMEM>>>(Th, Tl, 0, 0, 0,
                Wgbh + (size_t)li * 512 * 512, Wgbl + (size_t)li * 512 * 512,
                nullptr, oh, ol,
                (l == 1) ? yh : nullptr, (l == 1) ? yl : nullptr, M, 512, e);
        }
    }

    // ---- gc7 (+x residual), N=20 only ----
    {
        amix_mma<<<BSZ, 256, AM_SMEM>>>(Aph + 4 * 6400, Apl + 4 * 6400,
                                        yh, yl, nullptr, nullptr, pt);
        gc7_ffma<<<M / 128, 256>>>(pt, gc7_W, gc7_b, px, pdo);
    }

    // ---- final iDCT ----
    final_idct<<<4620, 256>>>(out);
    (void)in_sizes; (void)n_in; (void)out_size;
}

// round 15
// speedup vs baseline: 1.0512x; 1.0183x over previous
#include <cuda_runtime.h>
#include <cuda_bf16.h>
#include <math.h>
#include <stdint.h>

// ---------------- constants ----------------
#define BSZ   512
#define F66   66
#define TIN   50
#define KS_   10
#define VL    35          // KS + output_n
#define VN    16          // input_n - VL + 1
#define DCTN  20
#define GCNIN 40
#define MROWS (BSZ * F66) // 33792

#define FP    80          // padded feature row for src bf16 (160B pitch)
#define K1P   480         // conv1 K: 6*80
#define K2    2560        // conv2 K: 5*512

__device__ __forceinline__ uint32_t smem_u32(const void* p) {
    uint32_t a;
    asm("{ .reg .u64 t; cvta.to.shared.u64 t, %1; cvt.u32.u64 %0, t; }" : "=r"(a) : "l"(p));
    return a;
}

__device__ __forceinline__ void mma16816(float* c, const uint32_t* a, uint32_t b0, uint32_t b1) {
    asm volatile(
        "mma.sync.aligned.m16n8k16.row.col.f32.bf16.bf16.f32 "
        "{%0,%1,%2,%3}, {%4,%5,%6,%7}, {%8,%9}, {%0,%1,%2,%3};"
        : "+f"(c[0]), "+f"(c[1]), "+f"(c[2]), "+f"(c[3])
        : "r"(a[0]), "r"(a[1]), "r"(a[2]), "r"(a[3]), "r"(b0), "r"(b1));
}

#define LDSM4(r, addr) \
    asm volatile("ldmatrix.sync.aligned.m8n8.x4.shared.b16 {%0,%1,%2,%3}, [%4];" \
        : "=r"((r)[0]), "=r"((r)[1]), "=r"((r)[2]), "=r"((r)[3]) : "r"(addr))

#define LDSM4T(r, addr) \
    asm volatile("ldmatrix.sync.aligned.m8n8.x4.trans.shared.b16 {%0,%1,%2,%3}, [%4];" \
        : "=r"((r)[0]), "=r"((r)[1]), "=r"((r)[2]), "=r"((r)[3]) : "r"(addr))

#define CPA16(saddr, gptr) \
    asm volatile("cp.async.ca.shared.global [%0], [%1], 16;" :: "r"(saddr), "l"(gptr))

// swizzled 64B-row address: row r (64B stride), 16B-chunk c (0..3)
#define SWZ(r, c) ((uint32_t)(((r) << 6) + ((((c) ^ (((r) >> 1) & 3))) << 4)))

// ---------------- scratch (device globals; no allocation) ----------------
__device__ float g_dct[DCTN * VL];

#define SRCP_N (BSZ * TIN * FP)
__device__ __align__(16) __nv_bfloat16 g_srch[SRCP_N + 512];
__device__ __align__(16) __nv_bfloat16 g_srcl[SRCP_N + 512];
__device__ __align__(16) __nv_bfloat16 g_k1h[(size_t)10240 * 512];
__device__ __align__(16) __nv_bfloat16 g_k1l[(size_t)10240 * 512];
__device__ __align__(16) __nv_bfloat16 g_q1h[(size_t)2560 * 512];
__device__ __align__(16) __nv_bfloat16 g_q1l[(size_t)2560 * 512];

__device__ __align__(16) __nv_bfloat16 g_Wk1h[(size_t)512 * K1P];
__device__ __align__(16) __nv_bfloat16 g_Wk1l[(size_t)512 * K1P];
__device__ __align__(16) __nv_bfloat16 g_Wk2h[(size_t)512 * K2];
__device__ __align__(16) __nv_bfloat16 g_Wk2l[(size_t)512 * K2];
__device__ __align__(16) __nv_bfloat16 g_Wq1h[(size_t)512 * K1P];
__device__ __align__(16) __nv_bfloat16 g_Wq1l[(size_t)512 * K1P];
__device__ __align__(16) __nv_bfloat16 g_Wq2h[(size_t)512 * K2];
__device__ __align__(16) __nv_bfloat16 g_Wq2l[(size_t)512 * K2];
__device__ __align__(16) __nv_bfloat16 g_Wg1h[(size_t)512 * 64];
__device__ __align__(16) __nv_bfloat16 g_Wg1l[(size_t)512 * 64];
__device__ __align__(16) __nv_bfloat16 g_Wgbh[(size_t)4 * 512 * 512];
__device__ __align__(16) __nv_bfloat16 g_Wgbl[(size_t)4 * 512 * 512];
__device__ __align__(16) __nv_bfloat16 g_Th[(size_t)MROWS * 512];
__device__ __align__(16) __nv_bfloat16 g_Tl[(size_t)MROWS * 512];
__device__ __align__(16) __nv_bfloat16 g_yh[(size_t)MROWS * 512];
__device__ __align__(16) __nv_bfloat16 g_yl[(size_t)MROWS * 512];
__device__ __align__(16) __nv_bfloat16 g_zh[(size_t)MROWS * 512];
__device__ __align__(16) __nv_bfloat16 g_zl[(size_t)MROWS * 512];
__device__ __align__(16) __nv_bfloat16 g_Aph[5 * 80 * 80];
__device__ __align__(16) __nv_bfloat16 g_Apl[5 * 80 * 80];

__device__ float g_key2[(size_t)8192 * 512];
__device__ float g_q[(size_t)512 * 512];
__device__ float g_att[BSZ * VN];
__device__ float g_x[(size_t)BSZ * F66 * GCNIN];
__device__ float g_t[(size_t)MROWS * 512];
__device__ float g_do20[(size_t)MROWS * DCTN];

// ---------------- epilogue descriptor ----------------
// modes: 0 plain fp32, 1 relu, 2 bias+bn+tanh, 3 bias+bn+tanh+resid
struct Epi {
    const float* bias;
    const float* gamma;
    const float* beta;
    int mode;
};

__device__ __forceinline__ void split_bf16(float v, __nv_bfloat16& h, __nv_bfloat16& l) {
    h = __float2bfloat16_rn(v);
    l = __float2bfloat16_rn(v - __bfloat162float(h));
}

__device__ __forceinline__ uint32_t pack2(float a, float b, bool lo) {
    __nv_bfloat16 ha, la, hb, lb;
    split_bf16(a, ha, la); split_bf16(b, hb, lb);
    uint16_t x = lo ? __bfloat16_as_ushort(la) : __bfloat16_as_ushort(ha);
    uint16_t y = lo ? __bfloat16_as_ushort(lb) : __bfloat16_as_ushort(hb);
    return (uint32_t)x | ((uint32_t)y << 16);
}

// ---------------- dct matrix ----------------
__global__ void dct_build() {
    for (int i = threadIdx.x; i < DCTN * VL; i += blockDim.x) {
        int k = i / VL, v = i % VL;
        double w = (k == 0) ? sqrt(1.0 / VL) : sqrt(2.0 / VL);
        g_dct[i] = (float)(w * cos(3.14159265358979323846 * (v + 0.5) * k / VL));
    }
}

// ---------------- src -> bf16 hi/lo (x 1e-3), padded layout [b*50+t][80] ----------------
__global__ void src_to_bf16(const float* __restrict__ src) {
    int total = SRCP_N + 512;
    for (int i = blockIdx.x * blockDim.x + threadIdx.x; i < total;
         i += gridDim.x * blockDim.x) {
        float v = 0.f;
        if (i < SRCP_N) {
            int f = i % FP;
            int row = i / FP;
            if (f < F66) v = src[row * F66 + f] * 1e-3f;
        }
        __nv_bfloat16 h, l; split_bf16(v, h, l);
        g_srch[i] = h; g_srcl[i] = l;
    }
}

// ---------------- ALL weight preps fused into one grid-stride kernel ----------------
#define PJ_C1 (512 * K1P)     // 245760
#define PJ_C2 (512 * K2)      // 1310720
#define PJ_G1 (512 * 64)      // 32768
#define PJ_GB (512 * 512)     // 262144
#define PJ_AT (5 * 80 * 80)   // 32000
#define PJ_TOTAL (2 * PJ_C1 + 2 * PJ_C2 + PJ_G1 + 4 * PJ_GB + PJ_AT)

__global__ void prep_all(const float* __restrict__ Wk1, const float* __restrict__ Wq1,
                         const float* __restrict__ Wk2, const float* __restrict__ Wq2,
                         const float* __restrict__ gc1_W, const float* __restrict__ gcb_W,
                         const float* __restrict__ gcb_att, const float* __restrict__ gc7_att) {
    for (int i = blockIdx.x * blockDim.x + threadIdx.x; i < PJ_TOTAL;
         i += gridDim.x * blockDim.x) {
        int j = i;
        float v; __nv_bfloat16* Dh; __nv_bfloat16* Dl; int o;
        if (j < PJ_C1) {                         // Wk1: [512][66][6] -> [512][480], k=tt*80+f
            int n = j / K1P, k = j % K1P;
            int tt = k / FP, f = k % FP;
            v = (f < F66) ? Wk1[n * 396 + f * 6 + tt] : 0.f;
            Dh = g_Wk1h; Dl = g_Wk1l; o = j;
        } else if ((j -= PJ_C1) < PJ_C1) {       // Wq1
            int n = j / K1P, k = j % K1P;
            int tt = k / FP, f = k % FP;
            v = (f < F66) ? Wq1[n * 396 + f * 6 + tt] : 0.f;
            Dh = g_Wq1h; Dl = g_Wq1l; o = j;
        } else if ((j -= PJ_C1) < PJ_C2) {       // Wk2: [512][512][5] -> [512][2560], k=tt*512+c
            int n = j / K2, k = j % K2;
            int tt = k >> 9, c = k & 511;
            v = Wk2[n * K2 + c * 5 + tt];
            Dh = g_Wk2h; Dl = g_Wk2l; o = j;
        } else if ((j -= PJ_C2) < PJ_C2) {       // Wq2
            int n = j / K2, k = j % K2;
            int tt = k >> 9, c = k & 511;
            v = Wq2[n * K2 + c * 5 + tt];
            Dh = g_Wq2h; Dl = g_Wq2l; o = j;
        } else if ((j -= PJ_C2) < PJ_G1) {       // gc1_W: [40,512] -> [512][64] transposed/padded
            int k = j & 63, n = j >> 6;
            v = (k < GCNIN) ? gc1_W[(size_t)k * 512 + n] : 0.f;
            Dh = g_Wg1h; Dl = g_Wg1l; o = j;
        } else if ((j -= PJ_G1) < 4 * PJ_GB) {   // gcb_W x4: [512,512] -> [512][512] transposed
            int li = j / PJ_GB, r = j % PJ_GB;
            int k = r & 511, n = r >> 9;
            v = gcb_W[(size_t)li * PJ_GB + (size_t)k * 512 + n];
            Dh = g_Wgbh; Dl = g_Wgbl; o = j;
        } else {                                 // att pads: 5 x 66x66 -> 80x80
            j -= 4 * PJ_GB;
            int li = j / 6400, rem = j % 6400;
            int r = rem / 80, c = rem % 80;
            v = 0.f;
            if (r < F66 && c < F66) {
                const float* s = (li < 4) ? (gcb_att + (size_t)li * F66 * F66) : gc7_att;
                v = s[r * F66 + c];
            }
            Dh = g_Aph; Dl = g_Apl; o = j;
        }
        __nv_bfloat16 h, l; split_bf16(v, h, l);
        Dh[o] = h; Dl[o] = l;
    }
}

// ---------------- HMMA bf16x3 GEMM, 128x128 tile, 256 threads, 2 CTAs/SM ----------------
#define HG_SMEM 65536

__device__ __forceinline__ float epi_apply(float v, int col, int nmod, const Epi& e) {
    if (e.mode == 1) return fmaxf(v, 0.f);
    if (e.mode == 2 || e.mode == 3) {
        v += e.bias[col];
        int gi = nmod * 512 + col;
        v = tanhf(v * e.gamma[gi] * 0.9999950000374997f + e.beta[gi]);
    }
    return v;
}

__device__ __forceinline__ size_t amap(int amode, int r, int npos, int off, int K) {
    if (amode == 0)      return (size_t)r * K;
    else if (amode == 1) return ((size_t)(r / npos) * TIN + off + (r % npos)) * FP;
    else if (amode == 2) return ((size_t)(r >> 4) * 20 + (r & 15)) * 512;
    else                 return (size_t)r * 2560;
}

__global__ void __launch_bounds__(256, 2) hgemm(
    const __nv_bfloat16* __restrict__ Ah, const __nv_bfloat16* __restrict__ Al,
    int amode, int npos, int off,
    const __nv_bfloat16* __restrict__ Bh, const __nv_bfloat16* __restrict__ Bl,
    float* __restrict__ C, __nv_bfloat16* __restrict__ Ch, __nv_bfloat16* __restrict__ Cl,
    const __nv_bfloat16* __restrict__ Rh, const __nv_bfloat16* __restrict__ Rl,
    int M, int K, Epi e) {
    extern __shared__ __align__(16) char smem[];
    const uint32_t sb = smem_u32(smem);
    const int tid = threadIdx.x;
    const int bm0 = blockIdx.y * 128;
    const int bn0 = blockIdx.x * 128;
    const int warp = tid >> 5, lane = tid & 31;
    const int wm = warp & 1, wn = warp >> 1;
    const int KT = K >> 5;
    const int nkt = KT / gridDim.z;
    const int kt0 = blockIdx.z * nkt;
    const int ktend = kt0 + nkt;

    const int lr = tid >> 2;
    const int lc = tid & 3;
    const size_t aRow0 = amap(amode, bm0 + lr, npos, off, K);
    const size_t aRow1 = amap(amode, bm0 + 64 + lr, npos, off, K);
    const size_t bRow0 = (size_t)(bn0 + lr) * K;
    const size_t bRow1 = (size_t)(bn0 + 64 + lr) * K;
    const uint32_t swA0 = SWZ(lr, lc);
    const uint32_t swA1 = SWZ(lr + 64, lc);

    float c[4][4][4];
#pragma unroll
    for (int i = 0; i < 4; i++)
#pragma unroll
        for (int j = 0; j < 4; j++)
#pragma unroll
            for (int q = 0; q < 4; q++) c[i][j][q] = 0.f;

#define HLOAD(buf, kt) do {                                                        \
    const int k0 = (kt) << 5;                                                      \
    const uint32_t bo = sb + (uint32_t)(buf) * 32768u;                             \
    CPA16(bo + swA0, Ah + aRow0 + k0 + lc * 8);                                    \
    CPA16(bo + swA1, Ah + aRow1 + k0 + lc * 8);                                    \
    CPA16(bo + 8192u + swA0, Al + aRow0 + k0 + lc * 8);                            \
    CPA16(bo + 8192u + swA1, Al + aRow1 + k0 + lc * 8);                            \
    CPA16(bo + 16384u + swA0, Bh + bRow0 + k0 + lc * 8);                           \
    CPA16(bo + 16384u + swA1, Bh + bRow1 + k0 + lc * 8);                           \
    CPA16(bo + 24576u + swA0, Bl + bRow0 + k0 + lc * 8);                           \
    CPA16(bo + 24576u + swA1, Bl + bRow1 + k0 + lc * 8);                           \
    asm volatile("cp.async.commit_group;");                                        \
} while (0)

    HLOAD(0, kt0);
    for (int kt = kt0; kt < ktend; kt++) {
        const int buf = (kt - kt0) & 1;
        if (kt + 1 < ktend) {
            HLOAD(buf ^ 1, kt + 1);
            asm volatile("cp.async.wait_group 1;");
        } else {
            asm volatile("cp.async.wait_group 0;");
        }
        __syncthreads();
        const uint32_t base = sb + (uint32_t)buf * 32768u;
#pragma unroll
        for (int kh = 0; kh < 2; kh++) {
            uint32_t ah[4][4], al[4][4], bh2[2][4], bl2[2][4];
#pragma unroll
            for (int mi = 0; mi < 4; mi++) {
                int row = wm * 64 + mi * 16 + (lane & 7) + ((lane >> 3) & 1) * 8;
                int cc = kh * 2 + (lane >> 4);
                uint32_t ad = base + SWZ(row, cc);
                LDSM4(ah[mi], ad);
                LDSM4(al[mi], ad + 8192u);
            }
#pragma unroll
            for (int bi = 0; bi < 2; bi++) {
                int row = wn * 32 + bi * 16 + (lane & 7) + (lane >> 4) * 8;
                int cc = kh * 2 + ((lane >> 3) & 1);
                uint32_t bd = base + 16384u + SWZ(row, cc);
                LDSM4(bh2[bi], bd);
                LDSM4(bl2[bi], bd + 8192u);
            }
#pragma unroll
            for (int mi = 0; mi < 4; mi++)
#pragma unroll
                for (int ni = 0; ni < 4; ni++) {
                    uint32_t b0h = bh2[ni >> 1][(ni & 1) * 2];
                    uint32_t b1h = bh2[ni >> 1][(ni & 1) * 2 + 1];
                    uint32_t b0l = bl2[ni >> 1][(ni & 1) * 2];
                    uint32_t b1l = bl2[ni >> 1][(ni & 1) * 2 + 1];
                    mma16816(c[mi][ni], ah[mi], b0h, b1h);
                    mma16816(c[mi][ni], al[mi], b0h, b1h);
                    mma16816(c[mi][ni], ah[mi], b0l, b1l);
                }
        }
        __syncthreads();
    }
#undef HLOAD

    // ---- epilogue ----
    float* Cz = C ? (C + (size_t)blockIdx.z * M * 512) : C;
#pragma unroll
    for (int mi = 0; mi < 4; mi++) {
        int r0 = bm0 + wm * 64 + mi * 16 + (lane >> 2);
        int r1 = r0 + 8;
        int nm0 = r0 % F66, nm1 = r1 % F66;
#pragma unroll
        for (int ni = 0; ni < 4; ni++) {
            int cb = bn0 + wn * 32 + ni * 8 + (lane & 3) * 2;
            size_t i0 = (size_t)r0 * 512 + cb;
            size_t i1 = (size_t)r1 * 512 + cb;
            float v0 = epi_apply(c[mi][ni][0], cb, nm0, e);
            float v1 = epi_apply(c[mi][ni][1], cb + 1, nm0, e);
            float v2 = epi_apply(c[mi][ni][2], cb, nm1, e);
            float v3 = epi_apply(c[mi][ni][3], cb + 1, nm1, e);
            if (e.mode == 3) {
                __nv_bfloat162 rh0 = *reinterpret_cast<const __nv_bfloat162*>(Rh + i0);
                __nv_bfloat162 rl0 = *reinterpret_cast<const __nv_bfloat162*>(Rl + i0);
                __nv_bfloat162 rh1 = *reinterpret_cast<const __nv_bfloat162*>(Rh + i1);
                __nv_bfloat162 rl1 = *reinterpret_cast<const __nv_bfloat162*>(Rl + i1);
                v0 += __bfloat162float(rh0.x) + __bfloat162float(rl0.x);
                v1 += __bfloat162float(rh0.y) + __bfloat162float(rl0.y);
                v2 += __bfloat162float(rh1.x) + __bfloat162float(rl1.x);
                v3 += __bfloat162float(rh1.y) + __bfloat162float(rl1.y);
            }
            if (Cz) {
                *reinterpret_cast<float2*>(Cz + i0) = make_float2(v0, v1);
                *reinterpret_cast<float2*>(Cz + i1) = make_float2(v2, v3);
            }
            if (Ch) {
                *reinterpret_cast<uint32_t*>(Ch + i0) = pack2(v0, v1, false);
                *reinterpret_cast<uint32_t*>(Cl + i0) = pack2(v0, v1, true);
                *reinterpret_cast<uint32_t*>(Ch + i1) = pack2(v2, v3, false);
                *reinterpret_cast<uint32_t*>(Cl + i1) = pack2(v2, v3, true);
            }
        }
    }
}

// ---------------- split-K reduce + relu (fp32 out) ----------------
__global__ void reduce_relu(const float* __restrict__ part, float* __restrict__ outp,
                            int n, int zn) {
    for (int i = blockIdx.x * blockDim.x + threadIdx.x; i < n;
         i += gridDim.x * blockDim.x) {
        float s = 0.f;
        for (int z = 0; z < zn; z++) s += part[(size_t)z * n + i];
        outp[i] = fmaxf(s, 0.f);
    }
}

// ---------------- split-K reduce + relu -> bf16 hi/lo ----------------
__global__ void reduce_relu_bf16(const float* __restrict__ part,
                                 __nv_bfloat16* __restrict__ oh,
                                 __nv_bfloat16* __restrict__ ol, int n, int zn) {
    for (int i = blockIdx.x * blockDim.x + threadIdx.x; i < n;
         i += gridDim.x * blockDim.x) {
        float s = 0.f;
        for (int z = 0; z < zn; z++) s += part[(size_t)z * n + i];
        s = fmaxf(s, 0.f);
        __nv_bfloat16 h, l; split_bf16(s, h, l);
        oh[i] = h; ol[i] = l;
    }
}

// ---------------- batched node-mix via HMMA (A reused across 4 f-tiles) ----------------
#define AM_SMEM 71680

__global__ void __launch_bounds__(256, 2) amix_mma(
    const __nv_bfloat16* __restrict__ Aph, const __nv_bfloat16* __restrict__ Apl,
    const __nv_bfloat16* __restrict__ Yh, const __nv_bfloat16* __restrict__ Yl,
    __nv_bfloat16* __restrict__ Th, __nv_bfloat16* __restrict__ Tl,
    float* __restrict__ Tf) {
    extern __shared__ __align__(16) char smem[];
    const uint32_t sb = smem_u32(smem);
    const int b = blockIdx.x;
    const int tid = threadIdx.x;
    const int warp = tid >> 5, lane = tid & 31;

    for (int i = tid; i < 800; i += 256) {
        int r = i / 10, cc = i % 10;
        uint32_t dst = sb + (uint32_t)(r * 176 + cc * 16);
        CPA16(dst, Aph + r * 80 + cc * 8);
        CPA16(dst + 14080u, Apl + r * 80 + cc * 8);
    }
    for (int i = tid; i < 1056; i += 256) {
        int r = i >> 4, cc = i & 15;
        uint32_t dst = sb + 28160u + (uint32_t)(r * 272 + cc * 16);
        const size_t gsrc = ((size_t)b * F66 + r) * 512 + cc * 8;
        CPA16(dst, Yh + gsrc);
        CPA16(dst + 21760u, Yl + gsrc);
    }
    asm volatile("cp.async.commit_group;");
    for (int i = tid; i < 224; i += 256) {
        int r = 66 + (i >> 4), cc = i & 15;
        uint32_t dst = sb + 28160u + (uint32_t)(r * 272 + cc * 16);
        asm volatile("st.shared.v4.b32 [%0], {%1,%1,%1,%1};" :: "r"(dst), "r"(0u));
        asm volatile("st.shared.v4.b32 [%0], {%1,%1,%1,%1};" :: "r"(dst + 21760u), "r"(0u));
    }
    asm volatile("cp.async.wait_group 0;");
    __syncthreads();

    const int n0c = warp * 16;

    for (int fi = 0; fi < 4; fi++) {
        const int f0 = fi * 128;
        uint32_t bh[5][4], bl[5][4];
#pragma unroll
        for (int kt = 0; kt < 5; kt++) {
            int row = kt * 16 + ((lane >> 3) & 1) * 8 + (lane & 7);
            int col = n0c + (lane >> 4) * 8;
            uint32_t ad = sb + 28160u + (uint32_t)(row * 272 + col * 2);
            LDSM4T(bh[kt], ad);
            LDSM4T(bl[kt], ad + 21760u);
        }
        __syncthreads();
        if (fi + 1 < 4) {
            for (int i = tid; i < 1056; i += 256) {
                int r = i >> 4, cc = i & 15;
                uint32_t dst = sb + 28160u + (uint32_t)(r * 272 + cc * 16);
                const size_t gsrc = ((size_t)b * F66 + r) * 512 + (fi + 1) * 128 + cc * 8;
                CPA16(dst, Yh + gsrc);
                CPA16(dst + 21760u, Yl + gsrc);
            }
            asm volatile("cp.async.commit_group;");
        }

        float c[5][2][4];
#pragma unroll
        for (int mi = 0; mi < 5; mi++)
#pragma unroll
            for (int g = 0; g < 2; g++)
#pragma unroll
                for (int q = 0; q < 4; q++) c[mi][g][q] = 0.f;

#pragma unroll
        for (int mi = 0; mi < 5; mi++) {
#pragma unroll
            for (int kt = 0; kt < 5; kt++) {
                int row = mi * 16 + (lane & 7) + ((lane >> 3) & 1) * 8;
                int col = kt * 16 + (lane >> 4) * 8;
                uint32_t ad = sb + (uint32_t)(row * 176 + col * 2);
                uint32_t ah[4], al[4];
                LDSM4(ah, ad);
                LDSM4(al, ad + 14080u);
#pragma unroll
                for (int g = 0; g < 2; g++) {
                    mma16816(c[mi][g], ah, bh[kt][g * 2], bh[kt][g * 2 + 1]);
                    mma16816(c[mi][g], al, bh[kt][g * 2], bh[kt][g * 2 + 1]);
                    mma16816(c[mi][g], ah, bl[kt][g * 2], bl[kt][g * 2 + 1]);
                }
            }
        }

#pragma unroll
        for (int mi = 0; mi < 5; mi++) {
            int n_0 = mi * 16 + (lane >> 2);
            int n_1 = n_0 + 8;
#pragma unroll
            for (int g = 0; g < 2; g++) {
                int f = f0 + n0c + g * 8 + (lane & 3) * 2;
                if (n_0 < F66) {
                    size_t o = ((size_t)b * F66 + n_0) * 512 + f;
                    if (Tf) {
                        *reinterpret_cast<float2*>(Tf + o) = make_float2(c[mi][g][0], c[mi][g][1]);
                    } else {
                        *reinterpret_cast<uint32_t*>(Th + o) = pack2(c[mi][g][0], c[mi][g][1], false);
                        *reinterpret_cast<uint32_t*>(Tl + o) = pack2(c[mi][g][0], c[mi][g][1], true);
                    }
                }
                if (n_1 < F66) {
                    size_t o = ((size_t)b * F66 + n_1) * 512 + f;
                    if (Tf) {
                        *reinterpret_cast<float2*>(Tf + o) = make_float2(c[mi][g][2], c[mi][g][3]);
                    } else {
                        *reinterpret_cast<uint32_t*>(Th + o) = pack2(c[mi][g][2], c[mi][g][3], false);
                        *reinterpret_cast<uint32_t*>(Tl + o) = pack2(c[mi][g][2], c[mi][g][3], true);
                    }
                }
            }
        }

        if (fi + 1 < 4) {
            asm volatile("cp.async.wait_group 0;");
            __syncthreads();
        }
    }
}

// ---------------- gc7: C[M,20] = A[M,512] @ W[:, :20] + bias + x-resid ----------------
__global__ void __launch_bounds__(256) gc7_ffma(
    const float* __restrict__ A, const float* __restrict__ W,
    const float* __restrict__ bias, const float* __restrict__ xres,
    float* __restrict__ out20) {
    __shared__ float As[128][17];
    __shared__ float Bs[16][21];
    const int bm0 = blockIdx.x * 128;
    const int t = threadIdx.x;
    const int rp = t >> 2, cg = t & 3;
    float acc[2][5] = {};
    for (int k0 = 0; k0 < 512; k0 += 16) {
#pragma unroll
        for (int i = 0; i < 8; i++) {
            int idx = t + 256 * i;
            int r = idx >> 4, kk = idx & 15;
            As[r][kk] = A[(size_t)(bm0 + r) * 512 + k0 + kk];
        }
        for (int i = t; i < 320; i += 256) {
            int kk = i / 20, n = i % 20;
            Bs[kk][n] = W[(k0 + kk) * GCNIN + n];
        }
        __syncthreads();
#pragma unroll
        for (int kk = 0; kk < 16; kk++) {
            float a0 = As[rp * 2][kk], a1 = As[rp * 2 + 1][kk];
#pragma unroll
            for (int j = 0; j < 5; j++) {
                float bb = Bs[kk][cg * 5 + j];
                acc[0][j] += a0 * bb;
                acc[1][j] += a1 * bb;
            }
        }
        __syncthreads();
    }
#pragma unroll
    for (int rr = 0; rr < 2; rr++) {
        int row = bm0 + rp * 2 + rr;
#pragma unroll
        for (int j = 0; j < 5; j++) {
            int n = cg * 5 + j;
            out20[(size_t)row * DCTN + n] = acc[rr][j] + bias[n] + xres[(size_t)row * GCNIN + n];
        }
    }
}

// ---------------- attention: score + normalize ----------------
__global__ void score_att_kernel(const float* __restrict__ q,
                                 const float* __restrict__ key2,
                                 float* __restrict__ att) {
    int b = blockIdx.x;
    __shared__ float sc[VN];
    int t = threadIdx.x;
    int w = t / 32, lane = t % 32;
    for (int n = w; n < VN; n += 8) {
        float s = 0.f;
        const float* qp = q + (size_t)b * 512;
        const float* kp = key2 + (size_t)(b * VN + n) * 512;
        for (int d = lane; d < 512; d += 32) s += qp[d] * kp[d];
        for (int o = 16; o; o >>= 1) s += __shfl_xor_sync(0xffffffffu, s, o);
        if (lane == 0) sc[n] = s + 1e-15f;
    }
    __syncthreads();
    float tot = 0.f;
#pragma unroll
    for (int n = 0; n < VN; n++) tot += sc[n];
    if (t < VN) att[b * VN + t] = sc[t] / tot;
}

// ---------------- build x = [dct_in | dct_att]  (b, 66, 40) ----------------
__global__ void x_build(const float* __restrict__ src) {
    int b = blockIdx.x;
    int t = threadIdx.x;
    __shared__ float ss[TIN * F66];
    __shared__ float sh_s[VL * F66];
    __shared__ float sh_dct[DCTN * VL];
    __shared__ float sh_att[VN];
    for (int i = t; i < TIN * F66; i += 256) ss[i] = src[(size_t)b * TIN * F66 + i];
    for (int i = t; i < DCTN * VL; i += 256) sh_dct[i] = g_dct[i];
    if (t < VN) sh_att[t] = g_att[b * VN + t];
    __syncthreads();
    for (int i = t; i < VL * F66; i += 256) {
        int v = i / F66, f = i % F66;
        float a = 0.f;
#pragma unroll
        for (int n = 0; n < VN; n++) a += sh_att[n] * ss[(n + v) * F66 + f];
        sh_s[i] = a;
    }
    __syncthreads();
    for (int i = t; i < F66 * GCNIN; i += 256) {
        int f = i / GCNIN, k = i % GCNIN;
        float a = 0.f;
        if (k < DCTN) {
#pragma unroll
            for (int v = 0; v < VL; v++) {
                int r = (v < KS_) ? (TIN - KS_ + v) : (TIN - 1);
                a += sh_dct[k * VL + v] * ss[r * F66 + f];
            }
        } else {
            int kk = k - DCTN;
#pragma unroll
            for (int v = 0; v < VL; v++) a += sh_dct[kk * VL + v] * sh_s[v * F66 + f];
        }
        g_x[(size_t)b * F66 * GCNIN + i] = a;
    }
}

// ---------------- scalar node mix for gc1 (F=40 -> Th/Tl Kp=64) ----------------
__global__ void __launch_bounds__(256) amix2(
    const float* __restrict__ A, const float* __restrict__ in,
    __nv_bfloat16* __restrict__ oh, __nv_bfloat16* __restrict__ ol, int F, int Kp) {
    int b = blockIdx.x;
    __shared__ float Ash[F66 * F66];
    __shared__ float insh[F66][64];
    int t = threadIdx.x;
    for (int i = t; i < F66 * F66; i += 256) Ash[i] = A[i];
    int fw = F;
    for (int i = t; i < F66 * 64; i += 256) {
        int m = i >> 6, f = i & 63;
        insh[m][f] = (f < fw) ? in[((size_t)b * F66 + m) * F + f] : 0.f;
    }
    __syncthreads();
    int w = t >> 5, lane = t & 31;
    int h = lane >> 4, sub = lane & 15;
    int fl = sub * 4;
#pragma unroll
    for (int pass = 0; pass < 5; pass++) {
        int n = pass * 16 + w * 2 + h;
        int nn = (n < F66) ? n : 0;
        const float* arow = Ash + nn * F66;
        float ax = 0.f, ay = 0.f, az = 0.f, aw = 0.f;
#pragma unroll 6
        for (int m = 0; m < F66; m++) {
            float a = arow[m];
            float4 yv = *reinterpret_cast<const float4*>(&insh[m][fl]);
            ax += a * yv.x; ay += a * yv.y; az += a * yv.z; aw += a * yv.w;
        }
        if (n < F66) {
            float vals[4] = {ax, ay, az, aw};
            size_t o = ((size_t)b * F66 + n) * Kp + fl;
#pragma unroll
            for (int j = 0; j < 4; j++) {
                float v = (fl + j < fw) ? vals[j] : 0.f;
                __nv_bfloat16 hh, ll; split_bf16(v, hh, ll);
                oh[o + j] = hh; ol[o + j] = ll;
            }
        }
    }
}

// ---------------- final iDCT (reads compact [M][20] dct_out) ----------------
__global__ void final_idct(float* __restrict__ out) {
    size_t total = (size_t)BSZ * VL * F66;
    for (size_t i = (size_t)blockIdx.x * blockDim.x + threadIdx.x; i < total;
         i += (size_t)gridDim.x * blockDim.x) {
        int f = (int)(i % F66);
        int v = (int)((i / F66) % VL);
        int b = (int)(i / ((size_t)F66 * VL));
        float a = 0.f;
#pragma unroll
        for (int k = 0; k < DCTN; k++)
            a += g_dct[k * VL + v] * g_do20[((size_t)b * F66 + f) * DCTN + k];
        out[i] = a;
    }
}

// ---------------- host launcher ----------------
template <typename T>
static T* sym(const void* s) {
    void* p = nullptr;
    cudaGetSymbolAddress(&p, s);
    return (T*)p;
}

extern "C" void kernel_launch(void* const* d_in, const int* in_sizes, int n_in,
                              void* d_out, int out_size) {
    const float* src     = (const float*)d_in[0];
    const float* Wq1     = (const float*)d_in[1];
    const float* Wq2     = (const float*)d_in[2];
    const float* Wk1     = (const float*)d_in[3];
    const float* Wk2     = (const float*)d_in[4];
    const float* gc1_W   = (const float*)d_in[5];
    const float* gc1_att = (const float*)d_in[6];
    const float* gc1_b   = (const float*)d_in[7];
    const float* bn1_g   = (const float*)d_in[8];
    const float* bn1_b   = (const float*)d_in[9];
    const float* gcb_W   = (const float*)d_in[10];
    const float* gcb_att = (const float*)d_in[11];
    const float* gcb_b   = (const float*)d_in[12];
    const float* gcb_bn_g= (const float*)d_in[13];
    const float* gcb_bn_b= (const float*)d_in[14];
    const float* gc7_W   = (const float*)d_in[15];
    const float* gc7_att = (const float*)d_in[16];
    const float* gc7_b   = (const float*)d_in[17];
    float* out = (float*)d_out;

    cudaFuncSetAttribute(hgemm, cudaFuncAttributeMaxDynamicSharedMemorySize, HG_SMEM);
    cudaFuncSetAttribute(amix_mma, cudaFuncAttributeMaxDynamicSharedMemorySize, AM_SMEM);

    __nv_bfloat16* srch = sym<__nv_bfloat16>(g_srch); __nv_bfloat16* srcl = sym<__nv_bfloat16>(g_srcl);
    __nv_bfloat16* k1h  = sym<__nv_bfloat16>(g_k1h);  __nv_bfloat16* k1l  = sym<__nv_bfloat16>(g_k1l);
    __nv_bfloat16* q1h  = sym<__nv_bfloat16>(g_q1h);  __nv_bfloat16* q1l  = sym<__nv_bfloat16>(g_q1l);
    __nv_bfloat16* Wk1h = sym<__nv_bfloat16>(g_Wk1h); __nv_bfloat16* Wk1l = sym<__nv_bfloat16>(g_Wk1l);
    __nv_bfloat16* Wk2h = sym<__nv_bfloat16>(g_Wk2h); __nv_bfloat16* Wk2l = sym<__nv_bfloat16>(g_Wk2l);
    __nv_bfloat16* Wq1h = sym<__nv_bfloat16>(g_Wq1h); __nv_bfloat16* Wq1l = sym<__nv_bfloat16>(g_Wq1l);
    __nv_bfloat16* Wq2h = sym<__nv_bfloat16>(g_Wq2h); __nv_bfloat16* Wq2l = sym<__nv_bfloat16>(g_Wq2l);
    __nv_bfloat16* Wg1h = sym<__nv_bfloat16>(g_Wg1h); __nv_bfloat16* Wg1l = sym<__nv_bfloat16>(g_Wg1l);
    __nv_bfloat16* Wgbh = sym<__nv_bfloat16>(g_Wgbh); __nv_bfloat16* Wgbl = sym<__nv_bfloat16>(g_Wgbl);
    __nv_bfloat16* Th   = sym<__nv_bfloat16>(g_Th);   __nv_bfloat16* Tl   = sym<__nv_bfloat16>(g_Tl);
    __nv_bfloat16* yh   = sym<__nv_bfloat16>(g_yh);   __nv_bfloat16* yl   = sym<__nv_bfloat16>(g_yl);
    __nv_bfloat16* zh   = sym<__nv_bfloat16>(g_zh);   __nv_bfloat16* zl   = sym<__nv_bfloat16>(g_zl);
    __nv_bfloat16* Aph  = sym<__nv_bfloat16>(g_Aph);  __nv_bfloat16* Apl  = sym<__nv_bfloat16>(g_Apl);

    float* key2 = sym<float>(g_key2);
    float* qv   = sym<float>(g_q);
    float* patt = sym<float>(g_att);
    float* px   = sym<float>(g_x);
    float* pt   = sym<float>(g_t);
    float* pdo  = sym<float>(g_do20);

    Epi ep_relu  = {nullptr, nullptr, nullptr, 1};
    Epi ep_plain = {nullptr, nullptr, nullptr, 0};

    // launch #3 (0-indexed) = conv1 hgemm for ncu capture
    dct_build<<<1, 256>>>();                                    // #0
    src_to_bf16<<<1024, 256>>>(src);                             // #1
    prep_all<<<2048, 256>>>(Wk1, Wq1, Wk2, Wq2, gc1_W, gcb_W,    // #2 (all weight preps)
                            gcb_att, gc7_att);
    hgemm<<<dim3(4, 80), 256, HG_SMEM>>>(srch, srcl, 1, 20, 0,   // #3  <- ncu target
        Wk1h, Wk1l, nullptr, k1h, k1l, nullptr, nullptr, 10240, K1P, ep_relu);
    hgemm<<<dim3(4, 64), 256, HG_SMEM>>>(k1h, k1l, 2, 0, 0,      // #4
        Wk2h, Wk2l, key2, nullptr, nullptr, nullptr, nullptr, 8192, K2, ep_relu);

    // ---- query conv stack (conv1 split-K z=3: KT=15 -> 5 per slice) ----
    hgemm<<<dim3(4, 20, 3), 256, HG_SMEM>>>(srch, srcl, 1, 5, TIN - KS_, Wq1h, Wq1l,
        pt, nullptr, nullptr, nullptr, nullptr, 2560, K1P, ep_plain);
    reduce_relu_bf16<<<512, 256>>>(pt, q1h, q1l, 2560 * 512, 3);
    hgemm<<<dim3(4, 4, 16), 256, HG_SMEM>>>(q1h, q1l, 3, 0, 0, Wq2h, Wq2l,
        pt, nullptr, nullptr, nullptr, nullptr, 512, K2, ep_plain);
    reduce_relu<<<512, 256>>>(pt, qv, 512 * 512, 16);

    // ---- attention + x ----
    score_att_kernel<<<BSZ, 256>>>(qv, key2, patt);
    x_build<<<BSZ, 256>>>(src);

    const int M = MROWS;

    // ---- gc1 ----
    {
        amix2<<<BSZ, 256>>>(gc1_att, px, Th, Tl, GCNIN, 64);
        Epi e = {gc1_b, bn1_g, bn1_b, 2};
        hgemm<<<dim3(4, M / 128), 256, HG_SMEM>>>(Th, Tl, 0, 0, 0, Wg1h, Wg1l,
            nullptr, yh, yl, nullptr, nullptr, M, 64, e);
    }

    // ---- 2 stages x 2 layers ----
    for (int st = 0; st < 2; st++) {
        for (int l = 0; l < 2; l++) {
            int li = st * 2 + l;
            const __nv_bfloat16* ih = (l == 0) ? yh : zh;
            const __nv_bfloat16* il = (l == 0) ? yl : zl;
            __nv_bfloat16* oh = (l == 0) ? zh : yh;
            __nv_bfloat16* ol = (l == 0) ? zl : yl;
            amix_mma<<<BSZ, 256, AM_SMEM>>>(Aph + li * 6400, Apl + li * 6400,
                                            ih, il, Th, Tl, nullptr);
            Epi e = {gcb_b + (size_t)li * 512,
                     gcb_bn_g + (size_t)li * F66 * 512,
                     gcb_bn_b + (size_t)li * F66 * 512,
                     (l == 1) ? 3 : 2};
            hgemm<<<dim3(4, M / 128), 256, HG_SMEM>>>(Th, Tl, 0, 0, 0,
                Wgbh + (size_t)li * 512 * 512, Wgbl + (size_t)li * 512 * 512,
                nullptr, oh, ol,
                (l == 1) ? yh : nullptr, (l == 1) ? yl : nullptr, M, 512, e);
        }
    }

    // ---- gc7 (+x residual), N=20 only ----
    {
        amix_mma<<<BSZ, 256, AM_SMEM>>>(Aph + 4 * 6400, Apl + 4 * 6400,
                                        yh, yl, nullptr, nullptr, pt);
        gc7_ffma<<<M / 128, 256>>>(pt, gc7_W, gc7_b, px, pdo);
    }

    // ---- final iDCT ----
    final_idct<<<4620, 256>>>(out);
    (void)in_sizes; (void)n_in; (void)out_size;
}

// round 16
// speedup vs baseline: 1.0765x; 1.0241x over previous
#include <cuda_runtime.h>
#include <cuda_bf16.h>
#include <math.h>
#include <stdint.h>

// ---------------- constants ----------------
#define BSZ   512
#define F66   66
#define TIN   50
#define KS_   10
#define VL    35          // KS + output_n
#define VN    16          // input_n - VL + 1
#define DCTN  20
#define GCNIN 40
#define MROWS (BSZ * F66) // 33792

#define FP    80          // padded feature row for src bf16 (160B pitch)
#define K1P   480         // conv1 K: 6*80
#define K2    2560        // conv2 K: 5*512

__device__ __forceinline__ uint32_t smem_u32(const void* p) {
    uint32_t a;
    asm("{ .reg .u64 t; cvta.to.shared.u64 t, %1; cvt.u32.u64 %0, t; }" : "=r"(a) : "l"(p));
    return a;
}

__device__ __forceinline__ void mma16816(float* c, const uint32_t* a, uint32_t b0, uint32_t b1) {
    asm volatile(
        "mma.sync.aligned.m16n8k16.row.col.f32.bf16.bf16.f32 "
        "{%0,%1,%2,%3}, {%4,%5,%6,%7}, {%8,%9}, {%0,%1,%2,%3};"
        : "+f"(c[0]), "+f"(c[1]), "+f"(c[2]), "+f"(c[3])
        : "r"(a[0]), "r"(a[1]), "r"(a[2]), "r"(a[3]), "r"(b0), "r"(b1));
}

#define LDSM4(r, addr) \
    asm volatile("ldmatrix.sync.aligned.m8n8.x4.shared.b16 {%0,%1,%2,%3}, [%4];" \
        : "=r"((r)[0]), "=r"((r)[1]), "=r"((r)[2]), "=r"((r)[3]) : "r"(addr))

#define LDSM4T(r, addr) \
    asm volatile("ldmatrix.sync.aligned.m8n8.x4.trans.shared.b16 {%0,%1,%2,%3}, [%4];" \
        : "=r"((r)[0]), "=r"((r)[1]), "=r"((r)[2]), "=r"((r)[3]) : "r"(addr))

#define CPA16(saddr, gptr) \
    asm volatile("cp.async.ca.shared.global [%0], [%1], 16;" :: "r"(saddr), "l"(gptr))

// swizzled 64B-row address: row r (64B stride), 16B-chunk c (0..3)
#define SWZ(r, c) ((uint32_t)(((r) << 6) + ((((c) ^ (((r) >> 1) & 3))) << 4)))

// ---------------- scratch (device globals; no allocation) ----------------
__device__ float g_dct[DCTN * VL];

#define SRCP_N (BSZ * TIN * FP)
__device__ __align__(16) __nv_bfloat16 g_srch[SRCP_N + 512];
__device__ __align__(16) __nv_bfloat16 g_srcl[SRCP_N + 512];
__device__ __align__(16) __nv_bfloat16 g_k1h[(size_t)10240 * 512];
__device__ __align__(16) __nv_bfloat16 g_k1l[(size_t)10240 * 512];
__device__ __align__(16) __nv_bfloat16 g_q1h[(size_t)2560 * 512];
__device__ __align__(16) __nv_bfloat16 g_q1l[(size_t)2560 * 512];

__device__ __align__(16) __nv_bfloat16 g_Wk1h[(size_t)512 * K1P];
__device__ __align__(16) __nv_bfloat16 g_Wk1l[(size_t)512 * K1P];
__device__ __align__(16) __nv_bfloat16 g_Wk2h[(size_t)512 * K2];
__device__ __align__(16) __nv_bfloat16 g_Wk2l[(size_t)512 * K2];
__device__ __align__(16) __nv_bfloat16 g_Wq1h[(size_t)512 * K1P];
__device__ __align__(16) __nv_bfloat16 g_Wq1l[(size_t)512 * K1P];
__device__ __align__(16) __nv_bfloat16 g_Wq2h[(size_t)512 * K2];
__device__ __align__(16) __nv_bfloat16 g_Wq2l[(size_t)512 * K2];
__device__ __align__(16) __nv_bfloat16 g_Wg1h[(size_t)512 * 64];
__device__ __align__(16) __nv_bfloat16 g_Wg1l[(size_t)512 * 64];
__device__ __align__(16) __nv_bfloat16 g_Wgbh[(size_t)4 * 512 * 512];
__device__ __align__(16) __nv_bfloat16 g_Wgbl[(size_t)4 * 512 * 512];
__device__ __align__(16) __nv_bfloat16 g_Th[(size_t)MROWS * 512];
__device__ __align__(16) __nv_bfloat16 g_Tl[(size_t)MROWS * 512];
__device__ __align__(16) __nv_bfloat16 g_yh[(size_t)MROWS * 512];
__device__ __align__(16) __nv_bfloat16 g_yl[(size_t)MROWS * 512];
__device__ __align__(16) __nv_bfloat16 g_zh[(size_t)MROWS * 512];
__device__ __align__(16) __nv_bfloat16 g_zl[(size_t)MROWS * 512];
__device__ __align__(16) __nv_bfloat16 g_Aph[5 * 80 * 80];
__device__ __align__(16) __nv_bfloat16 g_Apl[5 * 80 * 80];

__device__ float g_key2[(size_t)8192 * 512];
__device__ float g_q[(size_t)512 * 512];
__device__ float g_att[BSZ * VN];
__device__ float g_x[(size_t)BSZ * F66 * GCNIN];
__device__ float g_t[(size_t)MROWS * 512];

// ---------------- epilogue descriptor ----------------
// modes: 0 plain fp32, 1 relu, 2 bias+bn+tanh, 3 bias+bn+tanh+resid
struct Epi {
    const float* bias;
    const float* gamma;
    const float* beta;
    int mode;
};

__device__ __forceinline__ void split_bf16(float v, __nv_bfloat16& h, __nv_bfloat16& l) {
    h = __float2bfloat16_rn(v);
    l = __float2bfloat16_rn(v - __bfloat162float(h));
}

__device__ __forceinline__ uint32_t pack2(float a, float b, bool lo) {
    __nv_bfloat16 ha, la, hb, lb;
    split_bf16(a, ha, la); split_bf16(b, hb, lb);
    uint16_t x = lo ? __bfloat16_as_ushort(la) : __bfloat16_as_ushort(ha);
    uint16_t y = lo ? __bfloat16_as_ushort(lb) : __bfloat16_as_ushort(hb);
    return (uint32_t)x | ((uint32_t)y << 16);
}

// ---------------- dct matrix ----------------
__global__ void dct_build() {
    for (int i = threadIdx.x; i < DCTN * VL; i += blockDim.x) {
        int k = i / VL, v = i % VL;
        double w = (k == 0) ? sqrt(1.0 / VL) : sqrt(2.0 / VL);
        g_dct[i] = (float)(w * cos(3.14159265358979323846 * (v + 0.5) * k / VL));
    }
}

// ---------------- src -> bf16 hi/lo (x 1e-3), padded layout [b*50+t][80] ----------------
__global__ void src_to_bf16(const float* __restrict__ src) {
    int total = SRCP_N + 512;
    for (int i = blockIdx.x * blockDim.x + threadIdx.x; i < total;
         i += gridDim.x * blockDim.x) {
        float v = 0.f;
        if (i < SRCP_N) {
            int f = i % FP;
            int row = i / FP;
            if (f < F66) v = src[row * F66 + f] * 1e-3f;
        }
        __nv_bfloat16 h, l; split_bf16(v, h, l);
        g_srch[i] = h; g_srcl[i] = l;
    }
}

// ---------------- ALL weight preps fused into one grid-stride kernel ----------------
#define PJ_C1 (512 * K1P)     // 245760
#define PJ_C2 (512 * K2)      // 1310720
#define PJ_G1 (512 * 64)      // 32768
#define PJ_GB (512 * 512)     // 262144
#define PJ_AT (5 * 80 * 80)   // 32000
#define PJ_TOTAL (2 * PJ_C1 + 2 * PJ_C2 + PJ_G1 + 4 * PJ_GB + PJ_AT)

__global__ void prep_all(const float* __restrict__ Wk1, const float* __restrict__ Wq1,
                         const float* __restrict__ Wk2, const float* __restrict__ Wq2,
                         const float* __restrict__ gc1_W, const float* __restrict__ gcb_W,
                         const float* __restrict__ gcb_att, const float* __restrict__ gc7_att) {
    for (int i = blockIdx.x * blockDim.x + threadIdx.x; i < PJ_TOTAL;
         i += gridDim.x * blockDim.x) {
        int j = i;
        float v; __nv_bfloat16* Dh; __nv_bfloat16* Dl; int o;
        if (j < PJ_C1) {
            int n = j / K1P, k = j % K1P;
            int tt = k / FP, f = k % FP;
            v = (f < F66) ? Wk1[n * 396 + f * 6 + tt] : 0.f;
            Dh = g_Wk1h; Dl = g_Wk1l; o = j;
        } else if ((j -= PJ_C1) < PJ_C1) {
            int n = j / K1P, k = j % K1P;
            int tt = k / FP, f = k % FP;
            v = (f < F66) ? Wq1[n * 396 + f * 6 + tt] : 0.f;
            Dh = g_Wq1h; Dl = g_Wq1l; o = j;
        } else if ((j -= PJ_C1) < PJ_C2) {
            int n = j / K2, k = j % K2;
            int tt = k >> 9, c = k & 511;
            v = Wk2[n * K2 + c * 5 + tt];
            Dh = g_Wk2h; Dl = g_Wk2l; o = j;
        } else if ((j -= PJ_C2) < PJ_C2) {
            int n = j / K2, k = j % K2;
            int tt = k >> 9, c = k & 511;
            v = Wq2[n * K2 + c * 5 + tt];
            Dh = g_Wq2h; Dl = g_Wq2l; o = j;
        } else if ((j -= PJ_C2) < PJ_G1) {
            int k = j & 63, n = j >> 6;
            v = (k < GCNIN) ? gc1_W[(size_t)k * 512 + n] : 0.f;
            Dh = g_Wg1h; Dl = g_Wg1l; o = j;
        } else if ((j -= PJ_G1) < 4 * PJ_GB) {
            int li = j / PJ_GB, r = j % PJ_GB;
            int k = r & 511, n = r >> 9;
            v = gcb_W[(size_t)li * PJ_GB + (size_t)k * 512 + n];
            Dh = g_Wgbh; Dl = g_Wgbl; o = j;
        } else {
            j -= 4 * PJ_GB;
            int li = j / 6400, rem = j % 6400;
            int r = rem / 80, c = rem % 80;
            v = 0.f;
            if (r < F66 && c < F66) {
                const float* s = (li < 4) ? (gcb_att + (size_t)li * F66 * F66) : gc7_att;
                v = s[r * F66 + c];
            }
            Dh = g_Aph; Dl = g_Apl; o = j;
        }
        __nv_bfloat16 h, l; split_bf16(v, h, l);
        Dh[o] = h; Dl[o] = l;
    }
}

// ---------------- HMMA bf16x3 GEMM, 128x128 tile, 256 threads, 2 CTAs/SM ----------------
// Optional batched second job: blocks with blockIdx.y >= ySplit switch to
// (B2h/B2l, C2h/C2l, npos2/off2) with fresh row range (query conv1 piggyback).
#define HG_SMEM 65536

__device__ __forceinline__ float epi_apply(float v, int col, int nmod, const Epi& e) {
    if (e.mode == 1) return fmaxf(v, 0.f);
    if (e.mode == 2 || e.mode == 3) {
        v += e.bias[col];
        int gi = nmod * 512 + col;
        v = tanhf(v * e.gamma[gi] * 0.9999950000374997f + e.beta[gi]);
    }
    return v;
}

__device__ __forceinline__ size_t amap(int amode, int r, int npos, int off, int K) {
    if (amode == 0)      return (size_t)r * K;
    else if (amode == 1) return ((size_t)(r / npos) * TIN + off + (r % npos)) * FP;
    else if (amode == 2) return ((size_t)(r >> 4) * 20 + (r & 15)) * 512;
    else                 return (size_t)r * 2560;
}

__global__ void __launch_bounds__(256, 2) hgemm(
    const __nv_bfloat16* __restrict__ Ah, const __nv_bfloat16* __restrict__ Al,
    int amode, int npos, int off,
    const __nv_bfloat16* __restrict__ Bh, const __nv_bfloat16* __restrict__ Bl,
    float* __restrict__ C, __nv_bfloat16* __restrict__ Ch, __nv_bfloat16* __restrict__ Cl,
    const __nv_bfloat16* __restrict__ Rh, const __nv_bfloat16* __restrict__ Rl,
    int M, int K, Epi e,
    int ySplit,
    const __nv_bfloat16* __restrict__ B2h, const __nv_bfloat16* __restrict__ B2l,
    __nv_bfloat16* __restrict__ C2h, __nv_bfloat16* __restrict__ C2l,
    int npos2, int off2) {
    extern __shared__ __align__(16) char smem[];
    const uint32_t sb = smem_u32(smem);
    const int tid = threadIdx.x;
    int bm0 = blockIdx.y * 128;
    if (ySplit > 0 && (int)blockIdx.y >= ySplit) {
        bm0 = ((int)blockIdx.y - ySplit) * 128;
        Bh = B2h; Bl = B2l; Ch = C2h; Cl = C2l;
        npos = npos2; off = off2; C = nullptr;
    }
    const int bn0 = blockIdx.x * 128;
    const int warp = tid >> 5, lane = tid & 31;
    const int wm = warp & 1, wn = warp >> 1;
    const int KT = K >> 5;
    const int nkt = KT / gridDim.z;
    const int kt0 = blockIdx.z * nkt;
    const int ktend = kt0 + nkt;

    const int lr = tid >> 2;
    const int lc = tid & 3;
    const size_t aRow0 = amap(amode, bm0 + lr, npos, off, K);
    const size_t aRow1 = amap(amode, bm0 + 64 + lr, npos, off, K);
    const size_t bRow0 = (size_t)(bn0 + lr) * K;
    const size_t bRow1 = (size_t)(bn0 + 64 + lr) * K;
    const uint32_t swA0 = SWZ(lr, lc);
    const uint32_t swA1 = SWZ(lr + 64, lc);

    float c[4][4][4];
#pragma unroll
    for (int i = 0; i < 4; i++)
#pragma unroll
        for (int j = 0; j < 4; j++)
#pragma unroll
            for (int q = 0; q < 4; q++) c[i][j][q] = 0.f;

#define HLOAD(buf, kt) do {                                                        \
    const int k0 = (kt) << 5;                                                      \
    const uint32_t bo = sb + (uint32_t)(buf) * 32768u;                             \
    CPA16(bo + swA0, Ah + aRow0 + k0 + lc * 8);                                    \
    CPA16(bo + swA1, Ah + aRow1 + k0 + lc * 8);                                    \
    CPA16(bo + 8192u + swA0, Al + aRow0 + k0 + lc * 8);                            \
    CPA16(bo + 8192u + swA1, Al + aRow1 + k0 + lc * 8);                            \
    CPA16(bo + 16384u + swA0, Bh + bRow0 + k0 + lc * 8);                           \
    CPA16(bo + 16384u + swA1, Bh + bRow1 + k0 + lc * 8);                           \
    CPA16(bo + 24576u + swA0, Bl + bRow0 + k0 + lc * 8);                           \
    CPA16(bo + 24576u + swA1, Bl + bRow1 + k0 + lc * 8);                           \
    asm volatile("cp.async.commit_group;");                                        \
} while (0)

    HLOAD(0, kt0);
    for (int kt = kt0; kt < ktend; kt++) {
        const int buf = (kt - kt0) & 1;
        if (kt + 1 < ktend) {
            HLOAD(buf ^ 1, kt + 1);
            asm volatile("cp.async.wait_group 1;");
        } else {
            asm volatile("cp.async.wait_group 0;");
        }
        __syncthreads();
        const uint32_t base = sb + (uint32_t)buf * 32768u;
#pragma unroll
        for (int kh = 0; kh < 2; kh++) {
            uint32_t ah[4][4], al[4][4], bh2[2][4], bl2[2][4];
#pragma unroll
            for (int mi = 0; mi < 4; mi++) {
                int row = wm * 64 + mi * 16 + (lane & 7) + ((lane >> 3) & 1) * 8;
                int cc = kh * 2 + (lane >> 4);
                uint32_t ad = base + SWZ(row, cc);
                LDSM4(ah[mi], ad);
                LDSM4(al[mi], ad + 8192u);
            }
#pragma unroll
            for (int bi = 0; bi < 2; bi++) {
                int row = wn * 32 + bi * 16 + (lane & 7) + (lane >> 4) * 8;
                int cc = kh * 2 + ((lane >> 3) & 1);
                uint32_t bd = base + 16384u + SWZ(row, cc);
                LDSM4(bh2[bi], bd);
                LDSM4(bl2[bi], bd + 8192u);
            }
#pragma unroll
            for (int mi = 0; mi < 4; mi++)
#pragma unroll
                for (int ni = 0; ni < 4; ni++) {
                    uint32_t b0h = bh2[ni >> 1][(ni & 1) * 2];
                    uint32_t b1h = bh2[ni >> 1][(ni & 1) * 2 + 1];
                    uint32_t b0l = bl2[ni >> 1][(ni & 1) * 2];
                    uint32_t b1l = bl2[ni >> 1][(ni & 1) * 2 + 1];
                    mma16816(c[mi][ni], ah[mi], b0h, b1h);
                    mma16816(c[mi][ni], al[mi], b0h, b1h);
                    mma16816(c[mi][ni], ah[mi], b0l, b1l);
                }
        }
        __syncthreads();
    }
#undef HLOAD

    // ---- epilogue ----
    float* Cz = C ? (C + (size_t)blockIdx.z * M * 512) : C;
#pragma unroll
    for (int mi = 0; mi < 4; mi++) {
        int r0 = bm0 + wm * 64 + mi * 16 + (lane >> 2);
        int r1 = r0 + 8;
        int nm0 = r0 % F66, nm1 = r1 % F66;
#pragma unroll
        for (int ni = 0; ni < 4; ni++) {
            int cb = bn0 + wn * 32 + ni * 8 + (lane & 3) * 2;
            size_t i0 = (size_t)r0 * 512 + cb;
            size_t i1 = (size_t)r1 * 512 + cb;
            float v0 = epi_apply(c[mi][ni][0], cb, nm0, e);
            float v1 = epi_apply(c[mi][ni][1], cb + 1, nm0, e);
            float v2 = epi_apply(c[mi][ni][2], cb, nm1, e);
            float v3 = epi_apply(c[mi][ni][3], cb + 1, nm1, e);
            if (e.mode == 3) {
                __nv_bfloat162 rh0 = *reinterpret_cast<const __nv_bfloat162*>(Rh + i0);
                __nv_bfloat162 rl0 = *reinterpret_cast<const __nv_bfloat162*>(Rl + i0);
                __nv_bfloat162 rh1 = *reinterpret_cast<const __nv_bfloat162*>(Rh + i1);
                __nv_bfloat162 rl1 = *reinterpret_cast<const __nv_bfloat162*>(Rl + i1);
                v0 += __bfloat162float(rh0.x) + __bfloat162float(rl0.x);
                v1 += __bfloat162float(rh0.y) + __bfloat162float(rl0.y);
                v2 += __bfloat162float(rh1.x) + __bfloat162float(rl1.x);
                v3 += __bfloat162float(rh1.y) + __bfloat162float(rl1.y);
            }
            if (Cz) {
                *reinterpret_cast<float2*>(Cz + i0) = make_float2(v0, v1);
                *reinterpret_cast<float2*>(Cz + i1) = make_float2(v2, v3);
            }
            if (Ch) {
                *reinterpret_cast<uint32_t*>(Ch + i0) = pack2(v0, v1, false);
                *reinterpret_cast<uint32_t*>(Cl + i0) = pack2(v0, v1, true);
                *reinterpret_cast<uint32_t*>(Ch + i1) = pack2(v2, v3, false);
                *reinterpret_cast<uint32_t*>(Cl + i1) = pack2(v2, v3, true);
            }
        }
    }
}

// ---------------- split-K reduce + relu (fp32 out) ----------------
__global__ void reduce_relu(const float* __restrict__ part, float* __restrict__ outp,
                            int n, int zn) {
    for (int i = blockIdx.x * blockDim.x + threadIdx.x; i < n;
         i += gridDim.x * blockDim.x) {
        float s = 0.f;
        for (int z = 0; z < zn; z++) s += part[(size_t)z * n + i];
        outp[i] = fmaxf(s, 0.f);
    }
}

// ---------------- batched node-mix via HMMA (A reused across 4 f-tiles) ----------------
#define AM_SMEM 71680

__global__ void __launch_bounds__(256, 2) amix_mma(
    const __nv_bfloat16* __restrict__ Aph, const __nv_bfloat16* __restrict__ Apl,
    const __nv_bfloat16* __restrict__ Yh, const __nv_bfloat16* __restrict__ Yl,
    __nv_bfloat16* __restrict__ Th, __nv_bfloat16* __restrict__ Tl,
    float* __restrict__ Tf) {
    extern __shared__ __align__(16) char smem[];
    const uint32_t sb = smem_u32(smem);
    const int b = blockIdx.x;
    const int tid = threadIdx.x;
    const int warp = tid >> 5, lane = tid & 31;

    for (int i = tid; i < 800; i += 256) {
        int r = i / 10, cc = i % 10;
        uint32_t dst = sb + (uint32_t)(r * 176 + cc * 16);
        CPA16(dst, Aph + r * 80 + cc * 8);
        CPA16(dst + 14080u, Apl + r * 80 + cc * 8);
    }
    for (int i = tid; i < 1056; i += 256) {
        int r = i >> 4, cc = i & 15;
        uint32_t dst = sb + 28160u + (uint32_t)(r * 272 + cc * 16);
        const size_t gsrc = ((size_t)b * F66 + r) * 512 + cc * 8;
        CPA16(dst, Yh + gsrc);
        CPA16(dst + 21760u, Yl + gsrc);
    }
    asm volatile("cp.async.commit_group;");
    for (int i = tid; i < 224; i += 256) {
        int r = 66 + (i >> 4), cc = i & 15;
        uint32_t dst = sb + 28160u + (uint32_t)(r * 272 + cc * 16);
        asm volatile("st.shared.v4.b32 [%0], {%1,%1,%1,%1};" :: "r"(dst), "r"(0u));
        asm volatile("st.shared.v4.b32 [%0], {%1,%1,%1,%1};" :: "r"(dst + 21760u), "r"(0u));
    }
    asm volatile("cp.async.wait_group 0;");
    __syncthreads();

    const int n0c = warp * 16;

    for (int fi = 0; fi < 4; fi++) {
        const int f0 = fi * 128;
        uint32_t bh[5][4], bl[5][4];
#pragma unroll
        for (int kt = 0; kt < 5; kt++) {
            int row = kt * 16 + ((lane >> 3) & 1) * 8 + (lane & 7);
            int col = n0c + (lane >> 4) * 8;
            uint32_t ad = sb + 28160u + (uint32_t)(row * 272 + col * 2);
            LDSM4T(bh[kt], ad);
            LDSM4T(bl[kt], ad + 21760u);
        }
        __syncthreads();
        if (fi + 1 < 4) {
            for (int i = tid; i < 1056; i += 256) {
                int r = i >> 4, cc = i & 15;
                uint32_t dst = sb + 28160u + (uint32_t)(r * 272 + cc * 16);
                const size_t gsrc = ((size_t)b * F66 + r) * 512 + (fi + 1) * 128 + cc * 8;
                CPA16(dst, Yh + gsrc);
                CPA16(dst + 21760u, Yl + gsrc);
            }
            asm volatile("cp.async.commit_group;");
        }

        float c[5][2][4];
#pragma unroll
        for (int mi = 0; mi < 5; mi++)
#pragma unroll
            for (int g = 0; g < 2; g++)
#pragma unroll
                for (int q = 0; q < 4; q++) c[mi][g][q] = 0.f;

#pragma unroll
        for (int mi = 0; mi < 5; mi++) {
#pragma unroll
            for (int kt = 0; kt < 5; kt++) {
                int row = mi * 16 + (lane & 7) + ((lane >> 3) & 1) * 8;
                int col = kt * 16 + (lane >> 4) * 8;
                uint32_t ad = sb + (uint32_t)(row * 176 + col * 2);
                uint32_t ah[4], al[4];
                LDSM4(ah, ad);
                LDSM4(al, ad + 14080u);
#pragma unroll
                for (int g = 0; g < 2; g++) {
                    mma16816(c[mi][g], ah, bh[kt][g * 2], bh[kt][g * 2 + 1]);
                    mma16816(c[mi][g], al, bh[kt][g * 2], bh[kt][g * 2 + 1]);
                    mma16816(c[mi][g], ah, bl[kt][g * 2], bl[kt][g * 2 + 1]);
                }
            }
        }

#pragma unroll
        for (int mi = 0; mi < 5; mi++) {
            int n_0 = mi * 16 + (lane >> 2);
            int n_1 = n_0 + 8;
#pragma unroll
            for (int g = 0; g < 2; g++) {
                int f = f0 + n0c + g * 8 + (lane & 3) * 2;
                if (n_0 < F66) {
                    size_t o = ((size_t)b * F66 + n_0) * 512 + f;
                    if (Tf) {
                        *reinterpret_cast<float2*>(Tf + o) = make_float2(c[mi][g][0], c[mi][g][1]);
                    } else {
                        *reinterpret_cast<uint32_t*>(Th + o) = pack2(c[mi][g][0], c[mi][g][1], false);
                        *reinterpret_cast<uint32_t*>(Tl + o) = pack2(c[mi][g][0], c[mi][g][1], true);
                    }
                }
                if (n_1 < F66) {
                    size_t o = ((size_t)b * F66 + n_1) * 512 + f;
                    if (Tf) {
                        *reinterpret_cast<float2*>(Tf + o) = make_float2(c[mi][g][2], c[mi][g][3]);
                    } else {
                        *reinterpret_cast<uint32_t*>(Th + o) = pack2(c[mi][g][2], c[mi][g][3], false);
                        *reinterpret_cast<uint32_t*>(Tl + o) = pack2(c[mi][g][2], c[mi][g][3], true);
                    }
                }
            }
        }

        if (fi + 1 < 4) {
            asm volatile("cp.async.wait_group 0;");
            __syncthreads();
        }
    }
}

// ---------------- gc7 + final iDCT fused ----------------
// Block of 128 rows (b,f): dct20[r] = A[row]@W[:, :20] + bias + xres; then
// out[b,v,f] = sum_k dct[k,v] * dct20[r][k] emitted directly.
__global__ void __launch_bounds__(256) gc7_idct(
    const float* __restrict__ A, const float* __restrict__ W,
    const float* __restrict__ bias, const float* __restrict__ xres,
    float* __restrict__ out) {
    __shared__ float As[128][17];
    __shared__ float Bs[16][21];
    __shared__ float Do[128][21];
    __shared__ float dctS[DCTN * VL];
    const int bm0 = blockIdx.x * 128;
    const int t = threadIdx.x;
    const int rp = t >> 2, cg = t & 3;
    float acc[2][5] = {};
    for (int k0 = 0; k0 < 512; k0 += 16) {
#pragma unroll
        for (int i = 0; i < 8; i++) {
            int idx = t + 256 * i;
            int r = idx >> 4, kk = idx & 15;
            As[r][kk] = A[(size_t)(bm0 + r) * 512 + k0 + kk];
        }
        for (int i = t; i < 320; i += 256) {
            int kk = i / 20, n = i % 20;
            Bs[kk][n] = W[(k0 + kk) * GCNIN + n];
        }
        __syncthreads();
#pragma unroll
        for (int kk = 0; kk < 16; kk++) {
            float a0 = As[rp * 2][kk], a1 = As[rp * 2 + 1][kk];
#pragma unroll
            for (int j = 0; j < 5; j++) {
                float bb = Bs[kk][cg * 5 + j];
                acc[0][j] += a0 * bb;
                acc[1][j] += a1 * bb;
            }
        }
        __syncthreads();
    }
    // stage dct20 into smem
#pragma unroll
    for (int rr = 0; rr < 2; rr++) {
        int r = rp * 2 + rr;
        int row = bm0 + r;
#pragma unroll
        for (int j = 0; j < 5; j++) {
            int n = cg * 5 + j;
            Do[r][n] = acc[rr][j] + bias[n] + xres[(size_t)row * GCNIN + n];
        }
    }
    for (int i = t; i < DCTN * VL; i += 256) dctS[i] = g_dct[i];
    __syncthreads();
    // emit out[b][v][f] for the 128 rows of this block
    for (int i = t; i < 128 * VL; i += 256) {
        int r = i / VL, v = i % VL;
        int row = bm0 + r;
        int b = row / F66, f = row % F66;
        float s = 0.f;
#pragma unroll
        for (int k = 0; k < DCTN; k++) s += dctS[k * VL + v] * Do[r][k];
        out[((size_t)b * VL + v) * F66 + f] = s;
    }
}

// ---------------- attention: score + normalize ----------------
__global__ void score_att_kernel(const float* __restrict__ q,
                                 const float* __restrict__ key2,
                                 float* __restrict__ att) {
    int b = blockIdx.x;
    __shared__ float sc[VN];
    int t = threadIdx.x;
    int w = t / 32, lane = t % 32;
    for (int n = w; n < VN; n += 8) {
        float s = 0.f;
        const float* qp = q + (size_t)b * 512;
        const float* kp = key2 + (size_t)(b * VN + n) * 512;
        for (int d = lane; d < 512; d += 32) s += qp[d] * kp[d];
        for (int o = 16; o; o >>= 1) s += __shfl_xor_sync(0xffffffffu, s, o);
        if (lane == 0) sc[n] = s + 1e-15f;
    }
    __syncthreads();
    float tot = 0.f;
#pragma unroll
    for (int n = 0; n < VN; n++) tot += sc[n];
    if (t < VN) att[b * VN + t] = sc[t] / tot;
}

// ---------------- build x = [dct_in | dct_att]  (b, 66, 40) ----------------
__global__ void x_build(const float* __restrict__ src) {
    int b = blockIdx.x;
    int t = threadIdx.x;
    __shared__ float ss[TIN * F66];
    __shared__ float sh_s[VL * F66];
    __shared__ float sh_dct[DCTN * VL];
    __shared__ float sh_att[VN];
    for (int i = t; i < TIN * F66; i += 256) ss[i] = src[(size_t)b * TIN * F66 + i];
    for (int i = t; i < DCTN * VL; i += 256) sh_dct[i] = g_dct[i];
    if (t < VN) sh_att[t] = g_att[b * VN + t];
    __syncthreads();
    for (int i = t; i < VL * F66; i += 256) {
        int v = i / F66, f = i % F66;
        float a = 0.f;
#pragma unroll
        for (int n = 0; n < VN; n++) a += sh_att[n] * ss[(n + v) * F66 + f];
        sh_s[i] = a;
    }
    __syncthreads();
    for (int i = t; i < F66 * GCNIN; i += 256) {
        int f = i / GCNIN, k = i % GCNIN;
        float a = 0.f;
        if (k < DCTN) {
#pragma unroll
            for (int v = 0; v < VL; v++) {
                int r = (v < KS_) ? (TIN - KS_ + v) : (TIN - 1);
                a += sh_dct[k * VL + v] * ss[r * F66 + f];
            }
        } else {
            int kk = k - DCTN;
#pragma unroll
            for (int v = 0; v < VL; v++) a += sh_dct[kk * VL + v] * sh_s[v * F66 + f];
        }
        g_x[(size_t)b * F66 * GCNIN + i] = a;
    }
}

// ---------------- scalar node mix for gc1 (F=40 -> Th/Tl Kp=64) ----------------
__global__ void __launch_bounds__(256) amix2(
    const float* __restrict__ A, const float* __restrict__ in,
    __nv_bfloat16* __restrict__ oh, __nv_bfloat16* __restrict__ ol, int F, int Kp) {
    int b = blockIdx.x;
    __shared__ float Ash[F66 * F66];
    __shared__ float insh[F66][64];
    int t = threadIdx.x;
    for (int i = t; i < F66 * F66; i += 256) Ash[i] = A[i];
    int fw = F;
    for (int i = t; i < F66 * 64; i += 256) {
        int m = i >> 6, f = i & 63;
        insh[m][f] = (f < fw) ? in[((size_t)b * F66 + m) * F + f] : 0.f;
    }
    __syncthreads();
    int w = t >> 5, lane = t & 31;
    int h = lane >> 4, sub = lane & 15;
    int fl = sub * 4;
#pragma unroll
    for (int pass = 0; pass < 5; pass++) {
        int n = pass * 16 + w * 2 + h;
        int nn = (n < F66) ? n : 0;
        const float* arow = Ash + nn * F66;
        float ax = 0.f, ay = 0.f, az = 0.f, aw = 0.f;
#pragma unroll 6
        for (int m = 0; m < F66; m++) {
            float a = arow[m];
            float4 yv = *reinterpret_cast<const float4*>(&insh[m][fl]);
            ax += a * yv.x; ay += a * yv.y; az += a * yv.z; aw += a * yv.w;
        }
        if (n < F66) {
            float vals[4] = {ax, ay, az, aw};
            size_t o = ((size_t)b * F66 + n) * Kp + fl;
#pragma unroll
            for (int j = 0; j < 4; j++) {
                float v = (fl + j < fw) ? vals[j] : 0.f;
                __nv_bfloat16 hh, ll; split_bf16(v, hh, ll);
                oh[o + j] = hh; ol[o + j] = ll;
            }
        }
    }
}

// ---------------- host launcher ----------------
template <typename T>
static T* sym(const void* s) {
    void* p = nullptr;
    cudaGetSymbolAddress(&p, s);
    return (T*)p;
}

extern "C" void kernel_launch(void* const* d_in, const int* in_sizes, int n_in,
                              void* d_out, int out_size) {
    const float* src     = (const float*)d_in[0];
    const float* Wq1     = (const float*)d_in[1];
    const float* Wq2     = (const float*)d_in[2];
    const float* Wk1     = (const float*)d_in[3];
    const float* Wk2     = (const float*)d_in[4];
    const float* gc1_W   = (const float*)d_in[5];
    const float* gc1_att = (const float*)d_in[6];
    const float* gc1_b   = (const float*)d_in[7];
    const float* bn1_g   = (const float*)d_in[8];
    const float* bn1_b   = (const float*)d_in[9];
    const float* gcb_W   = (const float*)d_in[10];
    const float* gcb_att = (const float*)d_in[11];
    const float* gcb_b   = (const float*)d_in[12];
    const float* gcb_bn_g= (const float*)d_in[13];
    const float* gcb_bn_b= (const float*)d_in[14];
    const float* gc7_W   = (const float*)d_in[15];
    const float* gc7_att = (const float*)d_in[16];
    const float* gc7_b   = (const float*)d_in[17];
    float* out = (float*)d_out;

    cudaFuncSetAttribute(hgemm, cudaFuncAttributeMaxDynamicSharedMemorySize, HG_SMEM);
    cudaFuncSetAttribute(amix_mma, cudaFuncAttributeMaxDynamicSharedMemorySize, AM_SMEM);

    __nv_bfloat16* srch = sym<__nv_bfloat16>(g_srch); __nv_bfloat16* srcl = sym<__nv_bfloat16>(g_srcl);
    __nv_bfloat16* k1h  = sym<__nv_bfloat16>(g_k1h);  __nv_bfloat16* k1l  = sym<__nv_bfloat16>(g_k1l);
    __nv_bfloat16* q1h  = sym<__nv_bfloat16>(g_q1h);  __nv_bfloat16* q1l  = sym<__nv_bfloat16>(g_q1l);
    __nv_bfloat16* Wk1h = sym<__nv_bfloat16>(g_Wk1h); __nv_bfloat16* Wk1l = sym<__nv_bfloat16>(g_Wk1l);
    __nv_bfloat16* Wk2h = sym<__nv_bfloat16>(g_Wk2h); __nv_bfloat16* Wk2l = sym<__nv_bfloat16>(g_Wk2l);
    __nv_bfloat16* Wq1h = sym<__nv_bfloat16>(g_Wq1h); __nv_bfloat16* Wq1l = sym<__nv_bfloat16>(g_Wq1l);
    __nv_bfloat16* Wq2h = sym<__nv_bfloat16>(g_Wq2h); __nv_bfloat16* Wq2l = sym<__nv_bfloat16>(g_Wq2l);
    __nv_bfloat16* Wg1h = sym<__nv_bfloat16>(g_Wg1h); __nv_bfloat16* Wg1l = sym<__nv_bfloat16>(g_Wg1l);
    __nv_bfloat16* Wgbh = sym<__nv_bfloat16>(g_Wgbh); __nv_bfloat16* Wgbl = sym<__nv_bfloat16>(g_Wgbl);
    __nv_bfloat16* Th   = sym<__nv_bfloat16>(g_Th);   __nv_bfloat16* Tl   = sym<__nv_bfloat16>(g_Tl);
    __nv_bfloat16* yh   = sym<__nv_bfloat16>(g_yh);   __nv_bfloat16* yl   = sym<__nv_bfloat16>(g_yl);
    __nv_bfloat16* zh   = sym<__nv_bfloat16>(g_zh);   __nv_bfloat16* zl   = sym<__nv_bfloat16>(g_zl);
    __nv_bfloat16* Aph  = sym<__nv_bfloat16>(g_Aph);  __nv_bfloat16* Apl  = sym<__nv_bfloat16>(g_Apl);

    float* key2 = sym<float>(g_key2);
    float* qv   = sym<float>(g_q);
    float* patt = sym<float>(g_att);
    float* px   = sym<float>(g_x);
    float* pt   = sym<float>(g_t);

    Epi ep_relu  = {nullptr, nullptr, nullptr, 1};
    Epi ep_plain = {nullptr, nullptr, nullptr, 0};

    // launch #3 (0-indexed) = fused conv1 hgemm (key tiles 0..79, query tiles 80..99)
    dct_build<<<1, 256>>>();                                    // #0
    src_to_bf16<<<1024, 256>>>(src);                             // #1
    prep_all<<<2048, 256>>>(Wk1, Wq1, Wk2, Wq2, gc1_W, gcb_W,    // #2
                            gcb_att, gc7_att);
    hgemm<<<dim3(4, 100), 256, HG_SMEM>>>(srch, srcl, 1, 20, 0,  // #3  <- ncu target
        Wk1h, Wk1l, nullptr, k1h, k1l, nullptr, nullptr, 10240, K1P, ep_relu,
        80, Wq1h, Wq1l, q1h, q1l, 5, TIN - KS_);
    hgemm<<<dim3(4, 64), 256, HG_SMEM>>>(k1h, k1l, 2, 0, 0,      // #4
        Wk2h, Wk2l, key2, nullptr, nullptr, nullptr, nullptr, 8192, K2, ep_relu,
        0, nullptr, nullptr, nullptr, nullptr, 0, 0);

    // ---- query conv2 (split-K z=16) ----
    hgemm<<<dim3(4, 4, 16), 256, HG_SMEM>>>(q1h, q1l, 3, 0, 0, Wq2h, Wq2l,
        pt, nullptr, nullptr, nullptr, nullptr, 512, K2, ep_plain,
        0, nullptr, nullptr, nullptr, nullptr, 0, 0);
    reduce_relu<<<512, 256>>>(pt, qv, 512 * 512, 16);

    // ---- attention + x ----
    score_att_kernel<<<BSZ, 256>>>(qv, key2, patt);
    x_build<<<BSZ, 256>>>(src);

    const int M = MROWS;

    // ---- gc1 ----
    {
        amix2<<<BSZ, 256>>>(gc1_att, px, Th, Tl, GCNIN, 64);
        Epi e = {gc1_b, bn1_g, bn1_b, 2};
        hgemm<<<dim3(4, M / 128), 256, HG_SMEM>>>(Th, Tl, 0, 0, 0, Wg1h, Wg1l,
            nullptr, yh, yl, nullptr, nullptr, M, 64, e,
            0, nullptr, nullptr, nullptr, nullptr, 0, 0);
    }

    // ---- 2 stages x 2 layers ----
    for (int st = 0; st < 2; st++) {
        for (int l = 0; l < 2; l++) {
            int li = st * 2 + l;
            const __nv_bfloat16* ih = (l == 0) ? yh : zh;
            const __nv_bfloat16* il = (l == 0) ? yl : zl;
            __nv_bfloat16* oh = (l == 0) ? zh : yh;
            __nv_bfloat16* ol = (l == 0) ? zl : yl;
            amix_mma<<<BSZ, 256, AM_SMEM>>>(Aph + li * 6400, Apl + li * 6400,
                                            ih, il, Th, Tl, nullptr);
            Epi e = {gcb_b + (size_t)li * 512,
                     gcb_bn_g + (size_t)li * F66 * 512,
                     gcb_bn_b + (size_t)li * F66 * 512,
                     (l == 1) ? 3 : 2};
            hgemm<<<dim3(4, M / 128), 256, HG_SMEM>>>(Th, Tl, 0, 0, 0,
                Wgbh + (size_t)li * 512 * 512, Wgbl + (size_t)li * 512 * 512,
                nullptr, oh, ol,
                (l == 1) ? yh : nullptr, (l == 1) ? yl : nullptr, M, 512, e,
                0, nullptr, nullptr, nullptr, nullptr, 0, 0);
        }
    }

    // ---- gc7 (+x residual) + final iDCT fused ----
    {
        amix_mma<<<BSZ, 256, AM_SMEM>>>(Aph + 4 * 6400, Apl + 4 * 6400,
                                        yh, yl, nullptr, nullptr, pt);
        gc7_idct<<<M / 128, 256>>>(pt, gc7_W, gc7_b, px, out);
    }

    (void)in_sizes; (void)n_in; (void)out_size;
}

// round 17
// speedup vs baseline: 1.0809x; 1.0042x over previous
#include <cuda_runtime.h>
#include <cuda_bf16.h>
#include <math.h>
#include <stdint.h>

// ---------------- constants ----------------
#define BSZ   512
#define F66   66
#define TIN   50
#define KS_   10
#define VL    35          // KS + output_n
#define VN    16          // input_n - VL + 1
#define DCTN  20
#define GCNIN 40
#define MROWS (BSZ * F66) // 33792

#define FP    80          // padded feature row for src bf16 (160B pitch)
#define K1P   480         // conv1 K: 6*80
#define K2    2560        // conv2 K: 5*512

__device__ __forceinline__ uint32_t smem_u32(const void* p) {
    uint32_t a;
    asm("{ .reg .u64 t; cvta.to.shared.u64 t, %1; cvt.u32.u64 %0, t; }" : "=r"(a) : "l"(p));
    return a;
}

__device__ __forceinline__ void mma16816(float* c, const uint32_t* a, uint32_t b0, uint32_t b1) {
    asm volatile(
        "mma.sync.aligned.m16n8k16.row.col.f32.bf16.bf16.f32 "
        "{%0,%1,%2,%3}, {%4,%5,%6,%7}, {%8,%9}, {%0,%1,%2,%3};"
        : "+f"(c[0]), "+f"(c[1]), "+f"(c[2]), "+f"(c[3])
        : "r"(a[0]), "r"(a[1]), "r"(a[2]), "r"(a[3]), "r"(b0), "r"(b1));
}

#define LDSM4(r, addr) \
    asm volatile("ldmatrix.sync.aligned.m8n8.x4.shared.b16 {%0,%1,%2,%3}, [%4];" \
        : "=r"((r)[0]), "=r"((r)[1]), "=r"((r)[2]), "=r"((r)[3]) : "r"(addr))

#define LDSM4T(r, addr) \
    asm volatile("ldmatrix.sync.aligned.m8n8.x4.trans.shared.b16 {%0,%1,%2,%3}, [%4];" \
        : "=r"((r)[0]), "=r"((r)[1]), "=r"((r)[2]), "=r"((r)[3]) : "r"(addr))

#define CPA16(saddr, gptr) \
    asm volatile("cp.async.ca.shared.global [%0], [%1], 16;" :: "r"(saddr), "l"(gptr))

// swizzled 64B-row address: row r (64B stride), 16B-chunk c (0..3)
#define SWZ(r, c) ((uint32_t)(((r) << 6) + ((((c) ^ (((r) >> 1) & 3))) << 4)))

// ---------------- scratch (device globals; no allocation) ----------------
__device__ float g_dct[DCTN * VL];

#define SRCP_N (BSZ * TIN * FP)
__device__ __align__(16) __nv_bfloat16 g_srch[SRCP_N + 512];
__device__ __align__(16) __nv_bfloat16 g_srcl[SRCP_N + 512];
__device__ __align__(16) __nv_bfloat16 g_k1h[(size_t)10240 * 512];
__device__ __align__(16) __nv_bfloat16 g_k1l[(size_t)10240 * 512];
__device__ __align__(16) __nv_bfloat16 g_q1h[(size_t)2560 * 512];
__device__ __align__(16) __nv_bfloat16 g_q1l[(size_t)2560 * 512];

__device__ __align__(16) __nv_bfloat16 g_Wk1h[(size_t)512 * K1P];
__device__ __align__(16) __nv_bfloat16 g_Wk1l[(size_t)512 * K1P];
__device__ __align__(16) __nv_bfloat16 g_Wk2h[(size_t)512 * K2];
__device__ __align__(16) __nv_bfloat16 g_Wk2l[(size_t)512 * K2];
__device__ __align__(16) __nv_bfloat16 g_Wq1h[(size_t)512 * K1P];
__device__ __align__(16) __nv_bfloat16 g_Wq1l[(size_t)512 * K1P];
__device__ __align__(16) __nv_bfloat16 g_Wq2h[(size_t)512 * K2];
__device__ __align__(16) __nv_bfloat16 g_Wq2l[(size_t)512 * K2];
__device__ __align__(16) __nv_bfloat16 g_Wg1h[(size_t)512 * 64];
__device__ __align__(16) __nv_bfloat16 g_Wg1l[(size_t)512 * 64];
__device__ __align__(16) __nv_bfloat16 g_Wgbh[(size_t)4 * 512 * 512];
__device__ __align__(16) __nv_bfloat16 g_Wgbl[(size_t)4 * 512 * 512];
__device__ __align__(16) __nv_bfloat16 g_Th[(size_t)MROWS * 512];
__device__ __align__(16) __nv_bfloat16 g_Tl[(size_t)MROWS * 512];
__device__ __align__(16) __nv_bfloat16 g_yh[(size_t)MROWS * 512];
__device__ __align__(16) __nv_bfloat16 g_yl[(size_t)MROWS * 512];
__device__ __align__(16) __nv_bfloat16 g_zh[(size_t)MROWS * 512];
__device__ __align__(16) __nv_bfloat16 g_zl[(size_t)MROWS * 512];
__device__ __align__(16) __nv_bfloat16 g_Aph[5 * 80 * 80];
__device__ __align__(16) __nv_bfloat16 g_Apl[5 * 80 * 80];

__device__ float g_key2[(size_t)8192 * 512];
__device__ float g_q[(size_t)512 * 512];
__device__ float g_x[(size_t)BSZ * F66 * GCNIN];
__device__ float g_t[(size_t)MROWS * 512];

// ---------------- epilogue descriptor ----------------
// modes: 0 plain fp32, 1 relu, 2 bias+bn+tanh, 3 bias+bn+tanh+resid
struct Epi {
    const float* bias;
    const float* gamma;
    const float* beta;
    int mode;
};

__device__ __forceinline__ void split_bf16(float v, __nv_bfloat16& h, __nv_bfloat16& l) {
    h = __float2bfloat16_rn(v);
    l = __float2bfloat16_rn(v - __bfloat162float(h));
}

__device__ __forceinline__ uint32_t pack2(float a, float b, bool lo) {
    __nv_bfloat16 ha, la, hb, lb;
    split_bf16(a, ha, la); split_bf16(b, hb, lb);
    uint16_t x = lo ? __bfloat16_as_ushort(la) : __bfloat16_as_ushort(ha);
    uint16_t y = lo ? __bfloat16_as_ushort(lb) : __bfloat16_as_ushort(hb);
    return (uint32_t)x | ((uint32_t)y << 16);
}

// ---------------- ALL preps fused: src->bf16, dct, weights, att pads ----------------
#define PJ_SRC (SRCP_N + 512)
#define PJ_DCT (DCTN * VL)
#define PJ_C1 (512 * K1P)
#define PJ_C2 (512 * K2)
#define PJ_G1 (512 * 64)
#define PJ_GB (512 * 512)
#define PJ_AT (5 * 80 * 80)
#define PJ_TOTAL (PJ_SRC + PJ_DCT + 2 * PJ_C1 + 2 * PJ_C2 + PJ_G1 + 4 * PJ_GB + PJ_AT)

__global__ void prep_all(const float* __restrict__ src,
                         const float* __restrict__ Wk1, const float* __restrict__ Wq1,
                         const float* __restrict__ Wk2, const float* __restrict__ Wq2,
                         const float* __restrict__ gc1_W, const float* __restrict__ gcb_W,
                         const float* __restrict__ gcb_att, const float* __restrict__ gc7_att) {
    for (int i = blockIdx.x * blockDim.x + threadIdx.x; i < PJ_TOTAL;
         i += gridDim.x * blockDim.x) {
        int j = i;
        float v; __nv_bfloat16* Dh; __nv_bfloat16* Dl; int o;
        if (j < PJ_SRC) {                        // src -> bf16 hi/lo x 1e-3, [b*50+t][80]
            v = 0.f;
            if (j < SRCP_N) {
                int f = j % FP;
                int row = j / FP;
                if (f < F66) v = src[row * F66 + f] * 1e-3f;
            }
            Dh = g_srch; Dl = g_srcl; o = j;
        } else if ((j -= PJ_SRC) < PJ_DCT) {     // dct matrix (fp32 direct)
            int k = j / VL, vv = j % VL;
            double w = (k == 0) ? sqrt(1.0 / VL) : sqrt(2.0 / VL);
            g_dct[j] = (float)(w * cos(3.14159265358979323846 * (vv + 0.5) * k / VL));
            continue;
        } else if ((j -= PJ_DCT) < PJ_C1) {
            int n = j / K1P, k = j % K1P;
            int tt = k / FP, f = k % FP;
            v = (f < F66) ? Wk1[n * 396 + f * 6 + tt] : 0.f;
            Dh = g_Wk1h; Dl = g_Wk1l; o = j;
        } else if ((j -= PJ_C1) < PJ_C1) {
            int n = j / K1P, k = j % K1P;
            int tt = k / FP, f = k % FP;
            v = (f < F66) ? Wq1[n * 396 + f * 6 + tt] : 0.f;
            Dh = g_Wq1h; Dl = g_Wq1l; o = j;
        } else if ((j -= PJ_C1) < PJ_C2) {
            int n = j / K2, k = j % K2;
            int tt = k >> 9, c = k & 511;
            v = Wk2[n * K2 + c * 5 + tt];
            Dh = g_Wk2h; Dl = g_Wk2l; o = j;
        } else if ((j -= PJ_C2) < PJ_C2) {
            int n = j / K2, k = j % K2;
            int tt = k >> 9, c = k & 511;
            v = Wq2[n * K2 + c * 5 + tt];
            Dh = g_Wq2h; Dl = g_Wq2l; o = j;
        } else if ((j -= PJ_C2) < PJ_G1) {
            int k = j & 63, n = j >> 6;
            v = (k < GCNIN) ? gc1_W[(size_t)k * 512 + n] : 0.f;
            Dh = g_Wg1h; Dl = g_Wg1l; o = j;
        } else if ((j -= PJ_G1) < 4 * PJ_GB) {
            int li = j / PJ_GB, r = j % PJ_GB;
            int k = r & 511, n = r >> 9;
            v = gcb_W[(size_t)li * PJ_GB + (size_t)k * 512 + n];
            Dh = g_Wgbh; Dl = g_Wgbl; o = j;
        } else {
            j -= 4 * PJ_GB;
            int li = j / 6400, rem = j % 6400;
            int r = rem / 80, c = rem % 80;
            v = 0.f;
            if (r < F66 && c < F66) {
                const float* s = (li < 4) ? (gcb_att + (size_t)li * F66 * F66) : gc7_att;
                v = s[r * F66 + c];
            }
            Dh = g_Aph; Dl = g_Apl; o = j;
        }
        __nv_bfloat16 h, l; split_bf16(v, h, l);
        Dh[o] = h; Dl[o] = l;
    }
}

// ---------------- HMMA bf16x3 GEMM, 128x128 tile, 256 threads, 2 CTAs/SM ----------------
// Optional batched second job: blocks with blockIdx.y >= ySplit switch to
// (B2h/B2l, C2h/C2l, npos2/off2) with fresh row range (query conv1 piggyback).
#define HG_SMEM 65536

__device__ __forceinline__ float epi_apply(float v, int col, int nmod, const Epi& e) {
    if (e.mode == 1) return fmaxf(v, 0.f);
    if (e.mode == 2 || e.mode == 3) {
        v += e.bias[col];
        int gi = nmod * 512 + col;
        v = tanhf(v * e.gamma[gi] * 0.9999950000374997f + e.beta[gi]);
    }
    return v;
}

__device__ __forceinline__ size_t amap(int amode, int r, int npos, int off, int K) {
    if (amode == 0)      return (size_t)r * K;
    else if (amode == 1) return ((size_t)(r / npos) * TIN + off + (r % npos)) * FP;
    else if (amode == 2) return ((size_t)(r >> 4) * 20 + (r & 15)) * 512;
    else                 return (size_t)r * 2560;
}

__global__ void __launch_bounds__(256, 2) hgemm(
    const __nv_bfloat16* __restrict__ Ah, const __nv_bfloat16* __restrict__ Al,
    int amode, int npos, int off,
    const __nv_bfloat16* __restrict__ Bh, const __nv_bfloat16* __restrict__ Bl,
    float* __restrict__ C, __nv_bfloat16* __restrict__ Ch, __nv_bfloat16* __restrict__ Cl,
    const __nv_bfloat16* __restrict__ Rh, const __nv_bfloat16* __restrict__ Rl,
    int M, int K, Epi e,
    int ySplit,
    const __nv_bfloat16* __restrict__ B2h, const __nv_bfloat16* __restrict__ B2l,
    __nv_bfloat16* __restrict__ C2h, __nv_bfloat16* __restrict__ C2l,
    int npos2, int off2) {
    extern __shared__ __align__(16) char smem[];
    const uint32_t sb = smem_u32(smem);
    const int tid = threadIdx.x;
    int bm0 = blockIdx.y * 128;
    if (ySplit > 0 && (int)blockIdx.y >= ySplit) {
        bm0 = ((int)blockIdx.y - ySplit) * 128;
        Bh = B2h; Bl = B2l; Ch = C2h; Cl = C2l;
        npos = npos2; off = off2; C = nullptr;
    }
    const int bn0 = blockIdx.x * 128;
    const int warp = tid >> 5, lane = tid & 31;
    const int wm = warp & 1, wn = warp >> 1;
    const int KT = K >> 5;
    const int nkt = KT / gridDim.z;
    const int kt0 = blockIdx.z * nkt;
    const int ktend = kt0 + nkt;

    const int lr = tid >> 2;
    const int lc = tid & 3;
    const size_t aRow0 = amap(amode, bm0 + lr, npos, off, K);
    const size_t aRow1 = amap(amode, bm0 + 64 + lr, npos, off, K);
    const size_t bRow0 = (size_t)(bn0 + lr) * K;
    const size_t bRow1 = (size_t)(bn0 + 64 + lr) * K;
    const uint32_t swA0 = SWZ(lr, lc);
    const uint32_t swA1 = SWZ(lr + 64, lc);

    float c[4][4][4];
#pragma unroll
    for (int i = 0; i < 4; i++)
#pragma unroll
        for (int j = 0; j < 4; j++)
#pragma unroll
            for (int q = 0; q < 4; q++) c[i][j][q] = 0.f;

#define HLOAD(buf, kt) do {                                                        \
    const int k0 = (kt) << 5;                                                      \
    const uint32_t bo = sb + (uint32_t)(buf) * 32768u;                             \
    CPA16(bo + swA0, Ah + aRow0 + k0 + lc * 8);                                    \
    CPA16(bo + swA1, Ah + aRow1 + k0 + lc * 8);                                    \
    CPA16(bo + 8192u + swA0, Al + aRow0 + k0 + lc * 8);                            \
    CPA16(bo + 8192u + swA1, Al + aRow1 + k0 + lc * 8);                            \
    CPA16(bo + 16384u + swA0, Bh + bRow0 + k0 + lc * 8);                           \
    CPA16(bo + 16384u + swA1, Bh + bRow1 + k0 + lc * 8);                           \
    CPA16(bo + 24576u + swA0, Bl + bRow0 + k0 + lc * 8);                           \
    CPA16(bo + 24576u + swA1, Bl + bRow1 + k0 + lc * 8);                           \
    asm volatile("cp.async.commit_group;");                                        \
} while (0)

    HLOAD(0, kt0);
    for (int kt = kt0; kt < ktend; kt++) {
        const int buf = (kt - kt0) & 1;
        if (kt + 1 < ktend) {
            HLOAD(buf ^ 1, kt + 1);
            asm volatile("cp.async.wait_group 1;");
        } else {
            asm volatile("cp.async.wait_group 0;");
        }
        __syncthreads();
        const uint32_t base = sb + (uint32_t)buf * 32768u;
#pragma unroll
        for (int kh = 0; kh < 2; kh++) {
            uint32_t ah[4][4], al[4][4], bh2[2][4], bl2[2][4];
#pragma unroll
            for (int mi = 0; mi < 4; mi++) {
                int row = wm * 64 + mi * 16 + (lane & 7) + ((lane >> 3) & 1) * 8;
                int cc = kh * 2 + (lane >> 4);
                uint32_t ad = base + SWZ(row, cc);
                LDSM4(ah[mi], ad);
                LDSM4(al[mi], ad + 8192u);
            }
#pragma unroll
            for (int bi = 0; bi < 2; bi++) {
                int row = wn * 32 + bi * 16 + (lane & 7) + (lane >> 4) * 8;
                int cc = kh * 2 + ((lane >> 3) & 1);
                uint32_t bd = base + 16384u + SWZ(row, cc);
                LDSM4(bh2[bi], bd);
                LDSM4(bl2[bi], bd + 8192u);
            }
#pragma unroll
            for (int mi = 0; mi < 4; mi++)
#pragma unroll
                for (int ni = 0; ni < 4; ni++) {
                    uint32_t b0h = bh2[ni >> 1][(ni & 1) * 2];
                    uint32_t b1h = bh2[ni >> 1][(ni & 1) * 2 + 1];
                    uint32_t b0l = bl2[ni >> 1][(ni & 1) * 2];
                    uint32_t b1l = bl2[ni >> 1][(ni & 1) * 2 + 1];
                    mma16816(c[mi][ni], ah[mi], b0h, b1h);
                    mma16816(c[mi][ni], al[mi], b0h, b1h);
                    mma16816(c[mi][ni], ah[mi], b0l, b1l);
                }
        }
        __syncthreads();
    }
#undef HLOAD

    // ---- epilogue ----
    float* Cz = C ? (C + (size_t)blockIdx.z * M * 512) : C;
#pragma unroll
    for (int mi = 0; mi < 4; mi++) {
        int r0 = bm0 + wm * 64 + mi * 16 + (lane >> 2);
        int r1 = r0 + 8;
        int nm0 = r0 % F66, nm1 = r1 % F66;
#pragma unroll
        for (int ni = 0; ni < 4; ni++) {
            int cb = bn0 + wn * 32 + ni * 8 + (lane & 3) * 2;
            size_t i0 = (size_t)r0 * 512 + cb;
            size_t i1 = (size_t)r1 * 512 + cb;
            float v0 = epi_apply(c[mi][ni][0], cb, nm0, e);
            float v1 = epi_apply(c[mi][ni][1], cb + 1, nm0, e);
            float v2 = epi_apply(c[mi][ni][2], cb, nm1, e);
            float v3 = epi_apply(c[mi][ni][3], cb + 1, nm1, e);
            if (e.mode == 3) {
                __nv_bfloat162 rh0 = *reinterpret_cast<const __nv_bfloat162*>(Rh + i0);
                __nv_bfloat162 rl0 = *reinterpret_cast<const __nv_bfloat162*>(Rl + i0);
                __nv_bfloat162 rh1 = *reinterpret_cast<const __nv_bfloat162*>(Rh + i1);
                __nv_bfloat162 rl1 = *reinterpret_cast<const __nv_bfloat162*>(Rl + i1);
                v0 += __bfloat162float(rh0.x) + __bfloat162float(rl0.x);
                v1 += __bfloat162float(rh0.y) + __bfloat162float(rl0.y);
                v2 += __bfloat162float(rh1.x) + __bfloat162float(rl1.x);
                v3 += __bfloat162float(rh1.y) + __bfloat162float(rl1.y);
            }
            if (Cz) {
                *reinterpret_cast<float2*>(Cz + i0) = make_float2(v0, v1);
                *reinterpret_cast<float2*>(Cz + i1) = make_float2(v2, v3);
            }
            if (Ch) {
                *reinterpret_cast<uint32_t*>(Ch + i0) = pack2(v0, v1, false);
                *reinterpret_cast<uint32_t*>(Cl + i0) = pack2(v0, v1, true);
                *reinterpret_cast<uint32_t*>(Ch + i1) = pack2(v2, v3, false);
                *reinterpret_cast<uint32_t*>(Cl + i1) = pack2(v2, v3, true);
            }
        }
    }
}

// ---------------- split-K reduce + relu (fp32 out) ----------------
__global__ void reduce_relu(const float* __restrict__ part, float* __restrict__ outp,
                            int n, int zn) {
    for (int i = blockIdx.x * blockDim.x + threadIdx.x; i < n;
         i += gridDim.x * blockDim.x) {
        float s = 0.f;
        for (int z = 0; z < zn; z++) s += part[(size_t)z * n + i];
        outp[i] = fmaxf(s, 0.f);
    }
}

// ---------------- fused attention + x build + gc1 node-mix ----------------
// Per batch b: scores(q,key2) -> att -> s -> x (written to px for gc7 resid)
// -> T = gc1_att @ x (emitted as Th/Tl with Kp=64 zero pad).
// dyn smem floats: ss 3300 | dct 700 | sc 16 | att 16 | shs 2310 | xsh 2640 | Ash 4356
#define AX_SMEM (13344 * 4)

__global__ void __launch_bounds__(256) att_x_mix(
    const float* __restrict__ src, const float* __restrict__ q,
    const float* __restrict__ key2, const float* __restrict__ gc1_att,
    float* __restrict__ px, __nv_bfloat16* __restrict__ Th, __nv_bfloat16* __restrict__ Tl) {
    extern __shared__ float sm[];
    float* ss  = sm;             // 3300
    float* dct = sm + 3300;      // 700
    float* sc  = sm + 4000;      // 16
    float* att = sm + 4016;      // 16
    float* shs = sm + 4032;      // 2310
    float* xsh = sm + 6342;      // 2640
    float* Ash = sm + 8982;      // 4356
    const int b = blockIdx.x;
    const int t = threadIdx.x;
    const int w = t >> 5, lane = t & 31;

    for (int i = t; i < TIN * F66; i += 256) ss[i] = src[(size_t)b * TIN * F66 + i];
    for (int i = t; i < DCTN * VL; i += 256) dct[i] = g_dct[i];
    for (int i = t; i < F66 * F66; i += 256) Ash[i] = gc1_att[i];

    // scores (uses only globals; no dependence on ss/dct loads)
    for (int n = w; n < VN; n += 8) {
        float s = 0.f;
        const float* qp = q + (size_t)b * 512;
        const float* kp = key2 + (size_t)(b * VN + n) * 512;
        for (int d = lane; d < 512; d += 32) s += qp[d] * kp[d];
        for (int o = 16; o; o >>= 1) s += __shfl_xor_sync(0xffffffffu, s, o);
        if (lane == 0) sc[n] = s + 1e-15f;
    }
    __syncthreads();
    if (t < VN) {
        float tot = 0.f;
#pragma unroll
        for (int n = 0; n < VN; n++) tot += sc[n];
        att[t] = sc[t] / tot;
    }
    __syncthreads();

    for (int i = t; i < VL * F66; i += 256) {
        int v = i / F66, f = i % F66;
        float a = 0.f;
#pragma unroll
        for (int n = 0; n < VN; n++) a += att[n] * ss[(n + v) * F66 + f];
        shs[i] = a;
    }
    __syncthreads();

    for (int i = t; i < F66 * GCNIN; i += 256) {
        int f = i / GCNIN, k = i % GCNIN;
        float a = 0.f;
        if (k < DCTN) {
#pragma unroll
            for (int v = 0; v < VL; v++) {
                int r = (v < KS_) ? (TIN - KS_ + v) : (TIN - 1);
                a += dct[k * VL + v] * ss[r * F66 + f];
            }
        } else {
            int kk = k - DCTN;
#pragma unroll
            for (int v = 0; v < VL; v++) a += dct[kk * VL + v] * shs[v * F66 + f];
        }
        xsh[i] = a;
        px[(size_t)b * F66 * GCNIN + i] = a;
    }
    __syncthreads();

    // T[n][f64] = sum_m Ash[n][m] * xsh[m][f] (f<40), 0 otherwise
    for (int i = t; i < F66 * 64; i += 256) {
        int n = i >> 6, f = i & 63;
        float a = 0.f;
        if (f < GCNIN) {
            const float* arow = Ash + n * F66;
#pragma unroll 6
            for (int m = 0; m < F66; m++) a += arow[m] * xsh[m * GCNIN + f];
        }
        __nv_bfloat16 h, l; split_bf16(a, h, l);
        size_t o = ((size_t)b * F66 + n) * 64 + f;
        Th[o] = h; Tl[o] = l;
    }
}

// ---------------- batched node-mix via HMMA (A reused across 4 f-tiles) ----------------
#define AM_SMEM 71680

__global__ void __launch_bounds__(256, 2) amix_mma(
    const __nv_bfloat16* __restrict__ Aph, const __nv_bfloat16* __restrict__ Apl,
    const __nv_bfloat16* __restrict__ Yh, const __nv_bfloat16* __restrict__ Yl,
    __nv_bfloat16* __restrict__ Th, __nv_bfloat16* __restrict__ Tl,
    float* __restrict__ Tf) {
    extern __shared__ __align__(16) char smem[];
    const uint32_t sb = smem_u32(smem);
    const int b = blockIdx.x;
    const int tid = threadIdx.x;
    const int warp = tid >> 5, lane = tid & 31;

    for (int i = tid; i < 800; i += 256) {
        int r = i / 10, cc = i % 10;
        uint32_t dst = sb + (uint32_t)(r * 176 + cc * 16);
        CPA16(dst, Aph + r * 80 + cc * 8);
        CPA16(dst + 14080u, Apl + r * 80 + cc * 8);
    }
    for (int i = tid; i < 1056; i += 256) {
        int r = i >> 4, cc = i & 15;
        uint32_t dst = sb + 28160u + (uint32_t)(r * 272 + cc * 16);
        const size_t gsrc = ((size_t)b * F66 + r) * 512 + cc * 8;
        CPA16(dst, Yh + gsrc);
        CPA16(dst + 21760u, Yl + gsrc);
    }
    asm volatile("cp.async.commit_group;");
    for (int i = tid; i < 224; i += 256) {
        int r = 66 + (i >> 4), cc = i & 15;
        uint32_t dst = sb + 28160u + (uint32_t)(r * 272 + cc * 16);
        asm volatile("st.shared.v4.b32 [%0], {%1,%1,%1,%1};" :: "r"(dst), "r"(0u));
        asm volatile("st.shared.v4.b32 [%0], {%1,%1,%1,%1};" :: "r"(dst + 21760u), "r"(0u));
    }
    asm volatile("cp.async.wait_group 0;");
    __syncthreads();

    const int n0c = warp * 16;

    for (int fi = 0; fi < 4; fi++) {
        const int f0 = fi * 128;
        uint32_t bh[5][4], bl[5][4];
#pragma unroll
        for (int kt = 0; kt < 5; kt++) {
            int row = kt * 16 + ((lane >> 3) & 1) * 8 + (lane & 7);
            int col = n0c + (lane >> 4) * 8;
            uint32_t ad = sb + 28160u + (uint32_t)(row * 272 + col * 2);
            LDSM4T(bh[kt], ad);
            LDSM4T(bl[kt], ad + 21760u);
        }
        __syncthreads();
        if (fi + 1 < 4) {
            for (int i = tid; i < 1056; i += 256) {
                int r = i >> 4, cc = i & 15;
                uint32_t dst = sb + 28160u + (uint32_t)(r * 272 + cc * 16);
                const size_t gsrc = ((size_t)b * F66 + r) * 512 + (fi + 1) * 128 + cc * 8;
                CPA16(dst, Yh + gsrc);
                CPA16(dst + 21760u, Yl + gsrc);
            }
            asm volatile("cp.async.commit_group;");
        }

        float c[5][2][4];
#pragma unroll
        for (int mi = 0; mi < 5; mi++)
#pragma unroll
            for (int g = 0; g < 2; g++)
#pragma unroll
                for (int q = 0; q < 4; q++) c[mi][g][q] = 0.f;

#pragma unroll
        for (int mi = 0; mi < 5; mi++) {
#pragma unroll
            for (int kt = 0; kt < 5; kt++) {
                int row = mi * 16 + (lane & 7) + ((lane >> 3) & 1) * 8;
                int col = kt * 16 + (lane >> 4) * 8;
                uint32_t ad = sb + (uint32_t)(row * 176 + col * 2);
                uint32_t ah[4], al[4];
                LDSM4(ah, ad);
                LDSM4(al, ad + 14080u);
#pragma unroll
                for (int g = 0; g < 2; g++) {
                    mma16816(c[mi][g], ah, bh[kt][g * 2], bh[kt][g * 2 + 1]);
                    mma16816(c[mi][g], al, bh[kt][g * 2], bh[kt][g * 2 + 1]);
                    mma16816(c[mi][g], ah, bl[kt][g * 2], bl[kt][g * 2 + 1]);
                }
            }
        }

#pragma unroll
        for (int mi = 0; mi < 5; mi++) {
            int n_0 = mi * 16 + (lane >> 2);
            int n_1 = n_0 + 8;
#pragma unroll
            for (int g = 0; g < 2; g++) {
                int f = f0 + n0c + g * 8 + (lane & 3) * 2;
                if (n_0 < F66) {
                    size_t o = ((size_t)b * F66 + n_0) * 512 + f;
                    if (Tf) {
                        *reinterpret_cast<float2*>(Tf + o) = make_float2(c[mi][g][0], c[mi][g][1]);
                    } else {
                        *reinterpret_cast<uint32_t*>(Th + o) = pack2(c[mi][g][0], c[mi][g][1], false);
                        *reinterpret_cast<uint32_t*>(Tl + o) = pack2(c[mi][g][0], c[mi][g][1], true);
                    }
                }
                if (n_1 < F66) {
                    size_t o = ((size_t)b * F66 + n_1) * 512 + f;
                    if (Tf) {
                        *reinterpret_cast<float2*>(Tf + o) = make_float2(c[mi][g][2], c[mi][g][3]);
                    } else {
                        *reinterpret_cast<uint32_t*>(Th + o) = pack2(c[mi][g][2], c[mi][g][3], false);
                        *reinterpret_cast<uint32_t*>(Tl + o) = pack2(c[mi][g][2], c[mi][g][3], true);
                    }
                }
            }
        }

        if (fi + 1 < 4) {
            asm volatile("cp.async.wait_group 0;");
            __syncthreads();
        }
    }
}

// ---------------- gc7 + final iDCT fused ----------------
__global__ void __launch_bounds__(256) gc7_idct(
    const float* __restrict__ A, const float* __restrict__ W,
    const float* __restrict__ bias, const float* __restrict__ xres,
    float* __restrict__ out) {
    __shared__ float As[128][17];
    __shared__ float Bs[16][21];
    __shared__ float Do[128][21];
    __shared__ float dctS[DCTN * VL];
    const int bm0 = blockIdx.x * 128;
    const int t = threadIdx.x;
    const int rp = t >> 2, cg = t & 3;
    float acc[2][5] = {};
    for (int k0 = 0; k0 < 512; k0 += 16) {
#pragma unroll
        for (int i = 0; i < 8; i++) {
            int idx = t + 256 * i;
            int r = idx >> 4, kk = idx & 15;
            As[r][kk] = A[(size_t)(bm0 + r) * 512 + k0 + kk];
        }
        for (int i = t; i < 320; i += 256) {
            int kk = i / 20, n = i % 20;
            Bs[kk][n] = W[(k0 + kk) * GCNIN + n];
        }
        __syncthreads();
#pragma unroll
        for (int kk = 0; kk < 16; kk++) {
            float a0 = As[rp * 2][kk], a1 = As[rp * 2 + 1][kk];
#pragma unroll
            for (int j = 0; j < 5; j++) {
                float bb = Bs[kk][cg * 5 + j];
                acc[0][j] += a0 * bb;
                acc[1][j] += a1 * bb;
            }
        }
        __syncthreads();
    }
#pragma unroll
    for (int rr = 0; rr < 2; rr++) {
        int r = rp * 2 + rr;
        int row = bm0 + r;
#pragma unroll
        for (int j = 0; j < 5; j++) {
            int n = cg * 5 + j;
            Do[r][n] = acc[rr][j] + bias[n] + xres[(size_t)row * GCNIN + n];
        }
    }
    for (int i = t; i < DCTN * VL; i += 256) dctS[i] = g_dct[i];
    __syncthreads();
    for (int i = t; i < 128 * VL; i += 256) {
        int r = i / VL, v = i % VL;
        int row = bm0 + r;
        int b = row / F66, f = row % F66;
        float s = 0.f;
#pragma unroll
        for (int k = 0; k < DCTN; k++) s += dctS[k * VL + v] * Do[r][k];
        out[((size_t)b * VL + v) * F66 + f] = s;
    }
}

// ---------------- host launcher ----------------
template <typename T>
static T* sym(const void* s) {
    void* p = nullptr;
    cudaGetSymbolAddress(&p, s);
    return (T*)p;
}

extern "C" void kernel_launch(void* const* d_in, const int* in_sizes, int n_in,
                              void* d_out, int out_size) {
    const float* src     = (const float*)d_in[0];
    const float* Wq1     = (const float*)d_in[1];
    const float* Wq2     = (const float*)d_in[2];
    const float* Wk1     = (const float*)d_in[3];
    const float* Wk2     = (const float*)d_in[4];
    const float* gc1_W   = (const float*)d_in[5];
    const float* gc1_att = (const float*)d_in[6];
    const float* gc1_b   = (const float*)d_in[7];
    const float* bn1_g   = (const float*)d_in[8];
    const float* bn1_b   = (const float*)d_in[9];
    const float* gcb_W   = (const float*)d_in[10];
    const float* gcb_att = (const float*)d_in[11];
    const float* gcb_b   = (const float*)d_in[12];
    const float* gcb_bn_g= (const float*)d_in[13];
    const float* gcb_bn_b= (const float*)d_in[14];
    const float* gc7_W   = (const float*)d_in[15];
    const float* gc7_att = (const float*)d_in[16];
    const float* gc7_b   = (const float*)d_in[17];
    float* out = (float*)d_out;

    cudaFuncSetAttribute(hgemm, cudaFuncAttributeMaxDynamicSharedMemorySize, HG_SMEM);
    cudaFuncSetAttribute(amix_mma, cudaFuncAttributeMaxDynamicSharedMemorySize, AM_SMEM);
    cudaFuncSetAttribute(att_x_mix, cudaFuncAttributeMaxDynamicSharedMemorySize, AX_SMEM);

    __nv_bfloat16* srch = sym<__nv_bfloat16>(g_srch); __nv_bfloat16* srcl = sym<__nv_bfloat16>(g_srcl);
    __nv_bfloat16* k1h  = sym<__nv_bfloat16>(g_k1h);  __nv_bfloat16* k1l  = sym<__nv_bfloat16>(g_k1l);
    __nv_bfloat16* q1h  = sym<__nv_bfloat16>(g_q1h);  __nv_bfloat16* q1l  = sym<__nv_bfloat16>(g_q1l);
    __nv_bfloat16* Wk1h = sym<__nv_bfloat16>(g_Wk1h); __nv_bfloat16* Wk1l = sym<__nv_bfloat16>(g_Wk1l);
    __nv_bfloat16* Wk2h = sym<__nv_bfloat16>(g_Wk2h); __nv_bfloat16* Wk2l = sym<__nv_bfloat16>(g_Wk2l);
    __nv_bfloat16* Wq1h = sym<__nv_bfloat16>(g_Wq1h); __nv_bfloat16* Wq1l = sym<__nv_bfloat16>(g_Wq1l);
    __nv_bfloat16* Wq2h = sym<__nv_bfloat16>(g_Wq2h); __nv_bfloat16* Wq2l = sym<__nv_bfloat16>(g_Wq2l);
    __nv_bfloat16* Wg1h = sym<__nv_bfloat16>(g_Wg1h); __nv_bfloat16* Wg1l = sym<__nv_bfloat16>(g_Wg1l);
    __nv_bfloat16* Wgbh = sym<__nv_bfloat16>(g_Wgbh); __nv_bfloat16* Wgbl = sym<__nv_bfloat16>(g_Wgbl);
    __nv_bfloat16* Th   = sym<__nv_bfloat16>(g_Th);   __nv_bfloat16* Tl   = sym<__nv_bfloat16>(g_Tl);
    __nv_bfloat16* yh   = sym<__nv_bfloat16>(g_yh);   __nv_bfloat16* yl   = sym<__nv_bfloat16>(g_yl);
    __nv_bfloat16* zh   = sym<__nv_bfloat16>(g_zh);   __nv_bfloat16* zl   = sym<__nv_bfloat16>(g_zl);
    __nv_bfloat16* Aph  = sym<__nv_bfloat16>(g_Aph);  __nv_bfloat16* Apl  = sym<__nv_bfloat16>(g_Apl);

    float* key2 = sym<float>(g_key2);
    float* qv   = sym<float>(g_q);
    float* px   = sym<float>(g_x);
    float* pt   = sym<float>(g_t);

    Epi ep_relu  = {nullptr, nullptr, nullptr, 1};
    Epi ep_plain = {nullptr, nullptr, nullptr, 0};

    prep_all<<<2048, 256>>>(src, Wk1, Wq1, Wk2, Wq2, gc1_W, gcb_W,   // #0
                            gcb_att, gc7_att);
    // fused conv1 (key tiles 0..79, query tiles 80..99)
    hgemm<<<dim3(4, 100), 256, HG_SMEM>>>(srch, srcl, 1, 20, 0,       // #1
        Wk1h, Wk1l, nullptr, k1h, k1l, nullptr, nullptr, 10240, K1P, ep_relu,
        80, Wq1h, Wq1l, q1h, q1l, 5, TIN - KS_);
    hgemm<<<dim3(4, 64), 256, HG_SMEM>>>(k1h, k1l, 2, 0, 0,           // #2
        Wk2h, Wk2l, key2, nullptr, nullptr, nullptr, nullptr, 8192, K2, ep_relu,
        0, nullptr, nullptr, nullptr, nullptr, 0, 0);
    hgemm<<<dim3(4, 4, 16), 256, HG_SMEM>>>(q1h, q1l, 3, 0, 0, Wq2h, Wq2l,  // #3
        pt, nullptr, nullptr, nullptr, nullptr, 512, K2, ep_plain,
        0, nullptr, nullptr, nullptr, nullptr, 0, 0);
    reduce_relu<<<512, 256>>>(pt, qv, 512 * 512, 16);

    // ---- fused attention + x + gc1 node-mix ----
    att_x_mix<<<BSZ, 256, AX_SMEM>>>(src, qv, key2, gc1_att, px, Th, Tl);

    const int M = MROWS;

    // ---- gc1 GEMM ----
    {
        Epi e = {gc1_b, bn1_g, bn1_b, 2};
        hgemm<<<dim3(4, M / 128), 256, HG_SMEM>>>(Th, Tl, 0, 0, 0, Wg1h, Wg1l,
            nullptr, yh, yl, nullptr, nullptr, M, 64, e,
            0, nullptr, nullptr, nullptr, nullptr, 0, 0);
    }

    // ---- 2 stages x 2 layers ----
    for (int st = 0; st < 2; st++) {
        for (int l = 0; l < 2; l++) {
            int li = st * 2 + l;
            const __nv_bfloat16* ih = (l == 0) ? yh : zh;
            const __nv_bfloat16* il = (l == 0) ? yl : zl;
            __nv_bfloat16* oh = (l == 0) ? zh : yh;
            __nv_bfloat16* ol = (l == 0) ? zl : yl;
            amix_mma<<<BSZ, 256, AM_SMEM>>>(Aph + li * 6400, Apl + li * 6400,
                                            ih, il, Th, Tl, nullptr);
            Epi e = {gcb_b + (size_t)li * 512,
                     gcb_bn_g + (size_t)li * F66 * 512,
                     gcb_bn_b + (size_t)li * F66 * 512,
                     (l == 1) ? 3 : 2};
            hgemm<<<dim3(4, M / 128), 256, HG_SMEM>>>(Th, Tl, 0, 0, 0,
                Wgbh + (size_t)li * 512 * 512, Wgbl + (size_t)li * 512 * 512,
                nullptr, oh, ol,
                (l == 1) ? yh : nullptr, (l == 1) ? yl : nullptr, M, 512, e,
                0, nullptr, nullptr, nullptr, nullptr, 0, 0);
        }
    }

    // ---- gc7 (+x residual) + final iDCT fused ----
    {
        amix_mma<<<BSZ, 256, AM_SMEM>>>(Aph + 4 * 6400, Apl + 4 * 6400,
                                        yh, yl, nullptr, nullptr, pt);
        gc7_idct<<<M / 128, 256>>>(pt, gc7_W, gc7_b, px, out);
    }

    (void)in_sizes; (void)n_in; (void)out_size;
}